// round 11
// baseline (speedup 1.0000x reference)
#include <cuda_runtime.h>
#include <cuda_bf16.h>
#include <cstdint>

// Problem dims
constexpr int kB  = 16;
constexpr int kN  = 128;
constexpr int kC  = 512;
constexpr int kH  = 8;
constexpr int kR  = 17;
constexpr int kHD = 64;
constexpr int kBN = kB * kN;    // 2048
constexpr int kKp = 3 * kC;     // 1536 split-K' (c contraction)
constexpr int kKq = 3 * kHD;    // 192 split-K' (d contraction, qk)

// Scratch (device globals; no allocations allowed)
__device__ float g_S[kB * kH * kN * kN];  // 8 MB (pre-scaled by 0.125)
__device__ float g_Wf[kB * kH * kN * kN]; // 8 MB attention weights fp32
__device__ float g_yvf[kB * kH * kN * kHD]; // 4 MB yv fp32 [bh][m][64]
__device__ float g_AsT[kN * kR * kN];     // 1.1 MB A^T fp32 [n][r][128m]
__device__ int   g_mask_mode;
__device__ __nv_bfloat16 g_Ax[kBN * kKp];        // x hi|lo|hi
__device__ __nv_bfloat16 g_Bqkv[kKp * kKp];      // [q_w;kv_w] hi|hi|lo
__device__ __nv_bfloat16 g_Bproj[kC * kKp];      // proj_w hi|hi|lo
__device__ __nv_bfloat16 g_AO[kBN * kKp];        // O hi|lo|hi (av epilogue)
__device__ __nv_bfloat16 g_qbf[kB * kH * kN * kKq]; // q hi|lo|hi per (b,h)
__device__ __nv_bfloat16 g_kbf[kB * kH * kN * kKq]; // k hi|hi|lo per (b,h)

__device__ __forceinline__ float neg_inf() { return __int_as_float(0xFF800000); }

// ===================== baseline-PTX helpers =====================
__device__ __forceinline__ uint32_t smem_u32(const void* p) {
    uint32_t a;
    asm("{ .reg .u64 t; cvta.to.shared.u64 t, %1; cvt.u32.u64 %0, t; }"
        : "=r"(a) : "l"(p));
    return a;
}
__device__ __forceinline__ void cp_async16(uint32_t saddr, const void* gaddr) {
    asm volatile("cp.async.cg.shared.global [%0], [%1], 16;"
                 :: "r"(saddr), "l"(gaddr) : "memory");
}
__device__ __forceinline__ void cp_commit() {
    asm volatile("cp.async.commit_group;" ::: "memory");
}
__device__ __forceinline__ void cp_wait0() {
    asm volatile("cp.async.wait_group 0;" ::: "memory");
}
__device__ __forceinline__ void cp_wait1() {
    asm volatile("cp.async.wait_group 1;" ::: "memory");
}
__device__ __forceinline__ void ldsm_x4(uint32_t* r, uint32_t addr) {
    asm volatile("ldmatrix.sync.aligned.m8n8.x4.shared.b16 {%0,%1,%2,%3}, [%4];"
                 : "=r"(r[0]), "=r"(r[1]), "=r"(r[2]), "=r"(r[3]) : "r"(addr));
}
__device__ __forceinline__ void mma16816(float* d, const uint32_t* a, const uint32_t* b) {
    asm volatile("mma.sync.aligned.m16n8k16.row.col.f32.bf16.bf16.f32 "
                 "{%0,%1,%2,%3}, {%4,%5,%6,%7}, {%8,%9}, {%0,%1,%2,%3};"
                 : "+f"(d[0]), "+f"(d[1]), "+f"(d[2]), "+f"(d[3])
                 : "r"(a[0]), "r"(a[1]), "r"(a[2]), "r"(a[3]),
                   "r"(b[0]), "r"(b[1]));
}
__device__ __forceinline__ uint32_t pack_bf2(__nv_bfloat16 lo, __nv_bfloat16 hi) {
    return ((uint32_t)__bfloat16_as_ushort(hi) << 16) | __bfloat16_as_ushort(lo);
}
__device__ __forceinline__ void sts32(uint32_t addr, uint32_t v) {
    asm volatile("st.shared.b32 [%0], %1;" :: "r"(addr), "r"(v) : "memory");
}
__device__ __forceinline__ void sts64(uint32_t addr, uint32_t v0, uint32_t v1) {
    asm volatile("st.shared.v2.b32 [%0], {%1,%2};" :: "r"(addr), "r"(v0), "r"(v1) : "memory");
}
__device__ __forceinline__ float dot4(float4 a, float4 b) {
    return a.x * b.x + a.y * b.y + a.z * b.z + a.w * b.w;
}

// ===================== fused converts + mask probe + A-transpose ============
__global__ __launch_bounds__(128) void convert_all_kernel(
    const float* __restrict__ x, const float* __restrict__ q_w,
    const float* __restrict__ kv_w, const float* __restrict__ proj_w,
    const float* __restrict__ assign, const void* __restrict__ mask,
    __nv_bfloat16* __restrict__ Ax, __nv_bfloat16* __restrict__ Bqkv,
    __nv_bfloat16* __restrict__ Bproj, float* __restrict__ AsTg)
{
    const int rb = blockIdx.x;
    if (rb == 4096) {
        __shared__ int s_not_i32, s_not_f32;
        if (threadIdx.x == 0) { s_not_i32 = 0; s_not_f32 = 0; }
        __syncthreads();
        const unsigned int* w = (const unsigned int*)mask;
        int bad_i = 0, bad_f = 0;
        for (int i = threadIdx.x; i < 544; i += 128) {
            unsigned int v = w[i];
            if (v > 1u) bad_i = 1;
            if (v != 0u && v != 0x3F800000u) bad_f = 1;
        }
        if (bad_i) atomicOr(&s_not_i32, 1);
        if (bad_f) atomicOr(&s_not_f32, 1);
        __syncthreads();
        if (threadIdx.x == 0)
            g_mask_mode = (!s_not_i32) ? 0 : ((!s_not_f32) ? 1 : 2);
        return;
    }
    if (rb >= 4097) {
        const int n = rb - 4097;
        __shared__ __align__(16) float At[2176];
        const float* arow = assign + (size_t)n * 2176;
        for (int i = threadIdx.x; i < 544; i += 128)
            *(float4*)&At[i * 4] = *(const float4*)&arow[i * 4];
        __syncthreads();
        float* out = AsTg + (size_t)n * 2176;
        for (int j = threadIdx.x; j < 544; j += 128) {
            const int o = j * 4;
            const int r = o >> 7, m = o & 127;
            float4 v = make_float4(At[m * kR + r], At[(m + 1) * kR + r],
                                   At[(m + 2) * kR + r], At[(m + 3) * kR + r]);
            *(float4*)&out[o] = v;
        }
        return;
    }
    const float* src;
    __nv_bfloat16* dst;
    bool aSide;
    if (rb < 2048)      { src = x + (size_t)rb * kC;             dst = Ax + (size_t)rb * kKp;           aSide = true;  }
    else if (rb < 2560) { int r = rb - 2048; src = q_w + (size_t)r * kC;    dst = Bqkv + (size_t)r * kKp;        aSide = false; }
    else if (rb < 3584) { int r = rb - 2560; src = kv_w + (size_t)r * kC;   dst = Bqkv + (size_t)(kC + r) * kKp; aSide = false; }
    else                { int r = rb - 3584; src = proj_w + (size_t)r * kC; dst = Bproj + (size_t)r * kKp;       aSide = false; }

    const int j0 = threadIdx.x * 4;
    float4 v = *(const float4*)&src[j0];
    float f[4] = {v.x, v.y, v.z, v.w};
    __nv_bfloat16 hi[4], lo[4];
#pragma unroll
    for (int t = 0; t < 4; t++) {
        hi[t] = __float2bfloat16(f[t]);
        lo[t] = __float2bfloat16(f[t] - __bfloat162float(hi[t]));
    }
    uint32_t hp0 = pack_bf2(hi[0], hi[1]), hp1 = pack_bf2(hi[2], hi[3]);
    uint32_t lp0 = pack_bf2(lo[0], lo[1]), lp1 = pack_bf2(lo[2], lo[3]);
    uint32_t* d0 = (uint32_t*)(dst + j0);
    uint32_t* d1 = (uint32_t*)(dst + kC + j0);
    uint32_t* d2 = (uint32_t*)(dst + 2 * kC + j0);
    d0[0] = hp0; d0[1] = hp1;
    if (aSide) { d1[0] = lp0; d1[1] = lp1; d2[0] = hp0; d2[1] = hp1; }
    else       { d1[0] = hp0; d1[1] = hp1; d2[0] = lp0; d2[1] = lp1; }
}

// ===================== templated mma.sync bf16 GEMM (3-stage pipeline) ======
// MODE 0: C0/C1 fp32 split-column output (+bias)
// MODE 1: qkv epilogue -> qbf/kbf triples + yvf fp32 [bh][m][64] (C1 = yvf)
// MODE 2: per-(b,h) qk: S = 0.125 * q@k^T
template<int KBYTES, int NITER, int MODE>
__global__ __launch_bounds__(256) void mma_gemm_t(
    const __nv_bfloat16* __restrict__ A,
    const __nv_bfloat16* __restrict__ Bw,
    float* __restrict__ C0, float* __restrict__ C1,
    const float* __restrict__ bias, int split, int ld0, int ld1,
    __nv_bfloat16* __restrict__ qbf, __nv_bfloat16* __restrict__ kbf)
{
    __shared__ __align__(16) char smem[3][16384];
    const int tid = threadIdx.x;
    const int wid = tid >> 5, lane = tid & 31;
    const int warp_m = wid >> 1, warp_n = wid & 1;

    int m0, n0;
    const char *Ag, *Bg;
    if (MODE == 2) {
        const size_t off = (size_t)blockIdx.x * 128 * KBYTES;
        Ag = (const char*)A + off;
        Bg = (const char*)Bw + off;
        m0 = 0; n0 = 0;
    } else {
        m0 = blockIdx.y * 128; n0 = blockIdx.x * 128;
        Ag = (const char*)A  + (size_t)m0 * KBYTES;
        Bg = (const char*)Bw + (size_t)n0 * KBYTES;
    }

    const int lr = tid >> 2, lc = tid & 3;
    const uint32_t lso  = (uint32_t)(lr * 64 + ((lc ^ (lr & 3)) << 4));
    const uint32_t lso2 = (uint32_t)((lr + 64) * 64 + ((lc ^ ((lr + 64) & 3)) << 4));
    uint32_t sbase = smem_u32(&smem[0][0]);

    auto stage_load = [&](int st, int k0b) {
        uint32_t sA = sbase + st * 16384;
        uint32_t sB = sA + 8192;
        const char* a0 = Ag + (size_t)lr * KBYTES + k0b + lc * 16;
        const char* b0 = Bg + (size_t)lr * KBYTES + k0b + lc * 16;
        cp_async16(sA + lso,  a0);
        cp_async16(sB + lso,  b0);
        cp_async16(sA + lso2, a0 + (size_t)64 * KBYTES);
        cp_async16(sB + lso2, b0 + (size_t)64 * KBYTES);
    };

    float acc[2][8][4];
#pragma unroll
    for (int i = 0; i < 2; i++)
#pragma unroll
        for (int j = 0; j < 8; j++)
#pragma unroll
            for (int t = 0; t < 4; t++) acc[i][j][t] = 0.f;

    stage_load(0, 0);
    cp_commit();
    if (NITER > 1) { stage_load(1, 64); cp_commit(); }

    const int a_row = warp_m * 32 + (lane & 15);
    const int a_chsel = lane >> 4;
    const int b_mi = lane >> 3;
    const int b_row = warp_n * 64 + ((b_mi >> 1) << 3) + (lane & 7);
    const int b_chsel = b_mi & 1;

    int st = 0;
    for (int it = 0; it < NITER; it++) {
        if (it + 1 < NITER) cp_wait1(); else cp_wait0();
        __syncthreads();
        if (it + 2 < NITER) {
            int st2 = st + 2; if (st2 >= 3) st2 -= 3;
            stage_load(st2, (it + 2) * 64);
            cp_commit();
        }

        const uint32_t sA = sbase + st * 16384;
        const uint32_t sB = sA + 8192;
#pragma unroll
        for (int kk = 0; kk < 2; kk++) {
            uint32_t a[2][4];
#pragma unroll
            for (int i = 0; i < 2; i++) {
                int r = a_row + i * 16;
                int ch = 2 * kk + a_chsel;
                ldsm_x4(a[i], sA + r * 64 + ((ch ^ (r & 3)) << 4));
            }
            uint32_t b[8][2];
#pragma unroll
            for (int g = 0; g < 4; g++) {
                int r = b_row + g * 16;
                int ch = 2 * kk + b_chsel;
                uint32_t rr[4];
                ldsm_x4(rr, sB + r * 64 + ((ch ^ (r & 3)) << 4));
                b[2 * g][0] = rr[0]; b[2 * g][1] = rr[1];
                b[2 * g + 1][0] = rr[2]; b[2 * g + 1][1] = rr[3];
            }
#pragma unroll
            for (int i = 0; i < 2; i++)
#pragma unroll
                for (int j = 0; j < 8; j++)
                    mma16816(acc[i][j], a[i], b[j]);
        }
        if (++st == 3) st = 0;
    }

    const int gq = lane >> 2, t4 = lane & 3;

    if (MODE == 2) {
        float* Sp = C0 + (size_t)blockIdx.x * kN * kN;
#pragma unroll
        for (int i = 0; i < 2; i++) {
#pragma unroll
            for (int j = 0; j < 8; j++) {
                int col = warp_n * 64 + j * 8 + t4 * 2;
                int r0 = warp_m * 32 + i * 16 + gq;
                *(float2*)&Sp[(size_t)r0 * kN + col] =
                    make_float2(acc[i][j][0] * 0.125f, acc[i][j][1] * 0.125f);
                *(float2*)&Sp[(size_t)(r0 + 8) * kN + col] =
                    make_float2(acc[i][j][2] * 0.125f, acc[i][j][3] * 0.125f);
            }
        }
        return;
    }

    if (MODE == 1) {
        auto emit = [&](int row, int colg, float f0, float f1) {
            if (colg < 1024) {
                const bool isQ = colg < 512;
                const int c = isQ ? colg : colg - 512;
                const int h = c >> 6, d = c & 63;
                __nv_bfloat16 h0 = __float2bfloat16(f0);
                __nv_bfloat16 h1 = __float2bfloat16(f1);
                __nv_bfloat16 l0 = __float2bfloat16(f0 - __bfloat162float(h0));
                __nv_bfloat16 l1 = __float2bfloat16(f1 - __bfloat162float(h1));
                uint32_t hp = pack_bf2(h0, h1);
                uint32_t lp = pack_bf2(l0, l1);
                const int bb = row >> 7, nn = row & 127;
                __nv_bfloat16* base = (isQ ? qbf : kbf)
                    + ((size_t)((bb * kH + h) * kN + nn)) * kKq + d;
                *(uint32_t*)(base)       = hp;
                *(uint32_t*)(base + 64)  = isQ ? lp : hp;
                *(uint32_t*)(base + 128) = isQ ? hp : lp;
            } else {
                const int c = colg - 1024;
                const int h = c >> 6, d = c & 63;
                const int bb = row >> 7, m = row & 127;
                *(float2*)&C1[((size_t)((bb * kH + h) * kN + m)) * kHD + d] =
                    make_float2(f0, f1);
            }
        };
#pragma unroll
        for (int i = 0; i < 2; i++) {
#pragma unroll
            for (int j = 0; j < 8; j++) {
                int colg = n0 + warp_n * 64 + j * 8 + t4 * 2;
                int row0 = m0 + warp_m * 32 + i * 16 + gq;
                emit(row0,     colg, acc[i][j][0], acc[i][j][1]);
                emit(row0 + 8, colg, acc[i][j][2], acc[i][j][3]);
            }
        }
        return;
    }

    // MODE 0
#pragma unroll
    for (int i = 0; i < 2; i++) {
#pragma unroll
        for (int j = 0; j < 8; j++) {
            int colg = n0 + warp_n * 64 + j * 8 + t4 * 2;
            float bz0 = bias ? bias[colg]     : 0.f;
            float bz1 = bias ? bias[colg + 1] : 0.f;
            float* Cc; int ldc, cc;
            if (colg < split) { Cc = C0; ldc = ld0; cc = colg; }
            else              { Cc = C1; ldc = ld1; cc = colg - split; }
            int row0 = m0 + warp_m * 32 + i * 16 + gq;
            *(float2*)&Cc[(size_t)row0 * ldc + cc] =
                make_float2(acc[i][j][0] + bz0, acc[i][j][1] + bz1);
            *(float2*)&Cc[(size_t)(row0 + 8) * ldc + cc] =
                make_float2(acc[i][j][2] + bz0, acc[i][j][3] + bz1);
        }
    }
}

// ===================== att v5: low-shuffle logits ================
// Block per (b,n). Warp h. Logits: lane=(r4,mseg), 5 iters, 3-shfl reduce.
__global__ __launch_bounds__(256) void att_kernel(
    const float* __restrict__ S, const float* __restrict__ AsTg,
    const void* __restrict__ mask, const float* __restrict__ rel_bias,
    float* __restrict__ Wf)
{
    __shared__ __align__(16) float As[kR * 132];
    __shared__ __align__(16) float Ss[kH * 132];
    __shared__ __align__(16) float Ls[kH * 20];
    __shared__ __align__(16) float Ps[kH * 20];
    __shared__ __align__(16) float rb[136];
    __shared__ __align__(16) int   mk[kR];

    const int t = threadIdx.x, wid = t >> 5, lane = t & 31;
    const int b = blockIdx.x >> 7, n = blockIdx.x & 127;

    // loads (all coalesced)
    {
        const int h = t >> 5, m0 = (t & 31) * 4;
        *(float4*)&Ss[h * 132 + m0] =
            *(const float4*)&S[(((size_t)(b * kH + h)) * kN + n) * kN + m0];
    }
    const float* ag = AsTg + (size_t)n * (kR * kN);
    for (int i = t; i < 544; i += 256) {
        const int r = i >> 5, m0 = (i & 31) * 4;
        *(float4*)&As[r * 132 + m0] = *(const float4*)&ag[r * kN + m0];
    }
    if (t < 136) rb[t] = rel_bias[t];
    if (t < kR) {
        int mode = g_mask_mode;
        int idx = n * kR + t;
        bool m_;
        if (mode == 0)      m_ = ((const int*)mask)[idx] != 0;
        else if (mode == 1) m_ = ((const float*)mask)[idx] != 0.f;
        else                m_ = ((const unsigned char*)mask)[idx] != 0;
        mk[t] = m_ ? 1 : 0;
    }
    __syncthreads();

    // logits: warp = head h; lane = (r4 = lane>>3, mseg = lane&7)
    {
        const int h = wid;
        const int r4 = lane >> 3, mseg = lane & 7;
        const float* sb = &Ss[h * 132 + mseg * 16];
        float4 s0 = *(const float4*)&sb[0];
        float4 s1 = *(const float4*)&sb[4];
        float4 s2 = *(const float4*)&sb[8];
        float4 s3 = *(const float4*)&sb[12];
#pragma unroll
        for (int rr = 0; rr < 5; rr++) {
            const int r = rr * 4 + r4;      // 0..19
            float d = 0.f;
            if (r < kR) {
                const float* a = &As[r * 132 + mseg * 16];
                d = dot4(s0, *(const float4*)&a[0])
                  + dot4(s1, *(const float4*)&a[4])
                  + dot4(s2, *(const float4*)&a[8])
                  + dot4(s3, *(const float4*)&a[12]);
            }
            d += __shfl_xor_sync(0xFFFFFFFFu, d, 1);
            d += __shfl_xor_sync(0xFFFFFFFFu, d, 2);
            d += __shfl_xor_sync(0xFFFFFFFFu, d, 4);
            if (mseg == 0 && r < kR)
                Ls[h * 20 + r] = mk[r] ? neg_inf() : (d + rb[h * kR + r]);
        }
    }
    __syncthreads();

    // softmax: warp wid == head h, lanes 0..16
    {
        const int h = wid;
        float v = (lane < kR) ? Ls[h * 20 + lane] : neg_inf();
        float mx = v;
#pragma unroll
        for (int o = 16; o > 0; o >>= 1)
            mx = fmaxf(mx, __shfl_xor_sync(0xFFFFFFFFu, mx, o));
        float e = (lane < kR) ? __expf(v - mx) : 0.f;
        float s = e;
#pragma unroll
        for (int o = 16; o > 0; o >>= 1)
            s += __shfl_xor_sync(0xFFFFFFFFu, s, o);
        if (lane < kR) Ps[h * 20 + lane] = e / s;
    }
    __syncthreads();

    // W: thread = (h-group, m); 4 heads per thread
    {
        const int m = t & 127, hg = t >> 7;
        float acc[4] = {0.f, 0.f, 0.f, 0.f};
#pragma unroll
        for (int r = 0; r < kR; r++) {
            float a = As[r * 132 + m];
#pragma unroll
            for (int u = 0; u < 4; u++)
                acc[u] += Ps[(hg * 4 + u) * 20 + r] * a;
        }
#pragma unroll
        for (int u = 0; u < 4; u++)
            Wf[(((size_t)(b * kH + hg * 4 + u)) * kN + n) * kN + m] = acc[u];
    }
}

// ===================== av combo mma: O = W @ yv^T per (b,h) =================
__global__ __launch_bounds__(256) void av_mma_kernel(
    const float* __restrict__ Wf, const float* __restrict__ yvf,
    __nv_bfloat16* __restrict__ AO)
{
    extern __shared__ __align__(16) char dsm[];
    const int tid = threadIdx.x, wid = tid >> 5, lane = tid & 31;
    const int bh = blockIdx.x;
    const int warp_m = wid >> 1, warp_n = wid & 1;
    const uint32_t sbase = smem_u32(dsm);           // A stages: 8 x 8KB
    const uint32_t vbase = sbase + 65536u;          // B stages: 8 x 4KB

    const float* Wb = Wf + (size_t)bh * kN * kN;
    {
        const int mq = tid & 31, r0 = tid >> 5;
#pragma unroll
        for (int i = 0; i < 16; i++) {
            const int row = r0 + 8 * i;
            float4 v = *(const float4*)&Wb[(size_t)row * kN + mq * 4];
            float f[4] = {v.x, v.y, v.z, v.w};
            __nv_bfloat16 hi[4], lo[4];
#pragma unroll
            for (int u = 0; u < 4; u++) {
                hi[u] = __float2bfloat16(f[u]);
                lo[u] = __float2bfloat16(f[u] - __bfloat162float(hi[u]));
            }
            const int m0 = mq * 4;
            const int stage = m0 >> 5;
            const int ch = (m0 & 31) >> 3;
            const int hb = (m0 & 7) >> 2;
            uint32_t addr = sbase + stage * 8192 + row * 64
                          + ((ch ^ (row & 3)) << 4) + hb * 8;
            sts64(addr, pack_bf2(hi[0], hi[1]), pack_bf2(hi[2], hi[3]));
            sts64(addr + 4 * 8192, pack_bf2(lo[0], lo[1]), pack_bf2(lo[2], lo[3]));
        }
    }
    const float* Vb = yvf + (size_t)bh * kN * kHD;
    {
        const int dq = tid & 15, mp0 = tid >> 4;
#pragma unroll
        for (int i = 0; i < 4; i++) {
            const int mp = mp0 + 16 * i;
            const int m0 = 2 * mp;
            float4 v0 = *(const float4*)&Vb[(size_t)m0 * kHD + dq * 4];
            float4 v1 = *(const float4*)&Vb[(size_t)(m0 + 1) * kHD + dq * 4];
            float f0[4] = {v0.x, v0.y, v0.z, v0.w};
            float f1[4] = {v1.x, v1.y, v1.z, v1.w};
            const int stage = m0 >> 5;
            const int ch = (m0 & 31) >> 3;
            const int ob = (m0 & 7) * 2;
#pragma unroll
            for (int u = 0; u < 4; u++) {
                const int row = dq * 4 + u;
                __nv_bfloat16 h0 = __float2bfloat16(f0[u]);
                __nv_bfloat16 h1 = __float2bfloat16(f1[u]);
                __nv_bfloat16 l0 = __float2bfloat16(f0[u] - __bfloat162float(h0));
                __nv_bfloat16 l1 = __float2bfloat16(f1[u] - __bfloat162float(h1));
                uint32_t addr = vbase + stage * 4096 + row * 64
                              + ((ch ^ (row & 3)) << 4) + ob;
                sts32(addr, pack_bf2(h0, h1));
                sts32(addr + 4 * 4096, pack_bf2(l0, l1));
            }
        }
    }
    __syncthreads();

    float acc[2][4][4];
#pragma unroll
    for (int i = 0; i < 2; i++)
#pragma unroll
        for (int j = 0; j < 4; j++)
#pragma unroll
            for (int t = 0; t < 4; t++) acc[i][j][t] = 0.f;

    const int a_row = warp_m * 32 + (lane & 15);
    const int a_chsel = lane >> 4;
    const int b_mi = lane >> 3;
    const int b_row = warp_n * 32 + ((b_mi >> 1) << 3) + (lane & 7);
    const int b_chsel = b_mi & 1;

    const int schedA[12] = {0,1,2,3, 4,5,6,7, 0,1,2,3};
    const int schedB[12] = {0,1,2,3, 0,1,2,3, 4,5,6,7};

#pragma unroll
    for (int it = 0; it < 12; it++) {
        const uint32_t sA = sbase + schedA[it] * 8192;
        const uint32_t sB = vbase + schedB[it] * 4096;
#pragma unroll
        for (int kk = 0; kk < 2; kk++) {
            uint32_t a[2][4];
#pragma unroll
            for (int i = 0; i < 2; i++) {
                int r = a_row + i * 16;
                int ch = 2 * kk + a_chsel;
                ldsm_x4(a[i], sA + r * 64 + ((ch ^ (r & 3)) << 4));
            }
            uint32_t b[4][2];
#pragma unroll
            for (int g = 0; g < 2; g++) {
                int r = b_row + g * 16;
                int ch = 2 * kk + b_chsel;
                uint32_t rr[4];
                ldsm_x4(rr, sB + r * 64 + ((ch ^ (r & 3)) << 4));
                b[2 * g][0] = rr[0]; b[2 * g][1] = rr[1];
                b[2 * g + 1][0] = rr[2]; b[2 * g + 1][1] = rr[3];
            }
#pragma unroll
            for (int i = 0; i < 2; i++)
#pragma unroll
                for (int j = 0; j < 4; j++)
                    mma16816(acc[i][j], a[i], b[j]);
        }
    }

    const int gq = lane >> 2, t4 = lane & 3;
    const int b_ = bh >> 3, h_ = bh & 7;
#pragma unroll
    for (int i = 0; i < 2; i++) {
#pragma unroll
        for (int j = 0; j < 4; j++) {
            const int d = warp_n * 32 + j * 8 + t4 * 2;
            const int c = h_ * kHD + d;
#pragma unroll
            for (int rr = 0; rr < 2; rr++) {
                const int nrow = warp_m * 32 + i * 16 + gq + rr * 8;
                const float f0 = acc[i][j][rr * 2], f1 = acc[i][j][rr * 2 + 1];
                __nv_bfloat16 h0 = __float2bfloat16(f0), h1 = __float2bfloat16(f1);
                __nv_bfloat16 l0 = __float2bfloat16(f0 - __bfloat162float(h0));
                __nv_bfloat16 l1 = __float2bfloat16(f1 - __bfloat162float(h1));
                __nv_bfloat16* base = AO + (size_t)(b_ * kN + nrow) * kKp + c;
                *(uint32_t*)(base)        = pack_bf2(h0, h1);
                *(uint32_t*)(base + 512)  = pack_bf2(l0, l1);
                *(uint32_t*)(base + 1024) = pack_bf2(h0, h1);
            }
        }
    }
}

// ===================== launch =====================
extern "C" void kernel_launch(void* const* d_in, const int* in_sizes, int n_in,
                              void* d_out, int out_size)
{
    const float* x        = (const float*)d_in[0];
    const float* assign   = (const float*)d_in[1];
    const void*  mask     = d_in[2];
    const float* q_w      = (const float*)d_in[3];
    const float* kv_w     = (const float*)d_in[4];
    const float* rel_bias = (const float*)d_in[5];
    const float* proj_w   = (const float*)d_in[6];
    const float* proj_b   = (const float*)d_in[7];

    float *S, *Wfp, *yvf, *AsTg;
    __nv_bfloat16 *Ax, *Bqkv, *Bproj, *AO, *qbf, *kbf;
    cudaGetSymbolAddress((void**)&S,    g_S);
    cudaGetSymbolAddress((void**)&Wfp,  g_Wf);
    cudaGetSymbolAddress((void**)&yvf,  g_yvf);
    cudaGetSymbolAddress((void**)&AsTg, g_AsT);
    cudaGetSymbolAddress((void**)&Ax,    g_Ax);
    cudaGetSymbolAddress((void**)&Bqkv,  g_Bqkv);
    cudaGetSymbolAddress((void**)&Bproj, g_Bproj);
    cudaGetSymbolAddress((void**)&AO,    g_AO);
    cudaGetSymbolAddress((void**)&qbf,   g_qbf);
    cudaGetSymbolAddress((void**)&kbf,   g_kbf);

    const int AV_SMEM = 8 * 8192 + 8 * 4096;  // 96 KB
    cudaFuncSetAttribute(av_mma_kernel,
                         cudaFuncAttributeMaxDynamicSharedMemorySize, AV_SMEM);

    // 1. input hi/lo splits + mask probe + A transpose
    convert_all_kernel<<<4225, 128>>>(x, q_w, kv_w, proj_w, assign, mask,
                                      Ax, Bqkv, Bproj, AsTg);

    // 2. fused q/kv projection -> qbf/kbf triples + yvf fp32
    mma_gemm_t<3072, 48, 1><<<dim3(12, 16), 256>>>(
        Ax, Bqkv, nullptr, yvf, nullptr, 0, 0, 0, qbf, kbf);

    // 3. S = 0.125 * q@k^T per (b,h)
    mma_gemm_t<384, 6, 2><<<dim3(128, 1), 256>>>(
        qbf, kbf, S, nullptr, nullptr, 0, 0, 0, nullptr, nullptr);

    // 4. logits + masked softmax + W (fp32), low-shuffle
    att_kernel<<<kB * kN, 256>>>(S, AsTg, mask, rel_bias, Wfp);

    // 5. O = W @ yv per (b,h), combo split-K on tensor cores (emits AO triple)
    av_mma_kernel<<<128, 256, AV_SMEM>>>(Wfp, yvf, AO);

    // 6. out-proj: AO @ Bproj^T + bias
    mma_gemm_t<3072, 48, 0><<<dim3(4, 16), 256>>>(
        AO, Bproj, (float*)d_out, (float*)d_out, proj_b, 1 << 30, kC, kC,
        nullptr, nullptr);
}

// round 12
// speedup vs baseline: 1.1019x; 1.1019x over previous
#include <cuda_runtime.h>
#include <cuda_bf16.h>
#include <cstdint>

// Problem dims
constexpr int kB  = 16;
constexpr int kN  = 128;
constexpr int kC  = 512;
constexpr int kH  = 8;
constexpr int kR  = 17;
constexpr int kHD = 64;
constexpr int kBN = kB * kN;    // 2048
constexpr int kKp = 3 * kC;     // 1536 split-K' (c contraction)
constexpr int kKq = 3 * kHD;    // 192 split-K' (d contraction, qk)

// Scratch (device globals; no allocations allowed)
__device__ float g_S[kB * kH * kN * kN];  // 8 MB (pre-scaled by 0.125)
__device__ float g_Wf[kB * kH * kN * kN]; // 8 MB attention weights fp32
__device__ float g_yvf[kB * kH * kN * kHD]; // 4 MB yv fp32 [bh][m][64]
__device__ float g_AsT[kN * kR * kN];     // 1.1 MB A^T fp32 [n][r][128m]
__device__ int   g_mask_mode;
__device__ __nv_bfloat16 g_Ax[kBN * kKp];        // x hi|lo|hi
__device__ __nv_bfloat16 g_Bqkv[kKp * kKp];      // [q_w;kv_w] hi|hi|lo
__device__ __nv_bfloat16 g_Bproj[kC * kKp];      // proj_w hi|hi|lo
__device__ __nv_bfloat16 g_AO[kBN * kKp];        // O hi|lo|hi (av epilogue)
__device__ __nv_bfloat16 g_qbf[kB * kH * kN * kKq]; // q hi|lo|hi per (b,h)
__device__ __nv_bfloat16 g_kbf[kB * kH * kN * kKq]; // k hi|hi|lo per (b,h)

__device__ __forceinline__ float neg_inf() { return __int_as_float(0xFF800000); }

// ===================== baseline-PTX helpers =====================
__device__ __forceinline__ uint32_t smem_u32(const void* p) {
    uint32_t a;
    asm("{ .reg .u64 t; cvta.to.shared.u64 t, %1; cvt.u32.u64 %0, t; }"
        : "=r"(a) : "l"(p));
    return a;
}
__device__ __forceinline__ void cp_async16(uint32_t saddr, const void* gaddr) {
    asm volatile("cp.async.cg.shared.global [%0], [%1], 16;"
                 :: "r"(saddr), "l"(gaddr) : "memory");
}
__device__ __forceinline__ void cp_commit() {
    asm volatile("cp.async.commit_group;" ::: "memory");
}
__device__ __forceinline__ void cp_wait0() {
    asm volatile("cp.async.wait_group 0;" ::: "memory");
}
__device__ __forceinline__ void ldsm_x4(uint32_t* r, uint32_t addr) {
    asm volatile("ldmatrix.sync.aligned.m8n8.x4.shared.b16 {%0,%1,%2,%3}, [%4];"
                 : "=r"(r[0]), "=r"(r[1]), "=r"(r[2]), "=r"(r[3]) : "r"(addr));
}
__device__ __forceinline__ void mma16816(float* d, const uint32_t* a, const uint32_t* b) {
    asm volatile("mma.sync.aligned.m16n8k16.row.col.f32.bf16.bf16.f32 "
                 "{%0,%1,%2,%3}, {%4,%5,%6,%7}, {%8,%9}, {%0,%1,%2,%3};"
                 : "+f"(d[0]), "+f"(d[1]), "+f"(d[2]), "+f"(d[3])
                 : "r"(a[0]), "r"(a[1]), "r"(a[2]), "r"(a[3]),
                   "r"(b[0]), "r"(b[1]));
}
__device__ __forceinline__ uint32_t pack_bf2(__nv_bfloat16 lo, __nv_bfloat16 hi) {
    return ((uint32_t)__bfloat16_as_ushort(hi) << 16) | __bfloat16_as_ushort(lo);
}
__device__ __forceinline__ void sts32(uint32_t addr, uint32_t v) {
    asm volatile("st.shared.b32 [%0], %1;" :: "r"(addr), "r"(v) : "memory");
}
__device__ __forceinline__ void sts64(uint32_t addr, uint32_t v0, uint32_t v1) {
    asm volatile("st.shared.v2.b32 [%0], {%1,%2};" :: "r"(addr), "r"(v0), "r"(v1) : "memory");
}
__device__ __forceinline__ float dot4(float4 a, float4 b) {
    return a.x * b.x + a.y * b.y + a.z * b.z + a.w * b.w;
}

// ===================== fused converts + mask probe + A-transpose ============
__global__ __launch_bounds__(128) void convert_all_kernel(
    const float* __restrict__ x, const float* __restrict__ q_w,
    const float* __restrict__ kv_w, const float* __restrict__ proj_w,
    const float* __restrict__ assign, const void* __restrict__ mask,
    __nv_bfloat16* __restrict__ Ax, __nv_bfloat16* __restrict__ Bqkv,
    __nv_bfloat16* __restrict__ Bproj, float* __restrict__ AsTg)
{
    const int rb = blockIdx.x;
    if (rb == 4096) {
        __shared__ int s_not_i32, s_not_f32;
        if (threadIdx.x == 0) { s_not_i32 = 0; s_not_f32 = 0; }
        __syncthreads();
        const unsigned int* w = (const unsigned int*)mask;
        int bad_i = 0, bad_f = 0;
        for (int i = threadIdx.x; i < 544; i += 128) {
            unsigned int v = w[i];
            if (v > 1u) bad_i = 1;
            if (v != 0u && v != 0x3F800000u) bad_f = 1;
        }
        if (bad_i) atomicOr(&s_not_i32, 1);
        if (bad_f) atomicOr(&s_not_f32, 1);
        __syncthreads();
        if (threadIdx.x == 0)
            g_mask_mode = (!s_not_i32) ? 0 : ((!s_not_f32) ? 1 : 2);
        return;
    }
    if (rb >= 4097) {
        const int n = rb - 4097;
        __shared__ __align__(16) float At[2176];
        const float* arow = assign + (size_t)n * 2176;
        for (int i = threadIdx.x; i < 544; i += 128)
            *(float4*)&At[i * 4] = *(const float4*)&arow[i * 4];
        __syncthreads();
        float* out = AsTg + (size_t)n * 2176;
        for (int j = threadIdx.x; j < 544; j += 128) {
            const int o = j * 4;
            const int r = o >> 7, m = o & 127;
            float4 v = make_float4(At[m * kR + r], At[(m + 1) * kR + r],
                                   At[(m + 2) * kR + r], At[(m + 3) * kR + r]);
            *(float4*)&out[o] = v;
        }
        return;
    }
    const float* src;
    __nv_bfloat16* dst;
    bool aSide;
    if (rb < 2048)      { src = x + (size_t)rb * kC;             dst = Ax + (size_t)rb * kKp;           aSide = true;  }
    else if (rb < 2560) { int r = rb - 2048; src = q_w + (size_t)r * kC;    dst = Bqkv + (size_t)r * kKp;        aSide = false; }
    else if (rb < 3584) { int r = rb - 2560; src = kv_w + (size_t)r * kC;   dst = Bqkv + (size_t)(kC + r) * kKp; aSide = false; }
    else                { int r = rb - 3584; src = proj_w + (size_t)r * kC; dst = Bproj + (size_t)r * kKp;       aSide = false; }

    const int j0 = threadIdx.x * 4;
    float4 v = *(const float4*)&src[j0];
    float f[4] = {v.x, v.y, v.z, v.w};
    __nv_bfloat16 hi[4], lo[4];
#pragma unroll
    for (int t = 0; t < 4; t++) {
        hi[t] = __float2bfloat16(f[t]);
        lo[t] = __float2bfloat16(f[t] - __bfloat162float(hi[t]));
    }
    uint32_t hp0 = pack_bf2(hi[0], hi[1]), hp1 = pack_bf2(hi[2], hi[3]);
    uint32_t lp0 = pack_bf2(lo[0], lo[1]), lp1 = pack_bf2(lo[2], lo[3]);
    uint32_t* d0 = (uint32_t*)(dst + j0);
    uint32_t* d1 = (uint32_t*)(dst + kC + j0);
    uint32_t* d2 = (uint32_t*)(dst + 2 * kC + j0);
    d0[0] = hp0; d0[1] = hp1;
    if (aSide) { d1[0] = lp0; d1[1] = lp1; d2[0] = hp0; d2[1] = hp1; }
    else       { d1[0] = hp0; d1[1] = hp1; d2[0] = lp0; d2[1] = lp1; }
}

// ===================== templated mma.sync bf16 GEMM (2-stage, R10) ==========
// MODE 0: C0/C1 fp32 split-column output (+bias)
// MODE 1: qkv epilogue -> qbf/kbf triples + yvf fp32 [bh][m][64] (C1 = yvf)
// MODE 2: per-(b,h) qk: S = 0.125 * q@k^T
template<int KBYTES, int NITER, int MODE>
__global__ __launch_bounds__(256) void mma_gemm_t(
    const __nv_bfloat16* __restrict__ A,
    const __nv_bfloat16* __restrict__ Bw,
    float* __restrict__ C0, float* __restrict__ C1,
    const float* __restrict__ bias, int split, int ld0, int ld1,
    __nv_bfloat16* __restrict__ qbf, __nv_bfloat16* __restrict__ kbf)
{
    __shared__ __align__(16) char smem[2][16384];
    const int tid = threadIdx.x;
    const int wid = tid >> 5, lane = tid & 31;
    const int warp_m = wid >> 1, warp_n = wid & 1;

    int m0, n0;
    const char *Ag, *Bg;
    if (MODE == 2) {
        const size_t off = (size_t)blockIdx.x * 128 * KBYTES;
        Ag = (const char*)A + off;
        Bg = (const char*)Bw + off;
        m0 = 0; n0 = 0;
    } else {
        m0 = blockIdx.y * 128; n0 = blockIdx.x * 128;
        Ag = (const char*)A  + (size_t)m0 * KBYTES;
        Bg = (const char*)Bw + (size_t)n0 * KBYTES;
    }

    const int lr = tid >> 2, lc = tid & 3;
    const uint32_t lso  = (uint32_t)(lr * 64 + ((lc ^ (lr & 3)) << 4));
    const uint32_t lso2 = (uint32_t)((lr + 64) * 64 + ((lc ^ ((lr + 64) & 3)) << 4));
    uint32_t sbase = smem_u32(&smem[0][0]);

    auto stage_load = [&](int st, int k0b) {
        uint32_t sA = sbase + st * 16384;
        uint32_t sB = sA + 8192;
        const char* a0 = Ag + (size_t)lr * KBYTES + k0b + lc * 16;
        const char* b0 = Bg + (size_t)lr * KBYTES + k0b + lc * 16;
        cp_async16(sA + lso,  a0);
        cp_async16(sB + lso,  b0);
        cp_async16(sA + lso2, a0 + (size_t)64 * KBYTES);
        cp_async16(sB + lso2, b0 + (size_t)64 * KBYTES);
    };

    float acc[2][8][4];
#pragma unroll
    for (int i = 0; i < 2; i++)
#pragma unroll
        for (int j = 0; j < 8; j++)
#pragma unroll
            for (int t = 0; t < 4; t++) acc[i][j][t] = 0.f;

    stage_load(0, 0);
    cp_commit();

    const int a_row = warp_m * 32 + (lane & 15);
    const int a_chsel = lane >> 4;
    const int b_mi = lane >> 3;
    const int b_row = warp_n * 64 + ((b_mi >> 1) << 3) + (lane & 7);
    const int b_chsel = b_mi & 1;

    for (int it = 0; it < NITER; it++) {
        cp_wait0();
        __syncthreads();
        if (it + 1 < NITER) { stage_load((it + 1) & 1, (it + 1) * 64); cp_commit(); }

        const uint32_t sA = sbase + (it & 1) * 16384;
        const uint32_t sB = sA + 8192;
#pragma unroll
        for (int kk = 0; kk < 2; kk++) {
            uint32_t a[2][4];
#pragma unroll
            for (int i = 0; i < 2; i++) {
                int r = a_row + i * 16;
                int ch = 2 * kk + a_chsel;
                ldsm_x4(a[i], sA + r * 64 + ((ch ^ (r & 3)) << 4));
            }
            uint32_t b[8][2];
#pragma unroll
            for (int g = 0; g < 4; g++) {
                int r = b_row + g * 16;
                int ch = 2 * kk + b_chsel;
                uint32_t rr[4];
                ldsm_x4(rr, sB + r * 64 + ((ch ^ (r & 3)) << 4));
                b[2 * g][0] = rr[0]; b[2 * g][1] = rr[1];
                b[2 * g + 1][0] = rr[2]; b[2 * g + 1][1] = rr[3];
            }
#pragma unroll
            for (int i = 0; i < 2; i++)
#pragma unroll
                for (int j = 0; j < 8; j++)
                    mma16816(acc[i][j], a[i], b[j]);
        }
        __syncthreads();
    }

    const int gq = lane >> 2, t4 = lane & 3;

    if (MODE == 2) {
        float* Sp = C0 + (size_t)blockIdx.x * kN * kN;
#pragma unroll
        for (int i = 0; i < 2; i++) {
#pragma unroll
            for (int j = 0; j < 8; j++) {
                int col = warp_n * 64 + j * 8 + t4 * 2;
                int r0 = warp_m * 32 + i * 16 + gq;
                *(float2*)&Sp[(size_t)r0 * kN + col] =
                    make_float2(acc[i][j][0] * 0.125f, acc[i][j][1] * 0.125f);
                *(float2*)&Sp[(size_t)(r0 + 8) * kN + col] =
                    make_float2(acc[i][j][2] * 0.125f, acc[i][j][3] * 0.125f);
            }
        }
        return;
    }

    if (MODE == 1) {
        auto emit = [&](int row, int colg, float f0, float f1) {
            if (colg < 1024) {
                const bool isQ = colg < 512;
                const int c = isQ ? colg : colg - 512;
                const int h = c >> 6, d = c & 63;
                __nv_bfloat16 h0 = __float2bfloat16(f0);
                __nv_bfloat16 h1 = __float2bfloat16(f1);
                __nv_bfloat16 l0 = __float2bfloat16(f0 - __bfloat162float(h0));
                __nv_bfloat16 l1 = __float2bfloat16(f1 - __bfloat162float(h1));
                uint32_t hp = pack_bf2(h0, h1);
                uint32_t lp = pack_bf2(l0, l1);
                const int bb = row >> 7, nn = row & 127;
                __nv_bfloat16* base = (isQ ? qbf : kbf)
                    + ((size_t)((bb * kH + h) * kN + nn)) * kKq + d;
                *(uint32_t*)(base)       = hp;
                *(uint32_t*)(base + 64)  = isQ ? lp : hp;
                *(uint32_t*)(base + 128) = isQ ? hp : lp;
            } else {
                const int c = colg - 1024;
                const int h = c >> 6, d = c & 63;
                const int bb = row >> 7, m = row & 127;
                *(float2*)&C1[((size_t)((bb * kH + h) * kN + m)) * kHD + d] =
                    make_float2(f0, f1);
            }
        };
#pragma unroll
        for (int i = 0; i < 2; i++) {
#pragma unroll
            for (int j = 0; j < 8; j++) {
                int colg = n0 + warp_n * 64 + j * 8 + t4 * 2;
                int row0 = m0 + warp_m * 32 + i * 16 + gq;
                emit(row0,     colg, acc[i][j][0], acc[i][j][1]);
                emit(row0 + 8, colg, acc[i][j][2], acc[i][j][3]);
            }
        }
        return;
    }

    // MODE 0
#pragma unroll
    for (int i = 0; i < 2; i++) {
#pragma unroll
        for (int j = 0; j < 8; j++) {
            int colg = n0 + warp_n * 64 + j * 8 + t4 * 2;
            float bz0 = bias ? bias[colg]     : 0.f;
            float bz1 = bias ? bias[colg + 1] : 0.f;
            float* Cc; int ldc, cc;
            if (colg < split) { Cc = C0; ldc = ld0; cc = colg; }
            else              { Cc = C1; ldc = ld1; cc = colg - split; }
            int row0 = m0 + warp_m * 32 + i * 16 + gq;
            *(float2*)&Cc[(size_t)row0 * ldc + cc] =
                make_float2(acc[i][j][0] + bz0, acc[i][j][1] + bz1);
            *(float2*)&Cc[(size_t)(row0 + 8) * ldc + cc] =
                make_float2(acc[i][j][2] + bz0, acc[i][j][3] + bz1);
        }
    }
}

// ===================== att v6: R10 layout + SMEM partial-sum reduce =========
// Block per (b,n). Warp h: conflict-free lane*4 dots; 2 shfl + 8 partials.
__global__ __launch_bounds__(256) void att_kernel(
    const float* __restrict__ S, const float* __restrict__ AsTg,
    const void* __restrict__ mask, const float* __restrict__ rel_bias,
    float* __restrict__ Wf)
{
    __shared__ __align__(16) float As[kR * 132];
    __shared__ __align__(16) float Ss[kH * 132];
    __shared__ __align__(16) float Lp[kH * kR * 8];   // 4.4 KB partials
    __shared__ __align__(16) float Ls[kH * 20];
    __shared__ __align__(16) float Ps[kH * 20];
    __shared__ __align__(16) float rb[136];
    __shared__ __align__(16) int   mk[kR];

    const int t = threadIdx.x, wid = t >> 5, lane = t & 31;
    const int b = blockIdx.x >> 7, n = blockIdx.x & 127;

    // loads (all coalesced)
    {
        const int h = t >> 5, m0 = (t & 31) * 4;
        *(float4*)&Ss[h * 132 + m0] =
            *(const float4*)&S[(((size_t)(b * kH + h)) * kN + n) * kN + m0];
    }
    const float* ag = AsTg + (size_t)n * (kR * kN);
    for (int i = t; i < 544; i += 256) {
        const int r = i >> 5, m0 = (i & 31) * 4;
        *(float4*)&As[r * 132 + m0] = *(const float4*)&ag[r * kN + m0];
    }
    if (t < 136) rb[t] = rel_bias[t];
    if (t < kR) {
        int mode = g_mask_mode;
        int idx = n * kR + t;
        bool m_;
        if (mode == 0)      m_ = ((const int*)mask)[idx] != 0;
        else if (mode == 1) m_ = ((const float*)mask)[idx] != 0.f;
        else                m_ = ((const unsigned char*)mask)[idx] != 0;
        mk[t] = m_ ? 1 : 0;
    }
    __syncthreads();

    // logits partials: warp = head h; lane dot over 4 m; reduce 4 lanes -> 1
    {
        const int h = wid;
        float4 sv = *(const float4*)&Ss[h * 132 + lane * 4];
#pragma unroll
        for (int r = 0; r < kR; r++) {
            float4 av = *(const float4*)&As[r * 132 + lane * 4];
            float d = dot4(sv, av);
            d += __shfl_xor_sync(0xFFFFFFFFu, d, 1);
            d += __shfl_xor_sync(0xFFFFFFFFu, d, 2);
            if ((lane & 3) == 0)
                Lp[(h * kR + r) * 8 + (lane >> 2)] = d;
        }
    }
    __syncthreads();

    // finalize logits: 136 threads, sum 8 partials + mask/bias
    if (t < 136) {
        const int h = t / kR, r = t - h * kR;
        const float* p = &Lp[t * 8];
        float s = ((p[0] + p[1]) + (p[2] + p[3]))
                + ((p[4] + p[5]) + (p[6] + p[7]));
        Ls[h * 20 + r] = mk[r] ? neg_inf() : (s + rb[t]);
    }
    __syncthreads();

    // softmax: warp wid == head h, lanes 0..16
    {
        const int h = wid;
        float v = (lane < kR) ? Ls[h * 20 + lane] : neg_inf();
        float mx = v;
#pragma unroll
        for (int o = 16; o > 0; o >>= 1)
            mx = fmaxf(mx, __shfl_xor_sync(0xFFFFFFFFu, mx, o));
        float e = (lane < kR) ? __expf(v - mx) : 0.f;
        float s = e;
#pragma unroll
        for (int o = 16; o > 0; o >>= 1)
            s += __shfl_xor_sync(0xFFFFFFFFu, s, o);
        if (lane < kR) Ps[h * 20 + lane] = e / s;
    }
    __syncthreads();

    // W: thread = (h-group, m); 4 heads per thread
    {
        const int m = t & 127, hg = t >> 7;
        float acc[4] = {0.f, 0.f, 0.f, 0.f};
#pragma unroll
        for (int r = 0; r < kR; r++) {
            float a = As[r * 132 + m];
#pragma unroll
            for (int u = 0; u < 4; u++)
                acc[u] += Ps[(hg * 4 + u) * 20 + r] * a;
        }
#pragma unroll
        for (int u = 0; u < 4; u++)
            Wf[(((size_t)(b * kH + hg * 4 + u)) * kN + n) * kN + m] = acc[u];
    }
}

// ===================== av combo mma: O = W @ yv^T per (b,h) =================
__global__ __launch_bounds__(256) void av_mma_kernel(
    const float* __restrict__ Wf, const float* __restrict__ yvf,
    __nv_bfloat16* __restrict__ AO)
{
    extern __shared__ __align__(16) char dsm[];
    const int tid = threadIdx.x, wid = tid >> 5, lane = tid & 31;
    const int bh = blockIdx.x;
    const int warp_m = wid >> 1, warp_n = wid & 1;
    const uint32_t sbase = smem_u32(dsm);           // A stages: 8 x 8KB
    const uint32_t vbase = sbase + 65536u;          // B stages: 8 x 4KB

    const float* Wb = Wf + (size_t)bh * kN * kN;
    {
        const int mq = tid & 31, r0 = tid >> 5;
#pragma unroll
        for (int i = 0; i < 16; i++) {
            const int row = r0 + 8 * i;
            float4 v = *(const float4*)&Wb[(size_t)row * kN + mq * 4];
            float f[4] = {v.x, v.y, v.z, v.w};
            __nv_bfloat16 hi[4], lo[4];
#pragma unroll
            for (int u = 0; u < 4; u++) {
                hi[u] = __float2bfloat16(f[u]);
                lo[u] = __float2bfloat16(f[u] - __bfloat162float(hi[u]));
            }
            const int m0 = mq * 4;
            const int stage = m0 >> 5;
            const int ch = (m0 & 31) >> 3;
            const int hb = (m0 & 7) >> 2;
            uint32_t addr = sbase + stage * 8192 + row * 64
                          + ((ch ^ (row & 3)) << 4) + hb * 8;
            sts64(addr, pack_bf2(hi[0], hi[1]), pack_bf2(hi[2], hi[3]));
            sts64(addr + 4 * 8192, pack_bf2(lo[0], lo[1]), pack_bf2(lo[2], lo[3]));
        }
    }
    const float* Vb = yvf + (size_t)bh * kN * kHD;
    {
        const int dq = tid & 15, mp0 = tid >> 4;
#pragma unroll
        for (int i = 0; i < 4; i++) {
            const int mp = mp0 + 16 * i;
            const int m0 = 2 * mp;
            float4 v0 = *(const float4*)&Vb[(size_t)m0 * kHD + dq * 4];
            float4 v1 = *(const float4*)&Vb[(size_t)(m0 + 1) * kHD + dq * 4];
            float f0[4] = {v0.x, v0.y, v0.z, v0.w};
            float f1[4] = {v1.x, v1.y, v1.z, v1.w};
            const int stage = m0 >> 5;
            const int ch = (m0 & 31) >> 3;
            const int ob = (m0 & 7) * 2;
#pragma unroll
            for (int u = 0; u < 4; u++) {
                const int row = dq * 4 + u;
                __nv_bfloat16 h0 = __float2bfloat16(f0[u]);
                __nv_bfloat16 h1 = __float2bfloat16(f1[u]);
                __nv_bfloat16 l0 = __float2bfloat16(f0[u] - __bfloat162float(h0));
                __nv_bfloat16 l1 = __float2bfloat16(f1[u] - __bfloat162float(h1));
                uint32_t addr = vbase + stage * 4096 + row * 64
                              + ((ch ^ (row & 3)) << 4) + ob;
                sts32(addr, pack_bf2(h0, h1));
                sts32(addr + 4 * 4096, pack_bf2(l0, l1));
            }
        }
    }
    __syncthreads();

    float acc[2][4][4];
#pragma unroll
    for (int i = 0; i < 2; i++)
#pragma unroll
        for (int j = 0; j < 4; j++)
#pragma unroll
            for (int t = 0; t < 4; t++) acc[i][j][t] = 0.f;

    const int a_row = warp_m * 32 + (lane & 15);
    const int a_chsel = lane >> 4;
    const int b_mi = lane >> 3;
    const int b_row = warp_n * 32 + ((b_mi >> 1) << 3) + (lane & 7);
    const int b_chsel = b_mi & 1;

    const int schedA[12] = {0,1,2,3, 4,5,6,7, 0,1,2,3};
    const int schedB[12] = {0,1,2,3, 0,1,2,3, 4,5,6,7};

#pragma unroll
    for (int it = 0; it < 12; it++) {
        const uint32_t sA = sbase + schedA[it] * 8192;
        const uint32_t sB = vbase + schedB[it] * 4096;
#pragma unroll
        for (int kk = 0; kk < 2; kk++) {
            uint32_t a[2][4];
#pragma unroll
            for (int i = 0; i < 2; i++) {
                int r = a_row + i * 16;
                int ch = 2 * kk + a_chsel;
                ldsm_x4(a[i], sA + r * 64 + ((ch ^ (r & 3)) << 4));
            }
            uint32_t b[4][2];
#pragma unroll
            for (int g = 0; g < 2; g++) {
                int r = b_row + g * 16;
                int ch = 2 * kk + b_chsel;
                uint32_t rr[4];
                ldsm_x4(rr, sB + r * 64 + ((ch ^ (r & 3)) << 4));
                b[2 * g][0] = rr[0]; b[2 * g][1] = rr[1];
                b[2 * g + 1][0] = rr[2]; b[2 * g + 1][1] = rr[3];
            }
#pragma unroll
            for (int i = 0; i < 2; i++)
#pragma unroll
                for (int j = 0; j < 4; j++)
                    mma16816(acc[i][j], a[i], b[j]);
        }
    }

    const int gq = lane >> 2, t4 = lane & 3;
    const int b_ = bh >> 3, h_ = bh & 7;
#pragma unroll
    for (int i = 0; i < 2; i++) {
#pragma unroll
        for (int j = 0; j < 4; j++) {
            const int d = warp_n * 32 + j * 8 + t4 * 2;
            const int c = h_ * kHD + d;
#pragma unroll
            for (int rr = 0; rr < 2; rr++) {
                const int nrow = warp_m * 32 + i * 16 + gq + rr * 8;
                const float f0 = acc[i][j][rr * 2], f1 = acc[i][j][rr * 2 + 1];
                __nv_bfloat16 h0 = __float2bfloat16(f0), h1 = __float2bfloat16(f1);
                __nv_bfloat16 l0 = __float2bfloat16(f0 - __bfloat162float(h0));
                __nv_bfloat16 l1 = __float2bfloat16(f1 - __bfloat162float(h1));
                __nv_bfloat16* base = AO + (size_t)(b_ * kN + nrow) * kKp + c;
                *(uint32_t*)(base)        = pack_bf2(h0, h1);
                *(uint32_t*)(base + 512)  = pack_bf2(l0, l1);
                *(uint32_t*)(base + 1024) = pack_bf2(h0, h1);
            }
        }
    }
}

// ===================== launch =====================
extern "C" void kernel_launch(void* const* d_in, const int* in_sizes, int n_in,
                              void* d_out, int out_size)
{
    const float* x        = (const float*)d_in[0];
    const float* assign   = (const float*)d_in[1];
    const void*  mask     = d_in[2];
    const float* q_w      = (const float*)d_in[3];
    const float* kv_w     = (const float*)d_in[4];
    const float* rel_bias = (const float*)d_in[5];
    const float* proj_w   = (const float*)d_in[6];
    const float* proj_b   = (const float*)d_in[7];

    float *S, *Wfp, *yvf, *AsTg;
    __nv_bfloat16 *Ax, *Bqkv, *Bproj, *AO, *qbf, *kbf;
    cudaGetSymbolAddress((void**)&S,    g_S);
    cudaGetSymbolAddress((void**)&Wfp,  g_Wf);
    cudaGetSymbolAddress((void**)&yvf,  g_yvf);
    cudaGetSymbolAddress((void**)&AsTg, g_AsT);
    cudaGetSymbolAddress((void**)&Ax,    g_Ax);
    cudaGetSymbolAddress((void**)&Bqkv,  g_Bqkv);
    cudaGetSymbolAddress((void**)&Bproj, g_Bproj);
    cudaGetSymbolAddress((void**)&AO,    g_AO);
    cudaGetSymbolAddress((void**)&qbf,   g_qbf);
    cudaGetSymbolAddress((void**)&kbf,   g_kbf);

    const int AV_SMEM = 8 * 8192 + 8 * 4096;  // 96 KB
    cudaFuncSetAttribute(av_mma_kernel,
                         cudaFuncAttributeMaxDynamicSharedMemorySize, AV_SMEM);

    // 1. input hi/lo splits + mask probe + A transpose
    convert_all_kernel<<<4225, 128>>>(x, q_w, kv_w, proj_w, assign, mask,
                                      Ax, Bqkv, Bproj, AsTg);

    // 2. fused q/kv projection -> qbf/kbf triples + yvf fp32
    mma_gemm_t<3072, 48, 1><<<dim3(12, 16), 256>>>(
        Ax, Bqkv, nullptr, yvf, nullptr, 0, 0, 0, qbf, kbf);

    // 3. S = 0.125 * q@k^T per (b,h)
    mma_gemm_t<384, 6, 2><<<dim3(128, 1), 256>>>(
        qbf, kbf, S, nullptr, nullptr, 0, 0, 0, nullptr, nullptr);

    // 4. logits + masked softmax + W (fp32)
    att_kernel<<<kB * kN, 256>>>(S, AsTg, mask, rel_bias, Wfp);

    // 5. O = W @ yv per (b,h), combo split-K on tensor cores (emits AO triple)
    av_mma_kernel<<<128, 256, AV_SMEM>>>(Wfp, yvf, AO);

    // 6. out-proj: AO @ Bproj^T + bias
    mma_gemm_t<3072, 48, 0><<<dim3(4, 16), 256>>>(
        AO, Bproj, (float*)d_out, (float*)d_out, proj_b, 1 << 30, kC, kC,
        nullptr, nullptr);
}

// round 13
// speedup vs baseline: 1.2466x; 1.1313x over previous
#include <cuda_runtime.h>
#include <cuda_bf16.h>
#include <cstdint>

// Problem dims
constexpr int kB  = 16;
constexpr int kN  = 128;
constexpr int kC  = 512;
constexpr int kH  = 8;
constexpr int kR  = 17;
constexpr int kHD = 64;
constexpr int kBN = kB * kN;    // 2048
constexpr int kKp = 3 * kC;     // 1536 split-K' (c contraction)
constexpr int kKq = 3 * kHD;    // 192 split-K' (d contraction, qk)

// Scratch (device globals; no allocations allowed)
__device__ float g_S[kB * kH * kN * kN];  // 8 MB (pre-scaled by 0.125)
__device__ float g_Wf[kB * kH * kN * kN]; // 8 MB attention weights fp32
__device__ float g_yvf[kB * kH * kN * kHD]; // 4 MB yv fp32 [bh][m][64]
__device__ float g_AsT[kN * kR * kN];     // 1.1 MB A^T fp32 [n][r][128m]
__device__ int   g_mask_mode;
__device__ __nv_bfloat16 g_Ax[kBN * kKp];        // x hi|lo|hi
__device__ __nv_bfloat16 g_Bqkv[kKp * kKp];      // [q_w;kv_w] hi|hi|lo
__device__ __nv_bfloat16 g_Bproj[kC * kKp];      // proj_w hi|hi|lo
__device__ __nv_bfloat16 g_AO[kBN * kKp];        // O hi|lo|hi (av epilogue)
__device__ __nv_bfloat16 g_qbf[kB * kH * kN * kKq]; // q hi|lo|hi per (b,h)
__device__ __nv_bfloat16 g_kbf[kB * kH * kN * kKq]; // k hi|hi|lo per (b,h)

__device__ __forceinline__ float neg_inf() { return __int_as_float(0xFF800000); }

// ===================== baseline-PTX helpers =====================
__device__ __forceinline__ uint32_t smem_u32(const void* p) {
    uint32_t a;
    asm("{ .reg .u64 t; cvta.to.shared.u64 t, %1; cvt.u32.u64 %0, t; }"
        : "=r"(a) : "l"(p));
    return a;
}
__device__ __forceinline__ void cp_async16(uint32_t saddr, const void* gaddr) {
    asm volatile("cp.async.cg.shared.global [%0], [%1], 16;"
                 :: "r"(saddr), "l"(gaddr) : "memory");
}
__device__ __forceinline__ void cp_commit() {
    asm volatile("cp.async.commit_group;" ::: "memory");
}
__device__ __forceinline__ void cp_wait0() {
    asm volatile("cp.async.wait_group 0;" ::: "memory");
}
__device__ __forceinline__ void ldsm_x4(uint32_t* r, uint32_t addr) {
    asm volatile("ldmatrix.sync.aligned.m8n8.x4.shared.b16 {%0,%1,%2,%3}, [%4];"
                 : "=r"(r[0]), "=r"(r[1]), "=r"(r[2]), "=r"(r[3]) : "r"(addr));
}
__device__ __forceinline__ void mma16816(float* d, const uint32_t* a, const uint32_t* b) {
    asm volatile("mma.sync.aligned.m16n8k16.row.col.f32.bf16.bf16.f32 "
                 "{%0,%1,%2,%3}, {%4,%5,%6,%7}, {%8,%9}, {%0,%1,%2,%3};"
                 : "+f"(d[0]), "+f"(d[1]), "+f"(d[2]), "+f"(d[3])
                 : "r"(a[0]), "r"(a[1]), "r"(a[2]), "r"(a[3]),
                   "r"(b[0]), "r"(b[1]));
}
__device__ __forceinline__ uint32_t pack_bf2(__nv_bfloat16 lo, __nv_bfloat16 hi) {
    return ((uint32_t)__bfloat16_as_ushort(hi) << 16) | __bfloat16_as_ushort(lo);
}
__device__ __forceinline__ void sts32(uint32_t addr, uint32_t v) {
    asm volatile("st.shared.b32 [%0], %1;" :: "r"(addr), "r"(v) : "memory");
}
__device__ __forceinline__ void sts64(uint32_t addr, uint32_t v0, uint32_t v1) {
    asm volatile("st.shared.v2.b32 [%0], {%1,%2};" :: "r"(addr), "r"(v0), "r"(v1) : "memory");
}
__device__ __forceinline__ float dot4(float4 a, float4 b) {
    return a.x * b.x + a.y * b.y + a.z * b.z + a.w * b.w;
}

// ===================== fused converts + mask probe + A-transpose ============
__global__ __launch_bounds__(128) void convert_all_kernel(
    const float* __restrict__ x, const float* __restrict__ q_w,
    const float* __restrict__ kv_w, const float* __restrict__ proj_w,
    const float* __restrict__ assign, const void* __restrict__ mask,
    __nv_bfloat16* __restrict__ Ax, __nv_bfloat16* __restrict__ Bqkv,
    __nv_bfloat16* __restrict__ Bproj, float* __restrict__ AsTg)
{
    const int rb = blockIdx.x;
    if (rb == 4096) {
        __shared__ int s_not_i32, s_not_f32;
        if (threadIdx.x == 0) { s_not_i32 = 0; s_not_f32 = 0; }
        __syncthreads();
        const unsigned int* w = (const unsigned int*)mask;
        int bad_i = 0, bad_f = 0;
        for (int i = threadIdx.x; i < 544; i += 128) {
            unsigned int v = w[i];
            if (v > 1u) bad_i = 1;
            if (v != 0u && v != 0x3F800000u) bad_f = 1;
        }
        if (bad_i) atomicOr(&s_not_i32, 1);
        if (bad_f) atomicOr(&s_not_f32, 1);
        __syncthreads();
        if (threadIdx.x == 0)
            g_mask_mode = (!s_not_i32) ? 0 : ((!s_not_f32) ? 1 : 2);
        return;
    }
    if (rb >= 4097) {
        const int n = rb - 4097;
        __shared__ __align__(16) float At[2176];
        const float* arow = assign + (size_t)n * 2176;
        for (int i = threadIdx.x; i < 544; i += 128)
            *(float4*)&At[i * 4] = *(const float4*)&arow[i * 4];
        __syncthreads();
        float* out = AsTg + (size_t)n * 2176;
        for (int j = threadIdx.x; j < 544; j += 128) {
            const int o = j * 4;
            const int r = o >> 7, m = o & 127;
            float4 v = make_float4(At[m * kR + r], At[(m + 1) * kR + r],
                                   At[(m + 2) * kR + r], At[(m + 3) * kR + r]);
            *(float4*)&out[o] = v;
        }
        return;
    }
    const float* src;
    __nv_bfloat16* dst;
    bool aSide;
    if (rb < 2048)      { src = x + (size_t)rb * kC;             dst = Ax + (size_t)rb * kKp;           aSide = true;  }
    else if (rb < 2560) { int r = rb - 2048; src = q_w + (size_t)r * kC;    dst = Bqkv + (size_t)r * kKp;        aSide = false; }
    else if (rb < 3584) { int r = rb - 2560; src = kv_w + (size_t)r * kC;   dst = Bqkv + (size_t)(kC + r) * kKp; aSide = false; }
    else                { int r = rb - 3584; src = proj_w + (size_t)r * kC; dst = Bproj + (size_t)r * kKp;       aSide = false; }

    const int j0 = threadIdx.x * 4;
    float4 v = *(const float4*)&src[j0];
    float f[4] = {v.x, v.y, v.z, v.w};
    __nv_bfloat16 hi[4], lo[4];
#pragma unroll
    for (int t = 0; t < 4; t++) {
        hi[t] = __float2bfloat16(f[t]);
        lo[t] = __float2bfloat16(f[t] - __bfloat162float(hi[t]));
    }
    uint32_t hp0 = pack_bf2(hi[0], hi[1]), hp1 = pack_bf2(hi[2], hi[3]);
    uint32_t lp0 = pack_bf2(lo[0], lo[1]), lp1 = pack_bf2(lo[2], lo[3]);
    uint32_t* d0 = (uint32_t*)(dst + j0);
    uint32_t* d1 = (uint32_t*)(dst + kC + j0);
    uint32_t* d2 = (uint32_t*)(dst + 2 * kC + j0);
    d0[0] = hp0; d0[1] = hp1;
    if (aSide) { d1[0] = lp0; d1[1] = lp1; d2[0] = hp0; d2[1] = hp1; }
    else       { d1[0] = hp0; d1[1] = hp1; d2[0] = lp0; d2[1] = lp1; }
}

// ===================== templated mma.sync bf16 GEMM =========================
// MTILE = rows per block (64/128/256). N-tile fixed at 128.
// MODE 0: C0/C1 fp32 split-column output (+bias)
// MODE 1: qkv epilogue -> qbf/kbf triples + yvf fp32 [bh][m][64] (C1 = yvf)
// MODE 2: per-(b,h) qk: S = 0.125 * q@k^T  (MTILE must be 128)
template<int KBYTES, int NITER, int MODE, int MTILE>
__global__ __launch_bounds__(256) void mma_gemm_t(
    const __nv_bfloat16* __restrict__ A,
    const __nv_bfloat16* __restrict__ Bw,
    float* __restrict__ C0, float* __restrict__ C1,
    const float* __restrict__ bias, int split, int ld0, int ld1,
    __nv_bfloat16* __restrict__ qbf, __nv_bfloat16* __restrict__ kbf)
{
    constexpr int IR = MTILE / 64;          // i-range (m16 groups per warp)
    constexpr int ASTG = MTILE * 64;        // A stage bytes
    constexpr int STAGE = ASTG + 8192;      // stage bytes (A + B)
    __shared__ __align__(16) char smem[2 * STAGE];
    const int tid = threadIdx.x;
    const int wid = tid >> 5, lane = tid & 31;
    const int warp_m = wid >> 1, warp_n = wid & 1;

    int m0, n0;
    const char *Ag, *Bg;
    if (MODE == 2) {
        const size_t off = (size_t)blockIdx.x * 128 * KBYTES;
        Ag = (const char*)A + off;
        Bg = (const char*)Bw + off;
        m0 = 0; n0 = 0;
    } else {
        m0 = blockIdx.y * MTILE; n0 = blockIdx.x * 128;
        Ag = (const char*)A  + (size_t)m0 * KBYTES;
        Bg = (const char*)Bw + (size_t)n0 * KBYTES;
    }

    const int lr = tid >> 2, lc = tid & 3;
    uint32_t sbase = smem_u32(&smem[0]);
    auto so = [&](int row) {
        return (uint32_t)(row * 64 + ((lc ^ (row & 3)) << 4));
    };

    auto stage_load = [&](int st, int k0b) {
        uint32_t sA = sbase + st * STAGE;
        uint32_t sB = sA + ASTG;
#pragma unroll
        for (int p = 0; p < IR; p++) {
            int row = lr + p * 64;
            cp_async16(sA + so(row), Ag + (size_t)row * KBYTES + k0b + lc * 16);
        }
        cp_async16(sB + so(lr), Bg + (size_t)lr * KBYTES + k0b + lc * 16);
        cp_async16(sB + so(lr + 64),
                   Bg + (size_t)(lr + 64) * KBYTES + k0b + lc * 16);
    };

    float acc[IR][8][4];
#pragma unroll
    for (int i = 0; i < IR; i++)
#pragma unroll
        for (int j = 0; j < 8; j++)
#pragma unroll
            for (int t = 0; t < 4; t++) acc[i][j][t] = 0.f;

    stage_load(0, 0);
    cp_commit();

    const int a_row = warp_m * (MTILE / 4) + (lane & 15);
    const int a_chsel = lane >> 4;
    const int b_mi = lane >> 3;
    const int b_row = warp_n * 64 + ((b_mi >> 1) << 3) + (lane & 7);
    const int b_chsel = b_mi & 1;

    for (int it = 0; it < NITER; it++) {
        cp_wait0();
        __syncthreads();
        if (it + 1 < NITER) { stage_load((it + 1) & 1, (it + 1) * 64); cp_commit(); }

        const uint32_t sA = sbase + (it & 1) * STAGE;
        const uint32_t sB = sA + ASTG;
#pragma unroll
        for (int kk = 0; kk < 2; kk++) {
            uint32_t a[IR][4];
#pragma unroll
            for (int i = 0; i < IR; i++) {
                int r = a_row + i * 16;
                int ch = 2 * kk + a_chsel;
                ldsm_x4(a[i], sA + r * 64 + ((ch ^ (r & 3)) << 4));
            }
            uint32_t b[8][2];
#pragma unroll
            for (int g = 0; g < 4; g++) {
                int r = b_row + g * 16;
                int ch = 2 * kk + b_chsel;
                uint32_t rr[4];
                ldsm_x4(rr, sB + r * 64 + ((ch ^ (r & 3)) << 4));
                b[2 * g][0] = rr[0]; b[2 * g][1] = rr[1];
                b[2 * g + 1][0] = rr[2]; b[2 * g + 1][1] = rr[3];
            }
#pragma unroll
            for (int i = 0; i < IR; i++)
#pragma unroll
                for (int j = 0; j < 8; j++)
                    mma16816(acc[i][j], a[i], b[j]);
        }
        __syncthreads();
    }

    const int gq = lane >> 2, t4 = lane & 3;

    if (MODE == 2) {
        float* Sp = C0 + (size_t)blockIdx.x * kN * kN;
#pragma unroll
        for (int i = 0; i < IR; i++) {
#pragma unroll
            for (int j = 0; j < 8; j++) {
                int col = warp_n * 64 + j * 8 + t4 * 2;
                int r0 = warp_m * (MTILE / 4) + i * 16 + gq;
                *(float2*)&Sp[(size_t)r0 * kN + col] =
                    make_float2(acc[i][j][0] * 0.125f, acc[i][j][1] * 0.125f);
                *(float2*)&Sp[(size_t)(r0 + 8) * kN + col] =
                    make_float2(acc[i][j][2] * 0.125f, acc[i][j][3] * 0.125f);
            }
        }
        return;
    }

    if (MODE == 1) {
        auto emit = [&](int row, int colg, float f0, float f1) {
            if (colg < 1024) {
                const bool isQ = colg < 512;
                const int c = isQ ? colg : colg - 512;
                const int h = c >> 6, d = c & 63;
                __nv_bfloat16 h0 = __float2bfloat16(f0);
                __nv_bfloat16 h1 = __float2bfloat16(f1);
                __nv_bfloat16 l0 = __float2bfloat16(f0 - __bfloat162float(h0));
                __nv_bfloat16 l1 = __float2bfloat16(f1 - __bfloat162float(h1));
                uint32_t hp = pack_bf2(h0, h1);
                uint32_t lp = pack_bf2(l0, l1);
                const int bb = row >> 7, nn = row & 127;
                __nv_bfloat16* base = (isQ ? qbf : kbf)
                    + ((size_t)((bb * kH + h) * kN + nn)) * kKq + d;
                *(uint32_t*)(base)       = hp;
                *(uint32_t*)(base + 64)  = isQ ? lp : hp;
                *(uint32_t*)(base + 128) = isQ ? hp : lp;
            } else {
                const int c = colg - 1024;
                const int h = c >> 6, d = c & 63;
                const int bb = row >> 7, m = row & 127;
                *(float2*)&C1[((size_t)((bb * kH + h) * kN + m)) * kHD + d] =
                    make_float2(f0, f1);
            }
        };
#pragma unroll
        for (int i = 0; i < IR; i++) {
#pragma unroll
            for (int j = 0; j < 8; j++) {
                int colg = n0 + warp_n * 64 + j * 8 + t4 * 2;
                int row0 = m0 + warp_m * (MTILE / 4) + i * 16 + gq;
                emit(row0,     colg, acc[i][j][0], acc[i][j][1]);
                emit(row0 + 8, colg, acc[i][j][2], acc[i][j][3]);
            }
        }
        return;
    }

    // MODE 0
#pragma unroll
    for (int i = 0; i < IR; i++) {
#pragma unroll
        for (int j = 0; j < 8; j++) {
            int colg = n0 + warp_n * 64 + j * 8 + t4 * 2;
            float bz0 = bias ? bias[colg]     : 0.f;
            float bz1 = bias ? bias[colg + 1] : 0.f;
            float* Cc; int ldc, cc;
            if (colg < split) { Cc = C0; ldc = ld0; cc = colg; }
            else              { Cc = C1; ldc = ld1; cc = colg - split; }
            int row0 = m0 + warp_m * (MTILE / 4) + i * 16 + gq;
            *(float2*)&Cc[(size_t)row0 * ldc + cc] =
                make_float2(acc[i][j][0] + bz0, acc[i][j][1] + bz1);
            *(float2*)&Cc[(size_t)(row0 + 8) * ldc + cc] =
                make_float2(acc[i][j][2] + bz0, acc[i][j][3] + bz1);
        }
    }
}

// ===================== att v6 (R12 champion) =====================
__global__ __launch_bounds__(256) void att_kernel(
    const float* __restrict__ S, const float* __restrict__ AsTg,
    const void* __restrict__ mask, const float* __restrict__ rel_bias,
    float* __restrict__ Wf)
{
    __shared__ __align__(16) float As[kR * 132];
    __shared__ __align__(16) float Ss[kH * 132];
    __shared__ __align__(16) float Lp[kH * kR * 8];
    __shared__ __align__(16) float Ls[kH * 20];
    __shared__ __align__(16) float Ps[kH * 20];
    __shared__ __align__(16) float rb[136];
    __shared__ __align__(16) int   mk[kR];

    const int t = threadIdx.x, wid = t >> 5, lane = t & 31;
    const int b = blockIdx.x >> 7, n = blockIdx.x & 127;

    {
        const int h = t >> 5, m0 = (t & 31) * 4;
        *(float4*)&Ss[h * 132 + m0] =
            *(const float4*)&S[(((size_t)(b * kH + h)) * kN + n) * kN + m0];
    }
    const float* ag = AsTg + (size_t)n * (kR * kN);
    for (int i = t; i < 544; i += 256) {
        const int r = i >> 5, m0 = (i & 31) * 4;
        *(float4*)&As[r * 132 + m0] = *(const float4*)&ag[r * kN + m0];
    }
    if (t < 136) rb[t] = rel_bias[t];
    if (t < kR) {
        int mode = g_mask_mode;
        int idx = n * kR + t;
        bool m_;
        if (mode == 0)      m_ = ((const int*)mask)[idx] != 0;
        else if (mode == 1) m_ = ((const float*)mask)[idx] != 0.f;
        else                m_ = ((const unsigned char*)mask)[idx] != 0;
        mk[t] = m_ ? 1 : 0;
    }
    __syncthreads();

    {
        const int h = wid;
        float4 sv = *(const float4*)&Ss[h * 132 + lane * 4];
#pragma unroll
        for (int r = 0; r < kR; r++) {
            float4 av = *(const float4*)&As[r * 132 + lane * 4];
            float d = dot4(sv, av);
            d += __shfl_xor_sync(0xFFFFFFFFu, d, 1);
            d += __shfl_xor_sync(0xFFFFFFFFu, d, 2);
            if ((lane & 3) == 0)
                Lp[(h * kR + r) * 8 + (lane >> 2)] = d;
        }
    }
    __syncthreads();

    if (t < 136) {
        const int h = t / kR, r = t - h * kR;
        const float* p = &Lp[t * 8];
        float s = ((p[0] + p[1]) + (p[2] + p[3]))
                + ((p[4] + p[5]) + (p[6] + p[7]));
        Ls[h * 20 + r] = mk[r] ? neg_inf() : (s + rb[t]);
    }
    __syncthreads();

    {
        const int h = wid;
        float v = (lane < kR) ? Ls[h * 20 + lane] : neg_inf();
        float mx = v;
#pragma unroll
        for (int o = 16; o > 0; o >>= 1)
            mx = fmaxf(mx, __shfl_xor_sync(0xFFFFFFFFu, mx, o));
        float e = (lane < kR) ? __expf(v - mx) : 0.f;
        float s = e;
#pragma unroll
        for (int o = 16; o > 0; o >>= 1)
            s += __shfl_xor_sync(0xFFFFFFFFu, s, o);
        if (lane < kR) Ps[h * 20 + lane] = e / s;
    }
    __syncthreads();

    {
        const int m = t & 127, hg = t >> 7;
        float acc[4] = {0.f, 0.f, 0.f, 0.f};
#pragma unroll
        for (int r = 0; r < kR; r++) {
            float a = As[r * 132 + m];
#pragma unroll
            for (int u = 0; u < 4; u++)
                acc[u] += Ps[(hg * 4 + u) * 20 + r] * a;
        }
#pragma unroll
        for (int u = 0; u < 4; u++)
            Wf[(((size_t)(b * kH + hg * 4 + u)) * kN + n) * kN + m] = acc[u];
    }
}

// ===================== av combo mma: O = W @ yv^T per (b,h) =================
__global__ __launch_bounds__(256) void av_mma_kernel(
    const float* __restrict__ Wf, const float* __restrict__ yvf,
    __nv_bfloat16* __restrict__ AO)
{
    extern __shared__ __align__(16) char dsm[];
    const int tid = threadIdx.x, wid = tid >> 5, lane = tid & 31;
    const int bh = blockIdx.x;
    const int warp_m = wid >> 1, warp_n = wid & 1;
    const uint32_t sbase = smem_u32(dsm);
    const uint32_t vbase = sbase + 65536u;

    const float* Wb = Wf + (size_t)bh * kN * kN;
    {
        const int mq = tid & 31, r0 = tid >> 5;
#pragma unroll
        for (int i = 0; i < 16; i++) {
            const int row = r0 + 8 * i;
            float4 v = *(const float4*)&Wb[(size_t)row * kN + mq * 4];
            float f[4] = {v.x, v.y, v.z, v.w};
            __nv_bfloat16 hi[4], lo[4];
#pragma unroll
            for (int u = 0; u < 4; u++) {
                hi[u] = __float2bfloat16(f[u]);
                lo[u] = __float2bfloat16(f[u] - __bfloat162float(hi[u]));
            }
            const int m0 = mq * 4;
            const int stage = m0 >> 5;
            const int ch = (m0 & 31) >> 3;
            const int hb = (m0 & 7) >> 2;
            uint32_t addr = sbase + stage * 8192 + row * 64
                          + ((ch ^ (row & 3)) << 4) + hb * 8;
            sts64(addr, pack_bf2(hi[0], hi[1]), pack_bf2(hi[2], hi[3]));
            sts64(addr + 4 * 8192, pack_bf2(lo[0], lo[1]), pack_bf2(lo[2], lo[3]));
        }
    }
    const float* Vb = yvf + (size_t)bh * kN * kHD;
    {
        const int dq = tid & 15, mp0 = tid >> 4;
#pragma unroll
        for (int i = 0; i < 4; i++) {
            const int mp = mp0 + 16 * i;
            const int m0 = 2 * mp;
            float4 v0 = *(const float4*)&Vb[(size_t)m0 * kHD + dq * 4];
            float4 v1 = *(const float4*)&Vb[(size_t)(m0 + 1) * kHD + dq * 4];
            float f0[4] = {v0.x, v0.y, v0.z, v0.w};
            float f1[4] = {v1.x, v1.y, v1.z, v1.w};
            const int stage = m0 >> 5;
            const int ch = (m0 & 31) >> 3;
            const int ob = (m0 & 7) * 2;
#pragma unroll
            for (int u = 0; u < 4; u++) {
                const int row = dq * 4 + u;
                __nv_bfloat16 h0 = __float2bfloat16(f0[u]);
                __nv_bfloat16 h1 = __float2bfloat16(f1[u]);
                __nv_bfloat16 l0 = __float2bfloat16(f0[u] - __bfloat162float(h0));
                __nv_bfloat16 l1 = __float2bfloat16(f1[u] - __bfloat162float(h1));
                uint32_t addr = vbase + stage * 4096 + row * 64
                              + ((ch ^ (row & 3)) << 4) + ob;
                sts32(addr, pack_bf2(h0, h1));
                sts32(addr + 4 * 4096, pack_bf2(l0, l1));
            }
        }
    }
    __syncthreads();

    float acc[2][4][4];
#pragma unroll
    for (int i = 0; i < 2; i++)
#pragma unroll
        for (int j = 0; j < 4; j++)
#pragma unroll
            for (int t = 0; t < 4; t++) acc[i][j][t] = 0.f;

    const int a_row = warp_m * 32 + (lane & 15);
    const int a_chsel = lane >> 4;
    const int b_mi = lane >> 3;
    const int b_row = warp_n * 32 + ((b_mi >> 1) << 3) + (lane & 7);
    const int b_chsel = b_mi & 1;

    const int schedA[12] = {0,1,2,3, 4,5,6,7, 0,1,2,3};
    const int schedB[12] = {0,1,2,3, 0,1,2,3, 4,5,6,7};

#pragma unroll
    for (int it = 0; it < 12; it++) {
        const uint32_t sA = sbase + schedA[it] * 8192;
        const uint32_t sB = vbase + schedB[it] * 4096;
#pragma unroll
        for (int kk = 0; kk < 2; kk++) {
            uint32_t a[2][4];
#pragma unroll
            for (int i = 0; i < 2; i++) {
                int r = a_row + i * 16;
                int ch = 2 * kk + a_chsel;
                ldsm_x4(a[i], sA + r * 64 + ((ch ^ (r & 3)) << 4));
            }
            uint32_t b[4][2];
#pragma unroll
            for (int g = 0; g < 2; g++) {
                int r = b_row + g * 16;
                int ch = 2 * kk + b_chsel;
                uint32_t rr[4];
                ldsm_x4(rr, sB + r * 64 + ((ch ^ (r & 3)) << 4));
                b[2 * g][0] = rr[0]; b[2 * g][1] = rr[1];
                b[2 * g + 1][0] = rr[2]; b[2 * g + 1][1] = rr[3];
            }
#pragma unroll
            for (int i = 0; i < 2; i++)
#pragma unroll
                for (int j = 0; j < 4; j++)
                    mma16816(acc[i][j], a[i], b[j]);
        }
    }

    const int gq = lane >> 2, t4 = lane & 3;
    const int b_ = bh >> 3, h_ = bh & 7;
#pragma unroll
    for (int i = 0; i < 2; i++) {
#pragma unroll
        for (int j = 0; j < 4; j++) {
            const int d = warp_n * 32 + j * 8 + t4 * 2;
            const int c = h_ * kHD + d;
#pragma unroll
            for (int rr = 0; rr < 2; rr++) {
                const int nrow = warp_m * 32 + i * 16 + gq + rr * 8;
                const float f0 = acc[i][j][rr * 2], f1 = acc[i][j][rr * 2 + 1];
                __nv_bfloat16 h0 = __float2bfloat16(f0), h1 = __float2bfloat16(f1);
                __nv_bfloat16 l0 = __float2bfloat16(f0 - __bfloat162float(h0));
                __nv_bfloat16 l1 = __float2bfloat16(f1 - __bfloat162float(h1));
                __nv_bfloat16* base = AO + (size_t)(b_ * kN + nrow) * kKp + c;
                *(uint32_t*)(base)        = pack_bf2(h0, h1);
                *(uint32_t*)(base + 512)  = pack_bf2(l0, l1);
                *(uint32_t*)(base + 1024) = pack_bf2(h0, h1);
            }
        }
    }
}

// ===================== launch =====================
extern "C" void kernel_launch(void* const* d_in, const int* in_sizes, int n_in,
                              void* d_out, int out_size)
{
    const float* x        = (const float*)d_in[0];
    const float* assign   = (const float*)d_in[1];
    const void*  mask     = d_in[2];
    const float* q_w      = (const float*)d_in[3];
    const float* kv_w     = (const float*)d_in[4];
    const float* rel_bias = (const float*)d_in[5];
    const float* proj_w   = (const float*)d_in[6];
    const float* proj_b   = (const float*)d_in[7];

    float *S, *Wfp, *yvf, *AsTg;
    __nv_bfloat16 *Ax, *Bqkv, *Bproj, *AO, *qbf, *kbf;
    cudaGetSymbolAddress((void**)&S,    g_S);
    cudaGetSymbolAddress((void**)&Wfp,  g_Wf);
    cudaGetSymbolAddress((void**)&yvf,  g_yvf);
    cudaGetSymbolAddress((void**)&AsTg, g_AsT);
    cudaGetSymbolAddress((void**)&Ax,    g_Ax);
    cudaGetSymbolAddress((void**)&Bqkv,  g_Bqkv);
    cudaGetSymbolAddress((void**)&Bproj, g_Bproj);
    cudaGetSymbolAddress((void**)&AO,    g_AO);
    cudaGetSymbolAddress((void**)&qbf,   g_qbf);
    cudaGetSymbolAddress((void**)&kbf,   g_kbf);

    const int AV_SMEM = 8 * 8192 + 8 * 4096;  // 96 KB
    cudaFuncSetAttribute(av_mma_kernel,
                         cudaFuncAttributeMaxDynamicSharedMemorySize, AV_SMEM);

    // 1. input hi/lo splits + mask probe + A transpose
    convert_all_kernel<<<4225, 128>>>(x, q_w, kv_w, proj_w, assign, mask,
                                      Ax, Bqkv, Bproj, AsTg);

    // 2. fused q/kv projection -> qbf/kbf triples + yvf fp32 (MTILE=256, 96 blocks)
    mma_gemm_t<3072, 48, 1, 256><<<dim3(12, 8), 256>>>(
        Ax, Bqkv, nullptr, yvf, nullptr, 0, 0, 0, qbf, kbf);

    // 3. S = 0.125 * q@k^T per (b,h)
    mma_gemm_t<384, 6, 2, 128><<<dim3(128, 1), 256>>>(
        qbf, kbf, S, nullptr, nullptr, 0, 0, 0, nullptr, nullptr);

    // 4. logits + masked softmax + W (fp32)
    att_kernel<<<kB * kN, 256>>>(S, AsTg, mask, rel_bias, Wfp);

    // 5. O = W @ yv per (b,h), combo split-K on tensor cores (emits AO triple)
    av_mma_kernel<<<128, 256, AV_SMEM>>>(Wfp, yvf, AO);

    // 6. out-proj: AO @ Bproj^T + bias (MTILE=64, 128 blocks)
    mma_gemm_t<3072, 48, 0, 64><<<dim3(4, 32), 256>>>(
        AO, Bproj, (float*)d_out, (float*)d_out, proj_b, 1 << 30, kC, kC,
        nullptr, nullptr);
}

// round 14
// speedup vs baseline: 1.2525x; 1.0047x over previous
#include <cuda_runtime.h>
#include <cuda_bf16.h>
#include <cstdint>

// Problem dims
constexpr int kB  = 16;
constexpr int kN  = 128;
constexpr int kC  = 512;
constexpr int kH  = 8;
constexpr int kR  = 17;
constexpr int kHD = 64;
constexpr int kBN = kB * kN;    // 2048
constexpr int kKp = 3 * kC;     // 1536 split-K' (c contraction)
constexpr int kKq = 3 * kHD;    // 192 split-K' (d contraction, qk)

// Scratch (device globals; no allocations allowed)
__device__ float g_S[kB * kH * kN * kN];  // 8 MB (pre-scaled by 0.125)
__device__ float g_Wf[kB * kH * kN * kN]; // 8 MB attention weights fp32
__device__ float g_yvf[kB * kH * kN * kHD]; // 4 MB yv fp32 [bh][m][64]
__device__ float g_AsT[kN * kR * kN];     // 1.1 MB A^T fp32 [n][r][128m]
__device__ int   g_mask_mode;
__device__ __nv_bfloat16 g_Ax[kBN * kKp];        // x hi|lo|hi
__device__ __nv_bfloat16 g_Bqkv[kKp * kKp];      // [q_w;kv_w] hi|hi|lo
__device__ __nv_bfloat16 g_Bproj[kC * kKp];      // proj_w hi|hi|lo
__device__ __nv_bfloat16 g_AO[kBN * kKp];        // O hi|lo|hi (av epilogue)
__device__ __nv_bfloat16 g_qbf[kB * kH * kN * kKq]; // q hi|lo|hi per (b,h)
__device__ __nv_bfloat16 g_kbf[kB * kH * kN * kKq]; // k hi|hi|lo per (b,h)

__device__ __forceinline__ float neg_inf() { return __int_as_float(0xFF800000); }

// ===================== baseline-PTX helpers =====================
__device__ __forceinline__ uint32_t smem_u32(const void* p) {
    uint32_t a;
    asm("{ .reg .u64 t; cvta.to.shared.u64 t, %1; cvt.u32.u64 %0, t; }"
        : "=r"(a) : "l"(p));
    return a;
}
__device__ __forceinline__ void cp_async16(uint32_t saddr, const void* gaddr) {
    asm volatile("cp.async.cg.shared.global [%0], [%1], 16;"
                 :: "r"(saddr), "l"(gaddr) : "memory");
}
__device__ __forceinline__ void cp_commit() {
    asm volatile("cp.async.commit_group;" ::: "memory");
}
__device__ __forceinline__ void cp_wait0() {
    asm volatile("cp.async.wait_group 0;" ::: "memory");
}
__device__ __forceinline__ void ldsm_x4(uint32_t* r, uint32_t addr) {
    asm volatile("ldmatrix.sync.aligned.m8n8.x4.shared.b16 {%0,%1,%2,%3}, [%4];"
                 : "=r"(r[0]), "=r"(r[1]), "=r"(r[2]), "=r"(r[3]) : "r"(addr));
}
__device__ __forceinline__ void mma16816(float* d, const uint32_t* a, const uint32_t* b) {
    asm volatile("mma.sync.aligned.m16n8k16.row.col.f32.bf16.bf16.f32 "
                 "{%0,%1,%2,%3}, {%4,%5,%6,%7}, {%8,%9}, {%0,%1,%2,%3};"
                 : "+f"(d[0]), "+f"(d[1]), "+f"(d[2]), "+f"(d[3])
                 : "r"(a[0]), "r"(a[1]), "r"(a[2]), "r"(a[3]),
                   "r"(b[0]), "r"(b[1]));
}
__device__ __forceinline__ uint32_t pack_bf2(__nv_bfloat16 lo, __nv_bfloat16 hi) {
    return ((uint32_t)__bfloat16_as_ushort(hi) << 16) | __bfloat16_as_ushort(lo);
}
__device__ __forceinline__ void sts32(uint32_t addr, uint32_t v) {
    asm volatile("st.shared.b32 [%0], %1;" :: "r"(addr), "r"(v) : "memory");
}
__device__ __forceinline__ void sts64(uint32_t addr, uint32_t v0, uint32_t v1) {
    asm volatile("st.shared.v2.b32 [%0], {%1,%2};" :: "r"(addr), "r"(v0), "r"(v1) : "memory");
}
__device__ __forceinline__ float dot4(float4 a, float4 b) {
    return a.x * b.x + a.y * b.y + a.z * b.z + a.w * b.w;
}

// ===================== fused converts + mask probe + A-transpose ============
__global__ __launch_bounds__(128) void convert_all_kernel(
    const float* __restrict__ x, const float* __restrict__ q_w,
    const float* __restrict__ kv_w, const float* __restrict__ proj_w,
    const float* __restrict__ assign, const void* __restrict__ mask,
    __nv_bfloat16* __restrict__ Ax, __nv_bfloat16* __restrict__ Bqkv,
    __nv_bfloat16* __restrict__ Bproj, float* __restrict__ AsTg)
{
    const int rb = blockIdx.x;
    if (rb == 4096) {
        __shared__ int s_not_i32, s_not_f32;
        if (threadIdx.x == 0) { s_not_i32 = 0; s_not_f32 = 0; }
        __syncthreads();
        const unsigned int* w = (const unsigned int*)mask;
        int bad_i = 0, bad_f = 0;
        for (int i = threadIdx.x; i < 544; i += 128) {
            unsigned int v = w[i];
            if (v > 1u) bad_i = 1;
            if (v != 0u && v != 0x3F800000u) bad_f = 1;
        }
        if (bad_i) atomicOr(&s_not_i32, 1);
        if (bad_f) atomicOr(&s_not_f32, 1);
        __syncthreads();
        if (threadIdx.x == 0)
            g_mask_mode = (!s_not_i32) ? 0 : ((!s_not_f32) ? 1 : 2);
        return;
    }
    if (rb >= 4097) {
        const int n = rb - 4097;
        __shared__ __align__(16) float At[2176];
        const float* arow = assign + (size_t)n * 2176;
        for (int i = threadIdx.x; i < 544; i += 128)
            *(float4*)&At[i * 4] = *(const float4*)&arow[i * 4];
        __syncthreads();
        float* out = AsTg + (size_t)n * 2176;
        for (int j = threadIdx.x; j < 544; j += 128) {
            const int o = j * 4;
            const int r = o >> 7, m = o & 127;
            float4 v = make_float4(At[m * kR + r], At[(m + 1) * kR + r],
                                   At[(m + 2) * kR + r], At[(m + 3) * kR + r]);
            *(float4*)&out[o] = v;
        }
        return;
    }
    const float* src;
    __nv_bfloat16* dst;
    bool aSide;
    if (rb < 2048)      { src = x + (size_t)rb * kC;             dst = Ax + (size_t)rb * kKp;           aSide = true;  }
    else if (rb < 2560) { int r = rb - 2048; src = q_w + (size_t)r * kC;    dst = Bqkv + (size_t)r * kKp;        aSide = false; }
    else if (rb < 3584) { int r = rb - 2560; src = kv_w + (size_t)r * kC;   dst = Bqkv + (size_t)(kC + r) * kKp; aSide = false; }
    else                { int r = rb - 3584; src = proj_w + (size_t)r * kC; dst = Bproj + (size_t)r * kKp;       aSide = false; }

    const int j0 = threadIdx.x * 4;
    float4 v = *(const float4*)&src[j0];
    float f[4] = {v.x, v.y, v.z, v.w};
    __nv_bfloat16 hi[4], lo[4];
#pragma unroll
    for (int t = 0; t < 4; t++) {
        hi[t] = __float2bfloat16(f[t]);
        lo[t] = __float2bfloat16(f[t] - __bfloat162float(hi[t]));
    }
    uint32_t hp0 = pack_bf2(hi[0], hi[1]), hp1 = pack_bf2(hi[2], hi[3]);
    uint32_t lp0 = pack_bf2(lo[0], lo[1]), lp1 = pack_bf2(lo[2], lo[3]);
    uint32_t* d0 = (uint32_t*)(dst + j0);
    uint32_t* d1 = (uint32_t*)(dst + kC + j0);
    uint32_t* d2 = (uint32_t*)(dst + 2 * kC + j0);
    d0[0] = hp0; d0[1] = hp1;
    if (aSide) { d1[0] = lp0; d1[1] = lp1; d2[0] = hp0; d2[1] = hp1; }
    else       { d1[0] = hp0; d1[1] = hp1; d2[0] = lp0; d2[1] = lp1; }
}

// ===================== templated mma.sync bf16 GEMM =========================
// MTILE = rows per block (64/128/256). N-tile fixed at 128.
// MODE 0: C0/C1 fp32 split-column output (+bias)
// MODE 1: qkv epilogue -> qbf/kbf triples + yvf fp32 [bh][m][64] (C1 = yvf)
// MODE 2: per-(b,h) qk: S = 0.125 * q@k^T  (MTILE must be 128)
template<int KBYTES, int NITER, int MODE, int MTILE>
__global__ __launch_bounds__(256) void mma_gemm_t(
    const __nv_bfloat16* __restrict__ A,
    const __nv_bfloat16* __restrict__ Bw,
    float* __restrict__ C0, float* __restrict__ C1,
    const float* __restrict__ bias, int split, int ld0, int ld1,
    __nv_bfloat16* __restrict__ qbf, __nv_bfloat16* __restrict__ kbf)
{
    constexpr int IR = MTILE / 64;
    constexpr int ASTG = MTILE * 64;
    constexpr int STAGE = ASTG + 8192;
    __shared__ __align__(16) char smem[2 * STAGE];
    const int tid = threadIdx.x;
    const int wid = tid >> 5, lane = tid & 31;
    const int warp_m = wid >> 1, warp_n = wid & 1;

    int m0, n0;
    const char *Ag, *Bg;
    if (MODE == 2) {
        const size_t off = (size_t)blockIdx.x * 128 * KBYTES;
        Ag = (const char*)A + off;
        Bg = (const char*)Bw + off;
        m0 = 0; n0 = 0;
    } else {
        m0 = blockIdx.y * MTILE; n0 = blockIdx.x * 128;
        Ag = (const char*)A  + (size_t)m0 * KBYTES;
        Bg = (const char*)Bw + (size_t)n0 * KBYTES;
    }

    const int lr = tid >> 2, lc = tid & 3;
    uint32_t sbase = smem_u32(&smem[0]);
    auto so = [&](int row) {
        return (uint32_t)(row * 64 + ((lc ^ (row & 3)) << 4));
    };

    auto stage_load = [&](int st, int k0b) {
        uint32_t sA = sbase + st * STAGE;
        uint32_t sB = sA + ASTG;
#pragma unroll
        for (int p = 0; p < IR; p++) {
            int row = lr + p * 64;
            cp_async16(sA + so(row), Ag + (size_t)row * KBYTES + k0b + lc * 16);
        }
        cp_async16(sB + so(lr), Bg + (size_t)lr * KBYTES + k0b + lc * 16);
        cp_async16(sB + so(lr + 64),
                   Bg + (size_t)(lr + 64) * KBYTES + k0b + lc * 16);
    };

    float acc[IR][8][4];
#pragma unroll
    for (int i = 0; i < IR; i++)
#pragma unroll
        for (int j = 0; j < 8; j++)
#pragma unroll
            for (int t = 0; t < 4; t++) acc[i][j][t] = 0.f;

    stage_load(0, 0);
    cp_commit();

    const int a_row = warp_m * (MTILE / 4) + (lane & 15);
    const int a_chsel = lane >> 4;
    const int b_mi = lane >> 3;
    const int b_row = warp_n * 64 + ((b_mi >> 1) << 3) + (lane & 7);
    const int b_chsel = b_mi & 1;

    for (int it = 0; it < NITER; it++) {
        cp_wait0();
        __syncthreads();
        if (it + 1 < NITER) { stage_load((it + 1) & 1, (it + 1) * 64); cp_commit(); }

        const uint32_t sA = sbase + (it & 1) * STAGE;
        const uint32_t sB = sA + ASTG;
#pragma unroll
        for (int kk = 0; kk < 2; kk++) {
            uint32_t a[IR][4];
#pragma unroll
            for (int i = 0; i < IR; i++) {
                int r = a_row + i * 16;
                int ch = 2 * kk + a_chsel;
                ldsm_x4(a[i], sA + r * 64 + ((ch ^ (r & 3)) << 4));
            }
            uint32_t b[8][2];
#pragma unroll
            for (int g = 0; g < 4; g++) {
                int r = b_row + g * 16;
                int ch = 2 * kk + b_chsel;
                uint32_t rr[4];
                ldsm_x4(rr, sB + r * 64 + ((ch ^ (r & 3)) << 4));
                b[2 * g][0] = rr[0]; b[2 * g][1] = rr[1];
                b[2 * g + 1][0] = rr[2]; b[2 * g + 1][1] = rr[3];
            }
#pragma unroll
            for (int i = 0; i < IR; i++)
#pragma unroll
                for (int j = 0; j < 8; j++)
                    mma16816(acc[i][j], a[i], b[j]);
        }
        __syncthreads();
    }

    const int gq = lane >> 2, t4 = lane & 3;

    if (MODE == 2) {
        float* Sp = C0 + (size_t)blockIdx.x * kN * kN;
#pragma unroll
        for (int i = 0; i < IR; i++) {
#pragma unroll
            for (int j = 0; j < 8; j++) {
                int col = warp_n * 64 + j * 8 + t4 * 2;
                int r0 = warp_m * (MTILE / 4) + i * 16 + gq;
                *(float2*)&Sp[(size_t)r0 * kN + col] =
                    make_float2(acc[i][j][0] * 0.125f, acc[i][j][1] * 0.125f);
                *(float2*)&Sp[(size_t)(r0 + 8) * kN + col] =
                    make_float2(acc[i][j][2] * 0.125f, acc[i][j][3] * 0.125f);
            }
        }
        return;
    }

    if (MODE == 1) {
        auto emit = [&](int row, int colg, float f0, float f1) {
            if (colg < 1024) {
                const bool isQ = colg < 512;
                const int c = isQ ? colg : colg - 512;
                const int h = c >> 6, d = c & 63;
                __nv_bfloat16 h0 = __float2bfloat16(f0);
                __nv_bfloat16 h1 = __float2bfloat16(f1);
                __nv_bfloat16 l0 = __float2bfloat16(f0 - __bfloat162float(h0));
                __nv_bfloat16 l1 = __float2bfloat16(f1 - __bfloat162float(h1));
                uint32_t hp = pack_bf2(h0, h1);
                uint32_t lp = pack_bf2(l0, l1);
                const int bb = row >> 7, nn = row & 127;
                __nv_bfloat16* base = (isQ ? qbf : kbf)
                    + ((size_t)((bb * kH + h) * kN + nn)) * kKq + d;
                *(uint32_t*)(base)       = hp;
                *(uint32_t*)(base + 64)  = isQ ? lp : hp;
                *(uint32_t*)(base + 128) = isQ ? hp : lp;
            } else {
                const int c = colg - 1024;
                const int h = c >> 6, d = c & 63;
                const int bb = row >> 7, m = row & 127;
                *(float2*)&C1[((size_t)((bb * kH + h) * kN + m)) * kHD + d] =
                    make_float2(f0, f1);
            }
        };
#pragma unroll
        for (int i = 0; i < IR; i++) {
#pragma unroll
            for (int j = 0; j < 8; j++) {
                int colg = n0 + warp_n * 64 + j * 8 + t4 * 2;
                int row0 = m0 + warp_m * (MTILE / 4) + i * 16 + gq;
                emit(row0,     colg, acc[i][j][0], acc[i][j][1]);
                emit(row0 + 8, colg, acc[i][j][2], acc[i][j][3]);
            }
        }
        return;
    }

    // MODE 0
#pragma unroll
    for (int i = 0; i < IR; i++) {
#pragma unroll
        for (int j = 0; j < 8; j++) {
            int colg = n0 + warp_n * 64 + j * 8 + t4 * 2;
            float bz0 = bias ? bias[colg]     : 0.f;
            float bz1 = bias ? bias[colg + 1] : 0.f;
            float* Cc; int ldc, cc;
            if (colg < split) { Cc = C0; ldc = ld0; cc = colg; }
            else              { Cc = C1; ldc = ld1; cc = colg - split; }
            int row0 = m0 + warp_m * (MTILE / 4) + i * 16 + gq;
            *(float2*)&Cc[(size_t)row0 * ldc + cc] =
                make_float2(acc[i][j][0] + bz0, acc[i][j][1] + bz1);
            *(float2*)&Cc[(size_t)(row0 + 8) * ldc + cc] =
                make_float2(acc[i][j][2] + bz0, acc[i][j][3] + bz1);
        }
    }
}

// ===================== att v7: R12 + transposed P for W phase ===============
__global__ __launch_bounds__(256) void att_kernel(
    const float* __restrict__ S, const float* __restrict__ AsTg,
    const void* __restrict__ mask, const float* __restrict__ rel_bias,
    float* __restrict__ Wf)
{
    __shared__ __align__(16) float As[kR * 132];
    __shared__ __align__(16) float Ss[kH * 132];
    __shared__ __align__(16) float Lp[kH * kR * 8];
    __shared__ __align__(16) float Ls[kH * 20];
    __shared__ __align__(16) float PsT[20 * kH];   // [r][h] transposed
    __shared__ __align__(16) float rb[136];
    __shared__ __align__(16) int   mk[kR];

    const int t = threadIdx.x, wid = t >> 5, lane = t & 31;
    const int b = blockIdx.x >> 7, n = blockIdx.x & 127;

    {
        const int h = t >> 5, m0 = (t & 31) * 4;
        *(float4*)&Ss[h * 132 + m0] =
            *(const float4*)&S[(((size_t)(b * kH + h)) * kN + n) * kN + m0];
    }
    const float* ag = AsTg + (size_t)n * (kR * kN);
    for (int i = t; i < 544; i += 256) {
        const int r = i >> 5, m0 = (i & 31) * 4;
        *(float4*)&As[r * 132 + m0] = *(const float4*)&ag[r * kN + m0];
    }
    if (t < 136) rb[t] = rel_bias[t];
    if (t < kR) {
        int mode = g_mask_mode;
        int idx = n * kR + t;
        bool m_;
        if (mode == 0)      m_ = ((const int*)mask)[idx] != 0;
        else if (mode == 1) m_ = ((const float*)mask)[idx] != 0.f;
        else                m_ = ((const unsigned char*)mask)[idx] != 0;
        mk[t] = m_ ? 1 : 0;
    }
    __syncthreads();

    // logits partials: warp = head h; lane dot over 4 m; reduce 4 lanes -> 1
    {
        const int h = wid;
        float4 sv = *(const float4*)&Ss[h * 132 + lane * 4];
#pragma unroll
        for (int r = 0; r < kR; r++) {
            float4 av = *(const float4*)&As[r * 132 + lane * 4];
            float d = dot4(sv, av);
            d += __shfl_xor_sync(0xFFFFFFFFu, d, 1);
            d += __shfl_xor_sync(0xFFFFFFFFu, d, 2);
            if ((lane & 3) == 0)
                Lp[(h * kR + r) * 8 + (lane >> 2)] = d;
        }
    }
    __syncthreads();

    if (t < 136) {
        const int h = t / kR, r = t - h * kR;
        const float* p = &Lp[t * 8];
        float s = ((p[0] + p[1]) + (p[2] + p[3]))
                + ((p[4] + p[5]) + (p[6] + p[7]));
        Ls[h * 20 + r] = mk[r] ? neg_inf() : (s + rb[t]);
    }
    __syncthreads();

    // softmax: warp wid == head h, lanes 0..16; writes PsT[r][h]
    {
        const int h = wid;
        float v = (lane < kR) ? Ls[h * 20 + lane] : neg_inf();
        float mx = v;
#pragma unroll
        for (int o = 16; o > 0; o >>= 1)
            mx = fmaxf(mx, __shfl_xor_sync(0xFFFFFFFFu, mx, o));
        float e = (lane < kR) ? __expf(v - mx) : 0.f;
        float s = e;
#pragma unroll
        for (int o = 16; o > 0; o >>= 1)
            s += __shfl_xor_sync(0xFFFFFFFFu, s, o);
        if (lane < kR) PsT[lane * kH + h] = e / s;
    }
    __syncthreads();

    // W: thread = (h-group, m); one LDS.128 covers 4 heads per r
    {
        const int m = t & 127, hg = t >> 7;
        float acc[4] = {0.f, 0.f, 0.f, 0.f};
#pragma unroll
        for (int r = 0; r < kR; r++) {
            float a = As[r * 132 + m];
            float4 p = *(const float4*)&PsT[r * kH + hg * 4];
            acc[0] += p.x * a; acc[1] += p.y * a;
            acc[2] += p.z * a; acc[3] += p.w * a;
        }
#pragma unroll
        for (int u = 0; u < 4; u++)
            Wf[(((size_t)(b * kH + hg * 4 + u)) * kN + n) * kN + m] = acc[u];
    }
}

// ===================== av combo mma: O = W @ yv^T per (b,h) =================
__global__ __launch_bounds__(256) void av_mma_kernel(
    const float* __restrict__ Wf, const float* __restrict__ yvf,
    __nv_bfloat16* __restrict__ AO)
{
    extern __shared__ __align__(16) char dsm[];
    const int tid = threadIdx.x, wid = tid >> 5, lane = tid & 31;
    const int bh = blockIdx.x;
    const int warp_m = wid >> 1, warp_n = wid & 1;
    const uint32_t sbase = smem_u32(dsm);
    const uint32_t vbase = sbase + 65536u;

    const float* Wb = Wf + (size_t)bh * kN * kN;
    {
        const int mq = tid & 31, r0 = tid >> 5;
#pragma unroll
        for (int i = 0; i < 16; i++) {
            const int row = r0 + 8 * i;
            float4 v = *(const float4*)&Wb[(size_t)row * kN + mq * 4];
            float f[4] = {v.x, v.y, v.z, v.w};
            __nv_bfloat16 hi[4], lo[4];
#pragma unroll
            for (int u = 0; u < 4; u++) {
                hi[u] = __float2bfloat16(f[u]);
                lo[u] = __float2bfloat16(f[u] - __bfloat162float(hi[u]));
            }
            const int m0 = mq * 4;
            const int stage = m0 >> 5;
            const int ch = (m0 & 31) >> 3;
            const int hb = (m0 & 7) >> 2;
            uint32_t addr = sbase + stage * 8192 + row * 64
                          + ((ch ^ (row & 3)) << 4) + hb * 8;
            sts64(addr, pack_bf2(hi[0], hi[1]), pack_bf2(hi[2], hi[3]));
            sts64(addr + 4 * 8192, pack_bf2(lo[0], lo[1]), pack_bf2(lo[2], lo[3]));
        }
    }
    const float* Vb = yvf + (size_t)bh * kN * kHD;
    {
        const int dq = tid & 15, mp0 = tid >> 4;
#pragma unroll
        for (int i = 0; i < 4; i++) {
            const int mp = mp0 + 16 * i;
            const int m0 = 2 * mp;
            float4 v0 = *(const float4*)&Vb[(size_t)m0 * kHD + dq * 4];
            float4 v1 = *(const float4*)&Vb[(size_t)(m0 + 1) * kHD + dq * 4];
            float f0[4] = {v0.x, v0.y, v0.z, v0.w};
            float f1[4] = {v1.x, v1.y, v1.z, v1.w};
            const int stage = m0 >> 5;
            const int ch = (m0 & 31) >> 3;
            const int ob = (m0 & 7) * 2;
#pragma unroll
            for (int u = 0; u < 4; u++) {
                const int row = dq * 4 + u;
                __nv_bfloat16 h0 = __float2bfloat16(f0[u]);
                __nv_bfloat16 h1 = __float2bfloat16(f1[u]);
                __nv_bfloat16 l0 = __float2bfloat16(f0[u] - __bfloat162float(h0));
                __nv_bfloat16 l1 = __float2bfloat16(f1[u] - __bfloat162float(h1));
                uint32_t addr = vbase + stage * 4096 + row * 64
                              + ((ch ^ (row & 3)) << 4) + ob;
                sts32(addr, pack_bf2(h0, h1));
                sts32(addr + 4 * 4096, pack_bf2(l0, l1));
            }
        }
    }
    __syncthreads();

    float acc[2][4][4];
#pragma unroll
    for (int i = 0; i < 2; i++)
#pragma unroll
        for (int j = 0; j < 4; j++)
#pragma unroll
            for (int t = 0; t < 4; t++) acc[i][j][t] = 0.f;

    const int a_row = warp_m * 32 + (lane & 15);
    const int a_chsel = lane >> 4;
    const int b_mi = lane >> 3;
    const int b_row = warp_n * 32 + ((b_mi >> 1) << 3) + (lane & 7);
    const int b_chsel = b_mi & 1;

    const int schedA[12] = {0,1,2,3, 4,5,6,7, 0,1,2,3};
    const int schedB[12] = {0,1,2,3, 0,1,2,3, 4,5,6,7};

#pragma unroll
    for (int it = 0; it < 12; it++) {
        const uint32_t sA = sbase + schedA[it] * 8192;
        const uint32_t sB = vbase + schedB[it] * 4096;
#pragma unroll
        for (int kk = 0; kk < 2; kk++) {
            uint32_t a[2][4];
#pragma unroll
            for (int i = 0; i < 2; i++) {
                int r = a_row + i * 16;
                int ch = 2 * kk + a_chsel;
                ldsm_x4(a[i], sA + r * 64 + ((ch ^ (r & 3)) << 4));
            }
            uint32_t b[4][2];
#pragma unroll
            for (int g = 0; g < 2; g++) {
                int r = b_row + g * 16;
                int ch = 2 * kk + b_chsel;
                uint32_t rr[4];
                ldsm_x4(rr, sB + r * 64 + ((ch ^ (r & 3)) << 4));
                b[2 * g][0] = rr[0]; b[2 * g][1] = rr[1];
                b[2 * g + 1][0] = rr[2]; b[2 * g + 1][1] = rr[3];
            }
#pragma unroll
            for (int i = 0; i < 2; i++)
#pragma unroll
                for (int j = 0; j < 4; j++)
                    mma16816(acc[i][j], a[i], b[j]);
        }
    }

    const int gq = lane >> 2, t4 = lane & 3;
    const int b_ = bh >> 3, h_ = bh & 7;
#pragma unroll
    for (int i = 0; i < 2; i++) {
#pragma unroll
        for (int j = 0; j < 4; j++) {
            const int d = warp_n * 32 + j * 8 + t4 * 2;
            const int c = h_ * kHD + d;
#pragma unroll
            for (int rr = 0; rr < 2; rr++) {
                const int nrow = warp_m * 32 + i * 16 + gq + rr * 8;
                const float f0 = acc[i][j][rr * 2], f1 = acc[i][j][rr * 2 + 1];
                __nv_bfloat16 h0 = __float2bfloat16(f0), h1 = __float2bfloat16(f1);
                __nv_bfloat16 l0 = __float2bfloat16(f0 - __bfloat162float(h0));
                __nv_bfloat16 l1 = __float2bfloat16(f1 - __bfloat162float(h1));
                __nv_bfloat16* base = AO + (size_t)(b_ * kN + nrow) * kKp + c;
                *(uint32_t*)(base)        = pack_bf2(h0, h1);
                *(uint32_t*)(base + 512)  = pack_bf2(l0, l1);
                *(uint32_t*)(base + 1024) = pack_bf2(h0, h1);
            }
        }
    }
}

// ===================== launch =====================
extern "C" void kernel_launch(void* const* d_in, const int* in_sizes, int n_in,
                              void* d_out, int out_size)
{
    const float* x        = (const float*)d_in[0];
    const float* assign   = (const float*)d_in[1];
    const void*  mask     = d_in[2];
    const float* q_w      = (const float*)d_in[3];
    const float* kv_w     = (const float*)d_in[4];
    const float* rel_bias = (const float*)d_in[5];
    const float* proj_w   = (const float*)d_in[6];
    const float* proj_b   = (const float*)d_in[7];

    float *S, *Wfp, *yvf, *AsTg;
    __nv_bfloat16 *Ax, *Bqkv, *Bproj, *AO, *qbf, *kbf;
    cudaGetSymbolAddress((void**)&S,    g_S);
    cudaGetSymbolAddress((void**)&Wfp,  g_Wf);
    cudaGetSymbolAddress((void**)&yvf,  g_yvf);
    cudaGetSymbolAddress((void**)&AsTg, g_AsT);
    cudaGetSymbolAddress((void**)&Ax,    g_Ax);
    cudaGetSymbolAddress((void**)&Bqkv,  g_Bqkv);
    cudaGetSymbolAddress((void**)&Bproj, g_Bproj);
    cudaGetSymbolAddress((void**)&AO,    g_AO);
    cudaGetSymbolAddress((void**)&qbf,   g_qbf);
    cudaGetSymbolAddress((void**)&kbf,   g_kbf);

    const int AV_SMEM = 8 * 8192 + 8 * 4096;  // 96 KB
    cudaFuncSetAttribute(av_mma_kernel,
                         cudaFuncAttributeMaxDynamicSharedMemorySize, AV_SMEM);

    // 1. input hi/lo splits + mask probe + A transpose
    convert_all_kernel<<<4225, 128>>>(x, q_w, kv_w, proj_w, assign, mask,
                                      Ax, Bqkv, Bproj, AsTg);

    // 2. fused q/kv projection -> qbf/kbf triples + yvf fp32 (MTILE=256, 96 blocks)
    mma_gemm_t<3072, 48, 1, 256><<<dim3(12, 8), 256>>>(
        Ax, Bqkv, nullptr, yvf, nullptr, 0, 0, 0, qbf, kbf);

    // 3. S = 0.125 * q@k^T per (b,h)
    mma_gemm_t<384, 6, 2, 128><<<dim3(128, 1), 256>>>(
        qbf, kbf, S, nullptr, nullptr, 0, 0, 0, nullptr, nullptr);

    // 4. logits + masked softmax + W (fp32)
    att_kernel<<<kB * kN, 256>>>(S, AsTg, mask, rel_bias, Wfp);

    // 5. O = W @ yv per (b,h), combo split-K on tensor cores (emits AO triple)
    av_mma_kernel<<<128, 256, AV_SMEM>>>(Wfp, yvf, AO);

    // 6. out-proj: AO @ Bproj^T + bias (MTILE=64, 128 blocks)
    mma_gemm_t<3072, 48, 0, 64><<<dim3(4, 32), 256>>>(
        AO, Bproj, (float*)d_out, (float*)d_out, proj_b, 1 << 30, kC, kC,
        nullptr, nullptr);
}

// round 15
// speedup vs baseline: 1.2963x; 1.0350x over previous
#include <cuda_runtime.h>
#include <cuda_bf16.h>
#include <cstdint>

// Problem dims
constexpr int kB  = 16;
constexpr int kN  = 128;
constexpr int kC  = 512;
constexpr int kH  = 8;
constexpr int kR  = 17;
constexpr int kHD = 64;
constexpr int kBN = kB * kN;    // 2048
constexpr int kKp = 3 * kC;     // 1536 split-K' (c contraction)

// Scratch (device globals; no allocations allowed)
__device__ float g_S[kB * kH * kN * kN];  // 8 MB (pre-scaled by 0.125)
__device__ float g_Wf[kB * kH * kN * kN]; // 8 MB attention weights fp32
__device__ float g_yvf[kB * kH * kN * kHD]; // 4 MB yv fp32 [bh][m][64]
__device__ float g_qf[kB * kH * kN * kHD];  // 4 MB q fp32 [bh][n][64]
__device__ float g_kf[kB * kH * kN * kHD];  // 4 MB k fp32 [bh][m][64]
__device__ float g_AsT[kN * kR * kN];     // 1.1 MB A^T fp32 [n][r][128m]
__device__ int   g_mask_mode;
__device__ __nv_bfloat16 g_Ax[kBN * kKp];        // x hi|lo|hi
__device__ __nv_bfloat16 g_Bqkv[kKp * kKp];      // [q_w;kv_w] hi|hi|lo
__device__ __nv_bfloat16 g_Bproj[kC * kKp];      // proj_w hi|hi|lo
__device__ __nv_bfloat16 g_AO[kBN * kKp];        // O hi|lo|hi (av epilogue)

__device__ __forceinline__ float neg_inf() { return __int_as_float(0xFF800000); }

// ===================== baseline-PTX helpers =====================
__device__ __forceinline__ uint32_t smem_u32(const void* p) {
    uint32_t a;
    asm("{ .reg .u64 t; cvta.to.shared.u64 t, %1; cvt.u32.u64 %0, t; }"
        : "=r"(a) : "l"(p));
    return a;
}
__device__ __forceinline__ void cp_async16(uint32_t saddr, const void* gaddr) {
    asm volatile("cp.async.cg.shared.global [%0], [%1], 16;"
                 :: "r"(saddr), "l"(gaddr) : "memory");
}
__device__ __forceinline__ void cp_commit() {
    asm volatile("cp.async.commit_group;" ::: "memory");
}
__device__ __forceinline__ void cp_wait0() {
    asm volatile("cp.async.wait_group 0;" ::: "memory");
}
__device__ __forceinline__ void ldsm_x4(uint32_t* r, uint32_t addr) {
    asm volatile("ldmatrix.sync.aligned.m8n8.x4.shared.b16 {%0,%1,%2,%3}, [%4];"
                 : "=r"(r[0]), "=r"(r[1]), "=r"(r[2]), "=r"(r[3]) : "r"(addr));
}
__device__ __forceinline__ void mma16816(float* d, const uint32_t* a, const uint32_t* b) {
    asm volatile("mma.sync.aligned.m16n8k16.row.col.f32.bf16.bf16.f32 "
                 "{%0,%1,%2,%3}, {%4,%5,%6,%7}, {%8,%9}, {%0,%1,%2,%3};"
                 : "+f"(d[0]), "+f"(d[1]), "+f"(d[2]), "+f"(d[3])
                 : "r"(a[0]), "r"(a[1]), "r"(a[2]), "r"(a[3]),
                   "r"(b[0]), "r"(b[1]));
}
__device__ __forceinline__ uint32_t pack_bf2(__nv_bfloat16 lo, __nv_bfloat16 hi) {
    return ((uint32_t)__bfloat16_as_ushort(hi) << 16) | __bfloat16_as_ushort(lo);
}
__device__ __forceinline__ void sts32(uint32_t addr, uint32_t v) {
    asm volatile("st.shared.b32 [%0], %1;" :: "r"(addr), "r"(v) : "memory");
}
__device__ __forceinline__ void sts64(uint32_t addr, uint32_t v0, uint32_t v1) {
    asm volatile("st.shared.v2.b32 [%0], {%1,%2};" :: "r"(addr), "r"(v0), "r"(v1) : "memory");
}
__device__ __forceinline__ float dot4(float4 a, float4 b) {
    return a.x * b.x + a.y * b.y + a.z * b.z + a.w * b.w;
}

// ===================== fused converts + mask probe + A-transpose ============
__global__ __launch_bounds__(128) void convert_all_kernel(
    const float* __restrict__ x, const float* __restrict__ q_w,
    const float* __restrict__ kv_w, const float* __restrict__ proj_w,
    const float* __restrict__ assign, const void* __restrict__ mask,
    __nv_bfloat16* __restrict__ Ax, __nv_bfloat16* __restrict__ Bqkv,
    __nv_bfloat16* __restrict__ Bproj, float* __restrict__ AsTg)
{
    const int rb = blockIdx.x;
    if (rb == 4096) {
        __shared__ int s_not_i32, s_not_f32;
        if (threadIdx.x == 0) { s_not_i32 = 0; s_not_f32 = 0; }
        __syncthreads();
        const unsigned int* w = (const unsigned int*)mask;
        int bad_i = 0, bad_f = 0;
        for (int i = threadIdx.x; i < 544; i += 128) {
            unsigned int v = w[i];
            if (v > 1u) bad_i = 1;
            if (v != 0u && v != 0x3F800000u) bad_f = 1;
        }
        if (bad_i) atomicOr(&s_not_i32, 1);
        if (bad_f) atomicOr(&s_not_f32, 1);
        __syncthreads();
        if (threadIdx.x == 0)
            g_mask_mode = (!s_not_i32) ? 0 : ((!s_not_f32) ? 1 : 2);
        return;
    }
    if (rb >= 4097) {
        const int n = rb - 4097;
        __shared__ __align__(16) float At[2176];
        const float* arow = assign + (size_t)n * 2176;
        for (int i = threadIdx.x; i < 544; i += 128)
            *(float4*)&At[i * 4] = *(const float4*)&arow[i * 4];
        __syncthreads();
        float* out = AsTg + (size_t)n * 2176;
        for (int j = threadIdx.x; j < 544; j += 128) {
            const int o = j * 4;
            const int r = o >> 7, m = o & 127;
            float4 v = make_float4(At[m * kR + r], At[(m + 1) * kR + r],
                                   At[(m + 2) * kR + r], At[(m + 3) * kR + r]);
            *(float4*)&out[o] = v;
        }
        return;
    }
    const float* src;
    __nv_bfloat16* dst;
    bool aSide;
    if (rb < 2048)      { src = x + (size_t)rb * kC;             dst = Ax + (size_t)rb * kKp;           aSide = true;  }
    else if (rb < 2560) { int r = rb - 2048; src = q_w + (size_t)r * kC;    dst = Bqkv + (size_t)r * kKp;        aSide = false; }
    else if (rb < 3584) { int r = rb - 2560; src = kv_w + (size_t)r * kC;   dst = Bqkv + (size_t)(kC + r) * kKp; aSide = false; }
    else                { int r = rb - 3584; src = proj_w + (size_t)r * kC; dst = Bproj + (size_t)r * kKp;       aSide = false; }

    const int j0 = threadIdx.x * 4;
    float4 v = *(const float4*)&src[j0];
    float f[4] = {v.x, v.y, v.z, v.w};
    __nv_bfloat16 hi[4], lo[4];
#pragma unroll
    for (int t = 0; t < 4; t++) {
        hi[t] = __float2bfloat16(f[t]);
        lo[t] = __float2bfloat16(f[t] - __bfloat162float(hi[t]));
    }
    uint32_t hp0 = pack_bf2(hi[0], hi[1]), hp1 = pack_bf2(hi[2], hi[3]);
    uint32_t lp0 = pack_bf2(lo[0], lo[1]), lp1 = pack_bf2(lo[2], lo[3]);
    uint32_t* d0 = (uint32_t*)(dst + j0);
    uint32_t* d1 = (uint32_t*)(dst + kC + j0);
    uint32_t* d2 = (uint32_t*)(dst + 2 * kC + j0);
    d0[0] = hp0; d0[1] = hp1;
    if (aSide) { d1[0] = lp0; d1[1] = lp1; d2[0] = hp0; d2[1] = hp1; }
    else       { d1[0] = hp0; d1[1] = hp1; d2[0] = lp0; d2[1] = lp1; }
}

// ===================== templated mma.sync bf16 GEMM =========================
// MTILE = rows per block (64/128/256). N-tile fixed at 128.
// MODE 0: C0/C1 fp32 split-column output (+bias)
// MODE 1: qkv epilogue -> qf/kf/yvf compact fp32 [bh][row][64] (coalesced)
template<int KBYTES, int NITER, int MODE, int MTILE>
__global__ __launch_bounds__(256) void mma_gemm_t(
    const __nv_bfloat16* __restrict__ A,
    const __nv_bfloat16* __restrict__ Bw,
    float* __restrict__ C0, float* __restrict__ C1,
    const float* __restrict__ bias, int split, int ld0, int ld1,
    float* __restrict__ qf, float* __restrict__ kf)
{
    constexpr int IR = MTILE / 64;
    constexpr int ASTG = MTILE * 64;
    constexpr int STAGE = ASTG + 8192;
    __shared__ __align__(16) char smem[2 * STAGE];
    const int tid = threadIdx.x;
    const int wid = tid >> 5, lane = tid & 31;
    const int warp_m = wid >> 1, warp_n = wid & 1;

    const int m0 = blockIdx.y * MTILE, n0 = blockIdx.x * 128;
    const char* Ag = (const char*)A  + (size_t)m0 * KBYTES;
    const char* Bg = (const char*)Bw + (size_t)n0 * KBYTES;

    const int lr = tid >> 2, lc = tid & 3;
    uint32_t sbase = smem_u32(&smem[0]);
    auto so = [&](int row) {
        return (uint32_t)(row * 64 + ((lc ^ (row & 3)) << 4));
    };

    auto stage_load = [&](int st, int k0b) {
        uint32_t sA = sbase + st * STAGE;
        uint32_t sB = sA + ASTG;
#pragma unroll
        for (int p = 0; p < IR; p++) {
            int row = lr + p * 64;
            cp_async16(sA + so(row), Ag + (size_t)row * KBYTES + k0b + lc * 16);
        }
        cp_async16(sB + so(lr), Bg + (size_t)lr * KBYTES + k0b + lc * 16);
        cp_async16(sB + so(lr + 64),
                   Bg + (size_t)(lr + 64) * KBYTES + k0b + lc * 16);
    };

    float acc[IR][8][4];
#pragma unroll
    for (int i = 0; i < IR; i++)
#pragma unroll
        for (int j = 0; j < 8; j++)
#pragma unroll
            for (int t = 0; t < 4; t++) acc[i][j][t] = 0.f;

    stage_load(0, 0);
    cp_commit();

    const int a_row = warp_m * (MTILE / 4) + (lane & 15);
    const int a_chsel = lane >> 4;
    const int b_mi = lane >> 3;
    const int b_row = warp_n * 64 + ((b_mi >> 1) << 3) + (lane & 7);
    const int b_chsel = b_mi & 1;

    for (int it = 0; it < NITER; it++) {
        cp_wait0();
        __syncthreads();
        if (it + 1 < NITER) { stage_load((it + 1) & 1, (it + 1) * 64); cp_commit(); }

        const uint32_t sA = sbase + (it & 1) * STAGE;
        const uint32_t sB = sA + ASTG;
#pragma unroll
        for (int kk = 0; kk < 2; kk++) {
            uint32_t a[IR][4];
#pragma unroll
            for (int i = 0; i < IR; i++) {
                int r = a_row + i * 16;
                int ch = 2 * kk + a_chsel;
                ldsm_x4(a[i], sA + r * 64 + ((ch ^ (r & 3)) << 4));
            }
            uint32_t b[8][2];
#pragma unroll
            for (int g = 0; g < 4; g++) {
                int r = b_row + g * 16;
                int ch = 2 * kk + b_chsel;
                uint32_t rr[4];
                ldsm_x4(rr, sB + r * 64 + ((ch ^ (r & 3)) << 4));
                b[2 * g][0] = rr[0]; b[2 * g][1] = rr[1];
                b[2 * g + 1][0] = rr[2]; b[2 * g + 1][1] = rr[3];
            }
#pragma unroll
            for (int i = 0; i < IR; i++)
#pragma unroll
                for (int j = 0; j < 8; j++)
                    mma16816(acc[i][j], a[i], b[j]);
        }
        __syncthreads();
    }

    const int gq = lane >> 2, t4 = lane & 3;

    if (MODE == 1) {
        auto emit = [&](int row, int colg, float f0, float f1) {
            float* dst; int c;
            if (colg < 512)       { dst = qf;  c = colg; }
            else if (colg < 1024) { dst = kf;  c = colg - 512; }
            else                  { dst = C1;  c = colg - 1024; }
            const int h = c >> 6, d = c & 63;
            const int bb = row >> 7, nn = row & 127;
            *(float2*)&dst[((size_t)((bb * kH + h) * kN + nn)) * kHD + d] =
                make_float2(f0, f1);
        };
#pragma unroll
        for (int i = 0; i < IR; i++) {
#pragma unroll
            for (int j = 0; j < 8; j++) {
                int colg = n0 + warp_n * 64 + j * 8 + t4 * 2;
                int row0 = m0 + warp_m * (MTILE / 4) + i * 16 + gq;
                emit(row0,     colg, acc[i][j][0], acc[i][j][1]);
                emit(row0 + 8, colg, acc[i][j][2], acc[i][j][3]);
            }
        }
        return;
    }

    // MODE 0
#pragma unroll
    for (int i = 0; i < IR; i++) {
#pragma unroll
        for (int j = 0; j < 8; j++) {
            int colg = n0 + warp_n * 64 + j * 8 + t4 * 2;
            float bz0 = bias ? bias[colg]     : 0.f;
            float bz1 = bias ? bias[colg + 1] : 0.f;
            float* Cc; int ldc, cc;
            if (colg < split) { Cc = C0; ldc = ld0; cc = colg; }
            else              { Cc = C1; ldc = ld1; cc = colg - split; }
            int row0 = m0 + warp_m * (MTILE / 4) + i * 16 + gq;
            *(float2*)&Cc[(size_t)row0 * ldc + cc] =
                make_float2(acc[i][j][0] + bz0, acc[i][j][1] + bz1);
            *(float2*)&Cc[(size_t)(row0 + 8) * ldc + cc] =
                make_float2(acc[i][j][2] + bz0, acc[i][j][3] + bz1);
        }
    }
}

// ===================== qk combo mma: S = 0.125 * q@k^T per (b,h) ============
// Loads q,k fp32 [bh][row][64]; converts to hi/lo SMEM stages in-loader.
// Combo schedule = qh*kh + ql*kh + qh*kl (6 iters of K=32).
__global__ __launch_bounds__(256) void qk_combo_kernel(
    const float* __restrict__ qf, const float* __restrict__ kf,
    float* __restrict__ S)
{
    extern __shared__ __align__(16) char dsm[];
    const int tid = threadIdx.x, wid = tid >> 5, lane = tid & 31;
    const int bh = blockIdx.x;
    const int warp_m = wid >> 1, warp_n = wid & 1;
    const uint32_t sbase = smem_u32(dsm);           // q stages: 4 x 8KB
    const uint32_t vbase = sbase + 32768u;          // k stages: 4 x 8KB

    // loaders: thread loads float4 (4 d); 128 rows x 16 quads
    auto load_side = [&](const float* src, uint32_t base) {
        const int dq = tid & 15, r0 = tid >> 4;
#pragma unroll
        for (int i = 0; i < 8; i++) {
            const int row = r0 + 16 * i;
            float4 v = *(const float4*)&src[(size_t)row * kHD + dq * 4];
            float f[4] = {v.x, v.y, v.z, v.w};
            __nv_bfloat16 hi[4], lo[4];
#pragma unroll
            for (int u = 0; u < 4; u++) {
                hi[u] = __float2bfloat16(f[u]);
                lo[u] = __float2bfloat16(f[u] - __bfloat162float(hi[u]));
            }
            const int d0 = dq * 4;
            const int stage = d0 >> 5;
            const int ch = (d0 & 31) >> 3;
            const int hb = (d0 & 7) >> 2;
            uint32_t addr = base + stage * 8192 + row * 64
                          + ((ch ^ (row & 3)) << 4) + hb * 8;
            sts64(addr, pack_bf2(hi[0], hi[1]), pack_bf2(hi[2], hi[3]));
            sts64(addr + 2 * 8192, pack_bf2(lo[0], lo[1]), pack_bf2(lo[2], lo[3]));
        }
    };
    load_side(qf + (size_t)bh * kN * kHD, sbase);
    load_side(kf + (size_t)bh * kN * kHD, vbase);
    __syncthreads();

    float acc[2][8][4];
#pragma unroll
    for (int i = 0; i < 2; i++)
#pragma unroll
        for (int j = 0; j < 8; j++)
#pragma unroll
            for (int t = 0; t < 4; t++) acc[i][j][t] = 0.f;

    const int a_row = warp_m * 32 + (lane & 15);
    const int a_chsel = lane >> 4;
    const int b_mi = lane >> 3;
    const int b_row = warp_n * 64 + ((b_mi >> 1) << 3) + (lane & 7);
    const int b_chsel = b_mi & 1;

    const int schedA[6] = {0,1, 2,3, 0,1};
    const int schedB[6] = {0,1, 0,1, 2,3};

#pragma unroll
    for (int it = 0; it < 6; it++) {
        const uint32_t sA = sbase + schedA[it] * 8192;
        const uint32_t sB = vbase + schedB[it] * 8192;
#pragma unroll
        for (int kk = 0; kk < 2; kk++) {
            uint32_t a[2][4];
#pragma unroll
            for (int i = 0; i < 2; i++) {
                int r = a_row + i * 16;
                int ch = 2 * kk + a_chsel;
                ldsm_x4(a[i], sA + r * 64 + ((ch ^ (r & 3)) << 4));
            }
            uint32_t b[8][2];
#pragma unroll
            for (int g = 0; g < 4; g++) {
                int r = b_row + g * 16;
                int ch = 2 * kk + b_chsel;
                uint32_t rr[4];
                ldsm_x4(rr, sB + r * 64 + ((ch ^ (r & 3)) << 4));
                b[2 * g][0] = rr[0]; b[2 * g][1] = rr[1];
                b[2 * g + 1][0] = rr[2]; b[2 * g + 1][1] = rr[3];
            }
#pragma unroll
            for (int i = 0; i < 2; i++)
#pragma unroll
                for (int j = 0; j < 8; j++)
                    mma16816(acc[i][j], a[i], b[j]);
        }
    }

    const int gq = lane >> 2, t4 = lane & 3;
    float* Sp = S + (size_t)bh * kN * kN;
#pragma unroll
    for (int i = 0; i < 2; i++) {
#pragma unroll
        for (int j = 0; j < 8; j++) {
            int col = warp_n * 64 + j * 8 + t4 * 2;
            int r0 = warp_m * 32 + i * 16 + gq;
            *(float2*)&Sp[(size_t)r0 * kN + col] =
                make_float2(acc[i][j][0] * 0.125f, acc[i][j][1] * 0.125f);
            *(float2*)&Sp[(size_t)(r0 + 8) * kN + col] =
                make_float2(acc[i][j][2] * 0.125f, acc[i][j][3] * 0.125f);
        }
    }
}

// ===================== att v7 (champion) =====================
__global__ __launch_bounds__(256) void att_kernel(
    const float* __restrict__ S, const float* __restrict__ AsTg,
    const void* __restrict__ mask, const float* __restrict__ rel_bias,
    float* __restrict__ Wf)
{
    __shared__ __align__(16) float As[kR * 132];
    __shared__ __align__(16) float Ss[kH * 132];
    __shared__ __align__(16) float Lp[kH * kR * 8];
    __shared__ __align__(16) float Ls[kH * 20];
    __shared__ __align__(16) float PsT[20 * kH];
    __shared__ __align__(16) float rb[136];
    __shared__ __align__(16) int   mk[kR];

    const int t = threadIdx.x, wid = t >> 5, lane = t & 31;
    const int b = blockIdx.x >> 7, n = blockIdx.x & 127;

    {
        const int h = t >> 5, m0 = (t & 31) * 4;
        *(float4*)&Ss[h * 132 + m0] =
            *(const float4*)&S[(((size_t)(b * kH + h)) * kN + n) * kN + m0];
    }
    const float* ag = AsTg + (size_t)n * (kR * kN);
    for (int i = t; i < 544; i += 256) {
        const int r = i >> 5, m0 = (i & 31) * 4;
        *(float4*)&As[r * 132 + m0] = *(const float4*)&ag[r * kN + m0];
    }
    if (t < 136) rb[t] = rel_bias[t];
    if (t < kR) {
        int mode = g_mask_mode;
        int idx = n * kR + t;
        bool m_;
        if (mode == 0)      m_ = ((const int*)mask)[idx] != 0;
        else if (mode == 1) m_ = ((const float*)mask)[idx] != 0.f;
        else                m_ = ((const unsigned char*)mask)[idx] != 0;
        mk[t] = m_ ? 1 : 0;
    }
    __syncthreads();

    {
        const int h = wid;
        float4 sv = *(const float4*)&Ss[h * 132 + lane * 4];
#pragma unroll
        for (int r = 0; r < kR; r++) {
            float4 av = *(const float4*)&As[r * 132 + lane * 4];
            float d = dot4(sv, av);
            d += __shfl_xor_sync(0xFFFFFFFFu, d, 1);
            d += __shfl_xor_sync(0xFFFFFFFFu, d, 2);
            if ((lane & 3) == 0)
                Lp[(h * kR + r) * 8 + (lane >> 2)] = d;
        }
    }
    __syncthreads();

    if (t < 136) {
        const int h = t / kR, r = t - h * kR;
        const float* p = &Lp[t * 8];
        float s = ((p[0] + p[1]) + (p[2] + p[3]))
                + ((p[4] + p[5]) + (p[6] + p[7]));
        Ls[h * 20 + r] = mk[r] ? neg_inf() : (s + rb[t]);
    }
    __syncthreads();

    {
        const int h = wid;
        float v = (lane < kR) ? Ls[h * 20 + lane] : neg_inf();
        float mx = v;
#pragma unroll
        for (int o = 16; o > 0; o >>= 1)
            mx = fmaxf(mx, __shfl_xor_sync(0xFFFFFFFFu, mx, o));
        float e = (lane < kR) ? __expf(v - mx) : 0.f;
        float s = e;
#pragma unroll
        for (int o = 16; o > 0; o >>= 1)
            s += __shfl_xor_sync(0xFFFFFFFFu, s, o);
        if (lane < kR) PsT[lane * kH + h] = e / s;
    }
    __syncthreads();

    {
        const int m = t & 127, hg = t >> 7;
        float acc[4] = {0.f, 0.f, 0.f, 0.f};
#pragma unroll
        for (int r = 0; r < kR; r++) {
            float a = As[r * 132 + m];
            float4 p = *(const float4*)&PsT[r * kH + hg * 4];
            acc[0] += p.x * a; acc[1] += p.y * a;
            acc[2] += p.z * a; acc[3] += p.w * a;
        }
#pragma unroll
        for (int u = 0; u < 4; u++)
            Wf[(((size_t)(b * kH + hg * 4 + u)) * kN + n) * kN + m] = acc[u];
    }
}

// ===================== av combo mma: O = W @ yv^T per (b,h) =================
__global__ __launch_bounds__(256) void av_mma_kernel(
    const float* __restrict__ Wf, const float* __restrict__ yvf,
    __nv_bfloat16* __restrict__ AO)
{
    extern __shared__ __align__(16) char dsm[];
    const int tid = threadIdx.x, wid = tid >> 5, lane = tid & 31;
    const int bh = blockIdx.x;
    const int warp_m = wid >> 1, warp_n = wid & 1;
    const uint32_t sbase = smem_u32(dsm);
    const uint32_t vbase = sbase + 65536u;

    const float* Wb = Wf + (size_t)bh * kN * kN;
    {
        const int mq = tid & 31, r0 = tid >> 5;
#pragma unroll
        for (int i = 0; i < 16; i++) {
            const int row = r0 + 8 * i;
            float4 v = *(const float4*)&Wb[(size_t)row * kN + mq * 4];
            float f[4] = {v.x, v.y, v.z, v.w};
            __nv_bfloat16 hi[4], lo[4];
#pragma unroll
            for (int u = 0; u < 4; u++) {
                hi[u] = __float2bfloat16(f[u]);
                lo[u] = __float2bfloat16(f[u] - __bfloat162float(hi[u]));
            }
            const int m0 = mq * 4;
            const int stage = m0 >> 5;
            const int ch = (m0 & 31) >> 3;
            const int hb = (m0 & 7) >> 2;
            uint32_t addr = sbase + stage * 8192 + row * 64
                          + ((ch ^ (row & 3)) << 4) + hb * 8;
            sts64(addr, pack_bf2(hi[0], hi[1]), pack_bf2(hi[2], hi[3]));
            sts64(addr + 4 * 8192, pack_bf2(lo[0], lo[1]), pack_bf2(lo[2], lo[3]));
        }
    }
    const float* Vb = yvf + (size_t)bh * kN * kHD;
    {
        const int dq = tid & 15, mp0 = tid >> 4;
#pragma unroll
        for (int i = 0; i < 4; i++) {
            const int mp = mp0 + 16 * i;
            const int m0 = 2 * mp;
            float4 v0 = *(const float4*)&Vb[(size_t)m0 * kHD + dq * 4];
            float4 v1 = *(const float4*)&Vb[(size_t)(m0 + 1) * kHD + dq * 4];
            float f0[4] = {v0.x, v0.y, v0.z, v0.w};
            float f1[4] = {v1.x, v1.y, v1.z, v1.w};
            const int stage = m0 >> 5;
            const int ch = (m0 & 31) >> 3;
            const int ob = (m0 & 7) * 2;
#pragma unroll
            for (int u = 0; u < 4; u++) {
                const int row = dq * 4 + u;
                __nv_bfloat16 h0 = __float2bfloat16(f0[u]);
                __nv_bfloat16 h1 = __float2bfloat16(f1[u]);
                __nv_bfloat16 l0 = __float2bfloat16(f0[u] - __bfloat162float(h0));
                __nv_bfloat16 l1 = __float2bfloat16(f1[u] - __bfloat162float(h1));
                uint32_t addr = vbase + stage * 4096 + row * 64
                              + ((ch ^ (row & 3)) << 4) + ob;
                sts32(addr, pack_bf2(h0, h1));
                sts32(addr + 4 * 4096, pack_bf2(l0, l1));
            }
        }
    }
    __syncthreads();

    float acc[2][4][4];
#pragma unroll
    for (int i = 0; i < 2; i++)
#pragma unroll
        for (int j = 0; j < 4; j++)
#pragma unroll
            for (int t = 0; t < 4; t++) acc[i][j][t] = 0.f;

    const int a_row = warp_m * 32 + (lane & 15);
    const int a_chsel = lane >> 4;
    const int b_mi = lane >> 3;
    const int b_row = warp_n * 32 + ((b_mi >> 1) << 3) + (lane & 7);
    const int b_chsel = b_mi & 1;

    const int schedA[12] = {0,1,2,3, 4,5,6,7, 0,1,2,3};
    const int schedB[12] = {0,1,2,3, 0,1,2,3, 4,5,6,7};

#pragma unroll
    for (int it = 0; it < 12; it++) {
        const uint32_t sA = sbase + schedA[it] * 8192;
        const uint32_t sB = vbase + schedB[it] * 4096;
#pragma unroll
        for (int kk = 0; kk < 2; kk++) {
            uint32_t a[2][4];
#pragma unroll
            for (int i = 0; i < 2; i++) {
                int r = a_row + i * 16;
                int ch = 2 * kk + a_chsel;
                ldsm_x4(a[i], sA + r * 64 + ((ch ^ (r & 3)) << 4));
            }
            uint32_t b[4][2];
#pragma unroll
            for (int g = 0; g < 2; g++) {
                int r = b_row + g * 16;
                int ch = 2 * kk + b_chsel;
                uint32_t rr[4];
                ldsm_x4(rr, sB + r * 64 + ((ch ^ (r & 3)) << 4));
                b[2 * g][0] = rr[0]; b[2 * g][1] = rr[1];
                b[2 * g + 1][0] = rr[2]; b[2 * g + 1][1] = rr[3];
            }
#pragma unroll
            for (int i = 0; i < 2; i++)
#pragma unroll
                for (int j = 0; j < 4; j++)
                    mma16816(acc[i][j], a[i], b[j]);
        }
    }

    const int gq = lane >> 2, t4 = lane & 3;
    const int b_ = bh >> 3, h_ = bh & 7;
#pragma unroll
    for (int i = 0; i < 2; i++) {
#pragma unroll
        for (int j = 0; j < 4; j++) {
            const int d = warp_n * 32 + j * 8 + t4 * 2;
            const int c = h_ * kHD + d;
#pragma unroll
            for (int rr = 0; rr < 2; rr++) {
                const int nrow = warp_m * 32 + i * 16 + gq + rr * 8;
                const float f0 = acc[i][j][rr * 2], f1 = acc[i][j][rr * 2 + 1];
                __nv_bfloat16 h0 = __float2bfloat16(f0), h1 = __float2bfloat16(f1);
                __nv_bfloat16 l0 = __float2bfloat16(f0 - __bfloat162float(h0));
                __nv_bfloat16 l1 = __float2bfloat16(f1 - __bfloat162float(h1));
                __nv_bfloat16* base = AO + (size_t)(b_ * kN + nrow) * kKp + c;
                *(uint32_t*)(base)        = pack_bf2(h0, h1);
                *(uint32_t*)(base + 512)  = pack_bf2(l0, l1);
                *(uint32_t*)(base + 1024) = pack_bf2(h0, h1);
            }
        }
    }
}

// ===================== launch =====================
extern "C" void kernel_launch(void* const* d_in, const int* in_sizes, int n_in,
                              void* d_out, int out_size)
{
    const float* x        = (const float*)d_in[0];
    const float* assign   = (const float*)d_in[1];
    const void*  mask     = d_in[2];
    const float* q_w      = (const float*)d_in[3];
    const float* kv_w     = (const float*)d_in[4];
    const float* rel_bias = (const float*)d_in[5];
    const float* proj_w   = (const float*)d_in[6];
    const float* proj_b   = (const float*)d_in[7];

    float *S, *Wfp, *yvf, *qfp, *kfp, *AsTg;
    __nv_bfloat16 *Ax, *Bqkv, *Bproj, *AO;
    cudaGetSymbolAddress((void**)&S,    g_S);
    cudaGetSymbolAddress((void**)&Wfp,  g_Wf);
    cudaGetSymbolAddress((void**)&yvf,  g_yvf);
    cudaGetSymbolAddress((void**)&qfp,  g_qf);
    cudaGetSymbolAddress((void**)&kfp,  g_kf);
    cudaGetSymbolAddress((void**)&AsTg, g_AsT);
    cudaGetSymbolAddress((void**)&Ax,    g_Ax);
    cudaGetSymbolAddress((void**)&Bqkv,  g_Bqkv);
    cudaGetSymbolAddress((void**)&Bproj, g_Bproj);
    cudaGetSymbolAddress((void**)&AO,    g_AO);

    const int AV_SMEM = 8 * 8192 + 8 * 4096;  // 96 KB
    cudaFuncSetAttribute(av_mma_kernel,
                         cudaFuncAttributeMaxDynamicSharedMemorySize, AV_SMEM);
    const int QK_SMEM = 8 * 8192;             // 64 KB
    cudaFuncSetAttribute(qk_combo_kernel,
                         cudaFuncAttributeMaxDynamicSharedMemorySize, QK_SMEM);

    // 1. input hi/lo splits + mask probe + A transpose
    convert_all_kernel<<<4225, 128>>>(x, q_w, kv_w, proj_w, assign, mask,
                                      Ax, Bqkv, Bproj, AsTg);

    // 2. fused q/kv projection -> qf/kf/yvf compact fp32 (MTILE=256, 96 blocks)
    mma_gemm_t<3072, 48, 1, 256><<<dim3(12, 8), 256>>>(
        Ax, Bqkv, nullptr, yvf, nullptr, 0, 0, 0, qfp, kfp);

    // 3. S = 0.125 * q@k^T per (b,h), combo split-K
    qk_combo_kernel<<<128, 256, QK_SMEM>>>(qfp, kfp, S);

    // 4. logits + masked softmax + W (fp32)
    att_kernel<<<kB * kN, 256>>>(S, AsTg, mask, rel_bias, Wfp);

    // 5. O = W @ yv per (b,h), combo split-K on tensor cores (emits AO triple)
    av_mma_kernel<<<128, 256, AV_SMEM>>>(Wfp, yvf, AO);

    // 6. out-proj: AO @ Bproj^T + bias (MTILE=64, 128 blocks)
    mma_gemm_t<3072, 48, 0, 64><<<dim3(4, 32), 256>>>(
        AO, Bproj, (float*)d_out, (float*)d_out, proj_b, 1 << 30, kC, kC,
        nullptr, nullptr);
}

// round 16
// speedup vs baseline: 1.3903x; 1.0725x over previous
#include <cuda_runtime.h>
#include <cuda_bf16.h>
#include <cuda_fp16.h>
#include <cstdint>

// Problem dims
constexpr int kB  = 16;
constexpr int kN  = 128;
constexpr int kC  = 512;
constexpr int kH  = 8;
constexpr int kR  = 17;
constexpr int kHD = 64;
constexpr int kBN = kB * kN;    // 2048
constexpr int kKp = 3 * kC;     // 1536 split-K' (qkv, bf16 3-term)
constexpr int kKo = 2 * kC;     // 1024 split-K' (proj, fp16 2-term)

// Scratch (device globals; no allocations allowed)
__device__ float g_S[kB * kH * kN * kN];
__device__ float g_Wf[kB * kH * kN * kN];
__device__ float g_yvf[kB * kH * kN * kHD];
__device__ float g_qf[kB * kH * kN * kHD];
__device__ float g_kf[kB * kH * kN * kHD];
__device__ float g_AsT[kN * kR * kN];
__device__ int   g_mask_mode;
__device__ __nv_bfloat16 g_Ax[kBN * kKp];        // x hi|lo|hi
__device__ __nv_bfloat16 g_Bqkv[kKp * kKp];      // [q_w;kv_w] hi|hi|lo
__device__ __half        g_Bproj2[kC * kKo];     // proj_w [Ph|Ph] fp16
__device__ __half        g_AO2[kBN * kKo];       // O [Oh|Ol] fp16

__device__ __forceinline__ float neg_inf() { return __int_as_float(0xFF800000); }

// ===================== baseline-PTX helpers =====================
__device__ __forceinline__ uint32_t smem_u32(const void* p) {
    uint32_t a;
    asm("{ .reg .u64 t; cvta.to.shared.u64 t, %1; cvt.u32.u64 %0, t; }"
        : "=r"(a) : "l"(p));
    return a;
}
__device__ __forceinline__ void cp_async16(uint32_t saddr, const void* gaddr) {
    asm volatile("cp.async.cg.shared.global [%0], [%1], 16;"
                 :: "r"(saddr), "l"(gaddr) : "memory");
}
__device__ __forceinline__ void cp_commit() {
    asm volatile("cp.async.commit_group;" ::: "memory");
}
__device__ __forceinline__ void cp_wait0() {
    asm volatile("cp.async.wait_group 0;" ::: "memory");
}
__device__ __forceinline__ void ldsm_x4(uint32_t* r, uint32_t addr) {
    asm volatile("ldmatrix.sync.aligned.m8n8.x4.shared.b16 {%0,%1,%2,%3}, [%4];"
                 : "=r"(r[0]), "=r"(r[1]), "=r"(r[2]), "=r"(r[3]) : "r"(addr));
}
__device__ __forceinline__ void mma_bf16(float* d, const uint32_t* a, const uint32_t* b) {
    asm volatile("mma.sync.aligned.m16n8k16.row.col.f32.bf16.bf16.f32 "
                 "{%0,%1,%2,%3}, {%4,%5,%6,%7}, {%8,%9}, {%0,%1,%2,%3};"
                 : "+f"(d[0]), "+f"(d[1]), "+f"(d[2]), "+f"(d[3])
                 : "r"(a[0]), "r"(a[1]), "r"(a[2]), "r"(a[3]),
                   "r"(b[0]), "r"(b[1]));
}
__device__ __forceinline__ void mma_f16(float* d, const uint32_t* a, const uint32_t* b) {
    asm volatile("mma.sync.aligned.m16n8k16.row.col.f32.f16.f16.f32 "
                 "{%0,%1,%2,%3}, {%4,%5,%6,%7}, {%8,%9}, {%0,%1,%2,%3};"
                 : "+f"(d[0]), "+f"(d[1]), "+f"(d[2]), "+f"(d[3])
                 : "r"(a[0]), "r"(a[1]), "r"(a[2]), "r"(a[3]),
                   "r"(b[0]), "r"(b[1]));
}
__device__ __forceinline__ uint32_t pack_bf2(__nv_bfloat16 lo, __nv_bfloat16 hi) {
    return ((uint32_t)__bfloat16_as_ushort(hi) << 16) | __bfloat16_as_ushort(lo);
}
__device__ __forceinline__ uint32_t pack_h2(__half lo, __half hi) {
    return ((uint32_t)__half_as_ushort(hi) << 16) | __half_as_ushort(lo);
}
__device__ __forceinline__ void sts32(uint32_t addr, uint32_t v) {
    asm volatile("st.shared.b32 [%0], %1;" :: "r"(addr), "r"(v) : "memory");
}
__device__ __forceinline__ void sts64(uint32_t addr, uint32_t v0, uint32_t v1) {
    asm volatile("st.shared.v2.b32 [%0], {%1,%2};" :: "r"(addr), "r"(v0), "r"(v1) : "memory");
}
__device__ __forceinline__ float dot4(float4 a, float4 b) {
    return a.x * b.x + a.y * b.y + a.z * b.z + a.w * b.w;
}

// ===================== fused converts + mask probe + A-transpose ============
__global__ __launch_bounds__(128) void convert_all_kernel(
    const float* __restrict__ x, const float* __restrict__ q_w,
    const float* __restrict__ kv_w, const float* __restrict__ proj_w,
    const float* __restrict__ assign, const void* __restrict__ mask,
    __nv_bfloat16* __restrict__ Ax, __nv_bfloat16* __restrict__ Bqkv,
    __half* __restrict__ Bproj2, float* __restrict__ AsTg)
{
    const int rb = blockIdx.x;
    if (rb == 4096) {
        __shared__ int s_not_i32, s_not_f32;
        if (threadIdx.x == 0) { s_not_i32 = 0; s_not_f32 = 0; }
        __syncthreads();
        const unsigned int* w = (const unsigned int*)mask;
        int bad_i = 0, bad_f = 0;
        for (int i = threadIdx.x; i < 544; i += 128) {
            unsigned int v = w[i];
            if (v > 1u) bad_i = 1;
            if (v != 0u && v != 0x3F800000u) bad_f = 1;
        }
        if (bad_i) atomicOr(&s_not_i32, 1);
        if (bad_f) atomicOr(&s_not_f32, 1);
        __syncthreads();
        if (threadIdx.x == 0)
            g_mask_mode = (!s_not_i32) ? 0 : ((!s_not_f32) ? 1 : 2);
        return;
    }
    if (rb >= 4097) {
        const int n = rb - 4097;
        __shared__ __align__(16) float At[2176];
        const float* arow = assign + (size_t)n * 2176;
        for (int i = threadIdx.x; i < 544; i += 128)
            *(float4*)&At[i * 4] = *(const float4*)&arow[i * 4];
        __syncthreads();
        float* out = AsTg + (size_t)n * 2176;
        for (int j = threadIdx.x; j < 544; j += 128) {
            const int o = j * 4;
            const int r = o >> 7, m = o & 127;
            float4 v = make_float4(At[m * kR + r], At[(m + 1) * kR + r],
                                   At[(m + 2) * kR + r], At[(m + 3) * kR + r]);
            *(float4*)&out[o] = v;
        }
        return;
    }
    if (rb >= 3584) {
        // proj_w -> fp16 [Ph|Ph], row width 1024
        const int r = rb - 3584;
        const float* src = proj_w + (size_t)r * kC;
        __half* dst = Bproj2 + (size_t)r * kKo;
        const int j0 = threadIdx.x * 4;
        float4 v = *(const float4*)&src[j0];
        uint32_t hp0 = pack_h2(__float2half(v.x), __float2half(v.y));
        uint32_t hp1 = pack_h2(__float2half(v.z), __float2half(v.w));
        uint32_t* d0 = (uint32_t*)(dst + j0);
        uint32_t* d1 = (uint32_t*)(dst + kC + j0);
        d0[0] = hp0; d0[1] = hp1;
        d1[0] = hp0; d1[1] = hp1;
        return;
    }
    const float* src;
    __nv_bfloat16* dst;
    bool aSide;
    if (rb < 2048)      { src = x + (size_t)rb * kC;             dst = Ax + (size_t)rb * kKp;           aSide = true;  }
    else if (rb < 2560) { int r = rb - 2048; src = q_w + (size_t)r * kC;    dst = Bqkv + (size_t)r * kKp;        aSide = false; }
    else                { int r = rb - 2560; src = kv_w + (size_t)r * kC;   dst = Bqkv + (size_t)(kC + r) * kKp; aSide = false; }

    const int j0 = threadIdx.x * 4;
    float4 v = *(const float4*)&src[j0];
    float f[4] = {v.x, v.y, v.z, v.w};
    __nv_bfloat16 hi[4], lo[4];
#pragma unroll
    for (int t = 0; t < 4; t++) {
        hi[t] = __float2bfloat16(f[t]);
        lo[t] = __float2bfloat16(f[t] - __bfloat162float(hi[t]));
    }
    uint32_t hp0 = pack_bf2(hi[0], hi[1]), hp1 = pack_bf2(hi[2], hi[3]);
    uint32_t lp0 = pack_bf2(lo[0], lo[1]), lp1 = pack_bf2(lo[2], lo[3]);
    uint32_t* d0 = (uint32_t*)(dst + j0);
    uint32_t* d1 = (uint32_t*)(dst + kC + j0);
    uint32_t* d2 = (uint32_t*)(dst + 2 * kC + j0);
    d0[0] = hp0; d0[1] = hp1;
    if (aSide) { d1[0] = lp0; d1[1] = lp1; d2[0] = hp0; d2[1] = hp1; }
    else       { d1[0] = hp0; d1[1] = hp1; d2[0] = lp0; d2[1] = lp1; }
}

// ===================== templated mma.sync GEMM ==============================
// MTILE = rows per block. N-tile fixed at 128. F16: use fp16 mma (else bf16).
// MODE 0: C0/C1 fp32 split-column output (+bias)
// MODE 1: qkv epilogue -> qf/kf/yvf compact fp32 [bh][row][64]
template<int KBYTES, int NITER, int MODE, int MTILE, bool F16>
__global__ __launch_bounds__(256) void mma_gemm_t(
    const __nv_bfloat16* __restrict__ A,
    const __nv_bfloat16* __restrict__ Bw,
    float* __restrict__ C0, float* __restrict__ C1,
    const float* __restrict__ bias, int split, int ld0, int ld1,
    float* __restrict__ qf, float* __restrict__ kf)
{
    constexpr int IR = MTILE / 64;
    constexpr int ASTG = MTILE * 64;
    constexpr int STAGE = ASTG + 8192;
    __shared__ __align__(16) char smem[2 * STAGE];
    const int tid = threadIdx.x;
    const int wid = tid >> 5, lane = tid & 31;
    const int warp_m = wid >> 1, warp_n = wid & 1;

    const int m0 = blockIdx.y * MTILE, n0 = blockIdx.x * 128;
    const char* Ag = (const char*)A  + (size_t)m0 * KBYTES;
    const char* Bg = (const char*)Bw + (size_t)n0 * KBYTES;

    const int lr = tid >> 2, lc = tid & 3;
    uint32_t sbase = smem_u32(&smem[0]);
    auto so = [&](int row) {
        return (uint32_t)(row * 64 + ((lc ^ (row & 3)) << 4));
    };

    auto stage_load = [&](int st, int k0b) {
        uint32_t sA = sbase + st * STAGE;
        uint32_t sB = sA + ASTG;
#pragma unroll
        for (int p = 0; p < IR; p++) {
            int row = lr + p * 64;
            cp_async16(sA + so(row), Ag + (size_t)row * KBYTES + k0b + lc * 16);
        }
        cp_async16(sB + so(lr), Bg + (size_t)lr * KBYTES + k0b + lc * 16);
        cp_async16(sB + so(lr + 64),
                   Bg + (size_t)(lr + 64) * KBYTES + k0b + lc * 16);
    };

    float acc[IR][8][4];
#pragma unroll
    for (int i = 0; i < IR; i++)
#pragma unroll
        for (int j = 0; j < 8; j++)
#pragma unroll
            for (int t = 0; t < 4; t++) acc[i][j][t] = 0.f;

    stage_load(0, 0);
    cp_commit();

    const int a_row = warp_m * (MTILE / 4) + (lane & 15);
    const int a_chsel = lane >> 4;
    const int b_mi = lane >> 3;
    const int b_row = warp_n * 64 + ((b_mi >> 1) << 3) + (lane & 7);
    const int b_chsel = b_mi & 1;

    for (int it = 0; it < NITER; it++) {
        cp_wait0();
        __syncthreads();
        if (it + 1 < NITER) { stage_load((it + 1) & 1, (it + 1) * 64); cp_commit(); }

        const uint32_t sA = sbase + (it & 1) * STAGE;
        const uint32_t sB = sA + ASTG;
#pragma unroll
        for (int kk = 0; kk < 2; kk++) {
            uint32_t a[IR][4];
#pragma unroll
            for (int i = 0; i < IR; i++) {
                int r = a_row + i * 16;
                int ch = 2 * kk + a_chsel;
                ldsm_x4(a[i], sA + r * 64 + ((ch ^ (r & 3)) << 4));
            }
            uint32_t b[8][2];
#pragma unroll
            for (int g = 0; g < 4; g++) {
                int r = b_row + g * 16;
                int ch = 2 * kk + b_chsel;
                uint32_t rr[4];
                ldsm_x4(rr, sB + r * 64 + ((ch ^ (r & 3)) << 4));
                b[2 * g][0] = rr[0]; b[2 * g][1] = rr[1];
                b[2 * g + 1][0] = rr[2]; b[2 * g + 1][1] = rr[3];
            }
#pragma unroll
            for (int i = 0; i < IR; i++)
#pragma unroll
                for (int j = 0; j < 8; j++) {
                    if (F16) mma_f16(acc[i][j], a[i], b[j]);
                    else     mma_bf16(acc[i][j], a[i], b[j]);
                }
        }
        __syncthreads();
    }

    const int gq = lane >> 2, t4 = lane & 3;

    if (MODE == 1) {
        auto emit = [&](int row, int colg, float f0, float f1) {
            float* dst; int c;
            if (colg < 512)       { dst = qf;  c = colg; }
            else if (colg < 1024) { dst = kf;  c = colg - 512; }
            else                  { dst = C1;  c = colg - 1024; }
            const int h = c >> 6, d = c & 63;
            const int bb = row >> 7, nn = row & 127;
            *(float2*)&dst[((size_t)((bb * kH + h) * kN + nn)) * kHD + d] =
                make_float2(f0, f1);
        };
#pragma unroll
        for (int i = 0; i < IR; i++) {
#pragma unroll
            for (int j = 0; j < 8; j++) {
                int colg = n0 + warp_n * 64 + j * 8 + t4 * 2;
                int row0 = m0 + warp_m * (MTILE / 4) + i * 16 + gq;
                emit(row0,     colg, acc[i][j][0], acc[i][j][1]);
                emit(row0 + 8, colg, acc[i][j][2], acc[i][j][3]);
            }
        }
        return;
    }

    // MODE 0
#pragma unroll
    for (int i = 0; i < IR; i++) {
#pragma unroll
        for (int j = 0; j < 8; j++) {
            int colg = n0 + warp_n * 64 + j * 8 + t4 * 2;
            float bz0 = bias ? bias[colg]     : 0.f;
            float bz1 = bias ? bias[colg + 1] : 0.f;
            float* Cc; int ldc, cc;
            if (colg < split) { Cc = C0; ldc = ld0; cc = colg; }
            else              { Cc = C1; ldc = ld1; cc = colg - split; }
            int row0 = m0 + warp_m * (MTILE / 4) + i * 16 + gq;
            *(float2*)&Cc[(size_t)row0 * ldc + cc] =
                make_float2(acc[i][j][0] + bz0, acc[i][j][1] + bz1);
            *(float2*)&Cc[(size_t)(row0 + 8) * ldc + cc] =
                make_float2(acc[i][j][2] + bz0, acc[i][j][3] + bz1);
        }
    }
}

// ===================== qk combo mma: S = 0.125 * q@k^T per (b,h) ============
__global__ __launch_bounds__(256) void qk_combo_kernel(
    const float* __restrict__ qf, const float* __restrict__ kf,
    float* __restrict__ S)
{
    extern __shared__ __align__(16) char dsm[];
    const int tid = threadIdx.x, wid = tid >> 5, lane = tid & 31;
    const int bh = blockIdx.x;
    const int warp_m = wid >> 1, warp_n = wid & 1;
    const uint32_t sbase = smem_u32(dsm);
    const uint32_t vbase = sbase + 32768u;

    auto load_side = [&](const float* src, uint32_t base) {
        const int dq = tid & 15, r0 = tid >> 4;
#pragma unroll
        for (int i = 0; i < 8; i++) {
            const int row = r0 + 16 * i;
            float4 v = *(const float4*)&src[(size_t)row * kHD + dq * 4];
            float f[4] = {v.x, v.y, v.z, v.w};
            __nv_bfloat16 hi[4], lo[4];
#pragma unroll
            for (int u = 0; u < 4; u++) {
                hi[u] = __float2bfloat16(f[u]);
                lo[u] = __float2bfloat16(f[u] - __bfloat162float(hi[u]));
            }
            const int d0 = dq * 4;
            const int stage = d0 >> 5;
            const int ch = (d0 & 31) >> 3;
            const int hb = (d0 & 7) >> 2;
            uint32_t addr = base + stage * 8192 + row * 64
                          + ((ch ^ (row & 3)) << 4) + hb * 8;
            sts64(addr, pack_bf2(hi[0], hi[1]), pack_bf2(hi[2], hi[3]));
            sts64(addr + 2 * 8192, pack_bf2(lo[0], lo[1]), pack_bf2(lo[2], lo[3]));
        }
    };
    load_side(qf + (size_t)bh * kN * kHD, sbase);
    load_side(kf + (size_t)bh * kN * kHD, vbase);
    __syncthreads();

    float acc[2][8][4];
#pragma unroll
    for (int i = 0; i < 2; i++)
#pragma unroll
        for (int j = 0; j < 8; j++)
#pragma unroll
            for (int t = 0; t < 4; t++) acc[i][j][t] = 0.f;

    const int a_row = warp_m * 32 + (lane & 15);
    const int a_chsel = lane >> 4;
    const int b_mi = lane >> 3;
    const int b_row = warp_n * 64 + ((b_mi >> 1) << 3) + (lane & 7);
    const int b_chsel = b_mi & 1;

    const int schedA[6] = {0,1, 2,3, 0,1};
    const int schedB[6] = {0,1, 0,1, 2,3};

#pragma unroll
    for (int it = 0; it < 6; it++) {
        const uint32_t sA = sbase + schedA[it] * 8192;
        const uint32_t sB = vbase + schedB[it] * 8192;
#pragma unroll
        for (int kk = 0; kk < 2; kk++) {
            uint32_t a[2][4];
#pragma unroll
            for (int i = 0; i < 2; i++) {
                int r = a_row + i * 16;
                int ch = 2 * kk + a_chsel;
                ldsm_x4(a[i], sA + r * 64 + ((ch ^ (r & 3)) << 4));
            }
            uint32_t b[8][2];
#pragma unroll
            for (int g = 0; g < 4; g++) {
                int r = b_row + g * 16;
                int ch = 2 * kk + b_chsel;
                uint32_t rr[4];
                ldsm_x4(rr, sB + r * 64 + ((ch ^ (r & 3)) << 4));
                b[2 * g][0] = rr[0]; b[2 * g][1] = rr[1];
                b[2 * g + 1][0] = rr[2]; b[2 * g + 1][1] = rr[3];
            }
#pragma unroll
            for (int i = 0; i < 2; i++)
#pragma unroll
                for (int j = 0; j < 8; j++)
                    mma_bf16(acc[i][j], a[i], b[j]);
        }
    }

    const int gq = lane >> 2, t4 = lane & 3;
    float* Sp = S + (size_t)bh * kN * kN;
#pragma unroll
    for (int i = 0; i < 2; i++) {
#pragma unroll
        for (int j = 0; j < 8; j++) {
            int col = warp_n * 64 + j * 8 + t4 * 2;
            int r0 = warp_m * 32 + i * 16 + gq;
            *(float2*)&Sp[(size_t)r0 * kN + col] =
                make_float2(acc[i][j][0] * 0.125f, acc[i][j][1] * 0.125f);
            *(float2*)&Sp[(size_t)(r0 + 8) * kN + col] =
                make_float2(acc[i][j][2] * 0.125f, acc[i][j][3] * 0.125f);
        }
    }
}

// ===================== att v7 (champion) =====================
__global__ __launch_bounds__(256) void att_kernel(
    const float* __restrict__ S, const float* __restrict__ AsTg,
    const void* __restrict__ mask, const float* __restrict__ rel_bias,
    float* __restrict__ Wf)
{
    __shared__ __align__(16) float As[kR * 132];
    __shared__ __align__(16) float Ss[kH * 132];
    __shared__ __align__(16) float Lp[kH * kR * 8];
    __shared__ __align__(16) float Ls[kH * 20];
    __shared__ __align__(16) float PsT[20 * kH];
    __shared__ __align__(16) float rb[136];
    __shared__ __align__(16) int   mk[kR];

    const int t = threadIdx.x, wid = t >> 5, lane = t & 31;
    const int b = blockIdx.x >> 7, n = blockIdx.x & 127;

    {
        const int h = t >> 5, m0 = (t & 31) * 4;
        *(float4*)&Ss[h * 132 + m0] =
            *(const float4*)&S[(((size_t)(b * kH + h)) * kN + n) * kN + m0];
    }
    const float* ag = AsTg + (size_t)n * (kR * kN);
    for (int i = t; i < 544; i += 256) {
        const int r = i >> 5, m0 = (i & 31) * 4;
        *(float4*)&As[r * 132 + m0] = *(const float4*)&ag[r * kN + m0];
    }
    if (t < 136) rb[t] = rel_bias[t];
    if (t < kR) {
        int mode = g_mask_mode;
        int idx = n * kR + t;
        bool m_;
        if (mode == 0)      m_ = ((const int*)mask)[idx] != 0;
        else if (mode == 1) m_ = ((const float*)mask)[idx] != 0.f;
        else                m_ = ((const unsigned char*)mask)[idx] != 0;
        mk[t] = m_ ? 1 : 0;
    }
    __syncthreads();

    {
        const int h = wid;
        float4 sv = *(const float4*)&Ss[h * 132 + lane * 4];
#pragma unroll
        for (int r = 0; r < kR; r++) {
            float4 av = *(const float4*)&As[r * 132 + lane * 4];
            float d = dot4(sv, av);
            d += __shfl_xor_sync(0xFFFFFFFFu, d, 1);
            d += __shfl_xor_sync(0xFFFFFFFFu, d, 2);
            if ((lane & 3) == 0)
                Lp[(h * kR + r) * 8 + (lane >> 2)] = d;
        }
    }
    __syncthreads();

    if (t < 136) {
        const int h = t / kR, r = t - h * kR;
        const float* p = &Lp[t * 8];
        float s = ((p[0] + p[1]) + (p[2] + p[3]))
                + ((p[4] + p[5]) + (p[6] + p[7]));
        Ls[h * 20 + r] = mk[r] ? neg_inf() : (s + rb[t]);
    }
    __syncthreads();

    {
        const int h = wid;
        float v = (lane < kR) ? Ls[h * 20 + lane] : neg_inf();
        float mx = v;
#pragma unroll
        for (int o = 16; o > 0; o >>= 1)
            mx = fmaxf(mx, __shfl_xor_sync(0xFFFFFFFFu, mx, o));
        float e = (lane < kR) ? __expf(v - mx) : 0.f;
        float s = e;
#pragma unroll
        for (int o = 16; o > 0; o >>= 1)
            s += __shfl_xor_sync(0xFFFFFFFFu, s, o);
        if (lane < kR) PsT[lane * kH + h] = e / s;
    }
    __syncthreads();

    {
        const int m = t & 127, hg = t >> 7;
        float acc[4] = {0.f, 0.f, 0.f, 0.f};
#pragma unroll
        for (int r = 0; r < kR; r++) {
            float a = As[r * 132 + m];
            float4 p = *(const float4*)&PsT[r * kH + hg * 4];
            acc[0] += p.x * a; acc[1] += p.y * a;
            acc[2] += p.z * a; acc[3] += p.w * a;
        }
#pragma unroll
        for (int u = 0; u < 4; u++)
            Wf[(((size_t)(b * kH + hg * 4 + u)) * kN + n) * kN + m] = acc[u];
    }
}

// ===================== av combo mma: O = W @ yv^T per (b,h) =================
// Emits fp16 [Oh|Ol] pairs into AO2 (row width 1024).
__global__ __launch_bounds__(256) void av_mma_kernel(
    const float* __restrict__ Wf, const float* __restrict__ yvf,
    __half* __restrict__ AO2)
{
    extern __shared__ __align__(16) char dsm[];
    const int tid = threadIdx.x, wid = tid >> 5, lane = tid & 31;
    const int bh = blockIdx.x;
    const int warp_m = wid >> 1, warp_n = wid & 1;
    const uint32_t sbase = smem_u32(dsm);
    const uint32_t vbase = sbase + 65536u;

    const float* Wb = Wf + (size_t)bh * kN * kN;
    {
        const int mq = tid & 31, r0 = tid >> 5;
#pragma unroll
        for (int i = 0; i < 16; i++) {
            const int row = r0 + 8 * i;
            float4 v = *(const float4*)&Wb[(size_t)row * kN + mq * 4];
            float f[4] = {v.x, v.y, v.z, v.w};
            __nv_bfloat16 hi[4], lo[4];
#pragma unroll
            for (int u = 0; u < 4; u++) {
                hi[u] = __float2bfloat16(f[u]);
                lo[u] = __float2bfloat16(f[u] - __bfloat162float(hi[u]));
            }
            const int m0 = mq * 4;
            const int stage = m0 >> 5;
            const int ch = (m0 & 31) >> 3;
            const int hb = (m0 & 7) >> 2;
            uint32_t addr = sbase + stage * 8192 + row * 64
                          + ((ch ^ (row & 3)) << 4) + hb * 8;
            sts64(addr, pack_bf2(hi[0], hi[1]), pack_bf2(hi[2], hi[3]));
            sts64(addr + 4 * 8192, pack_bf2(lo[0], lo[1]), pack_bf2(lo[2], lo[3]));
        }
    }
    const float* Vb = yvf + (size_t)bh * kN * kHD;
    {
        const int dq = tid & 15, mp0 = tid >> 4;
#pragma unroll
        for (int i = 0; i < 4; i++) {
            const int mp = mp0 + 16 * i;
            const int m0 = 2 * mp;
            float4 v0 = *(const float4*)&Vb[(size_t)m0 * kHD + dq * 4];
            float4 v1 = *(const float4*)&Vb[(size_t)(m0 + 1) * kHD + dq * 4];
            float f0[4] = {v0.x, v0.y, v0.z, v0.w};
            float f1[4] = {v1.x, v1.y, v1.z, v1.w};
            const int stage = m0 >> 5;
            const int ch = (m0 & 31) >> 3;
            const int ob = (m0 & 7) * 2;
#pragma unroll
            for (int u = 0; u < 4; u++) {
                const int row = dq * 4 + u;
                __nv_bfloat16 h0 = __float2bfloat16(f0[u]);
                __nv_bfloat16 h1 = __float2bfloat16(f1[u]);
                __nv_bfloat16 l0 = __float2bfloat16(f0[u] - __bfloat162float(h0));
                __nv_bfloat16 l1 = __float2bfloat16(f1[u] - __bfloat162float(h1));
                uint32_t addr = vbase + stage * 4096 + row * 64
                              + ((ch ^ (row & 3)) << 4) + ob;
                sts32(addr, pack_bf2(h0, h1));
                sts32(addr + 4 * 4096, pack_bf2(l0, l1));
            }
        }
    }
    __syncthreads();

    float acc[2][4][4];
#pragma unroll
    for (int i = 0; i < 2; i++)
#pragma unroll
        for (int j = 0; j < 4; j++)
#pragma unroll
            for (int t = 0; t < 4; t++) acc[i][j][t] = 0.f;

    const int a_row = warp_m * 32 + (lane & 15);
    const int a_chsel = lane >> 4;
    const int b_mi = lane >> 3;
    const int b_row = warp_n * 32 + ((b_mi >> 1) << 3) + (lane & 7);
    const int b_chsel = b_mi & 1;

    const int schedA[12] = {0,1,2,3, 4,5,6,7, 0,1,2,3};
    const int schedB[12] = {0,1,2,3, 0,1,2,3, 4,5,6,7};

#pragma unroll
    for (int it = 0; it < 12; it++) {
        const uint32_t sA = sbase + schedA[it] * 8192;
        const uint32_t sB = vbase + schedB[it] * 4096;
#pragma unroll
        for (int kk = 0; kk < 2; kk++) {
            uint32_t a[2][4];
#pragma unroll
            for (int i = 0; i < 2; i++) {
                int r = a_row + i * 16;
                int ch = 2 * kk + a_chsel;
                ldsm_x4(a[i], sA + r * 64 + ((ch ^ (r & 3)) << 4));
            }
            uint32_t b[4][2];
#pragma unroll
            for (int g = 0; g < 2; g++) {
                int r = b_row + g * 16;
                int ch = 2 * kk + b_chsel;
                uint32_t rr[4];
                ldsm_x4(rr, sB + r * 64 + ((ch ^ (r & 3)) << 4));
                b[2 * g][0] = rr[0]; b[2 * g][1] = rr[1];
                b[2 * g + 1][0] = rr[2]; b[2 * g + 1][1] = rr[3];
            }
#pragma unroll
            for (int i = 0; i < 2; i++)
#pragma unroll
                for (int j = 0; j < 4; j++)
                    mma_bf16(acc[i][j], a[i], b[j]);
        }
    }

    const int gq = lane >> 2, t4 = lane & 3;
    const int b_ = bh >> 3, h_ = bh & 7;
#pragma unroll
    for (int i = 0; i < 2; i++) {
#pragma unroll
        for (int j = 0; j < 4; j++) {
            const int d = warp_n * 32 + j * 8 + t4 * 2;
            const int c = h_ * kHD + d;
#pragma unroll
            for (int rr = 0; rr < 2; rr++) {
                const int nrow = warp_m * 32 + i * 16 + gq + rr * 8;
                const float f0 = acc[i][j][rr * 2], f1 = acc[i][j][rr * 2 + 1];
                __half h0 = __float2half(f0), h1 = __float2half(f1);
                __half l0 = __float2half(f0 - __half2float(h0));
                __half l1 = __float2half(f1 - __half2float(h1));
                __half* base = AO2 + (size_t)(b_ * kN + nrow) * kKo + c;
                *(uint32_t*)(base)       = pack_h2(h0, h1);
                *(uint32_t*)(base + 512) = pack_h2(l0, l1);
            }
        }
    }
}

// ===================== launch =====================
extern "C" void kernel_launch(void* const* d_in, const int* in_sizes, int n_in,
                              void* d_out, int out_size)
{
    const float* x        = (const float*)d_in[0];
    const float* assign   = (const float*)d_in[1];
    const void*  mask     = d_in[2];
    const float* q_w      = (const float*)d_in[3];
    const float* kv_w     = (const float*)d_in[4];
    const float* rel_bias = (const float*)d_in[5];
    const float* proj_w   = (const float*)d_in[6];
    const float* proj_b   = (const float*)d_in[7];

    float *S, *Wfp, *yvf, *qfp, *kfp, *AsTg;
    __nv_bfloat16 *Ax, *Bqkv;
    __half *Bproj2, *AO2;
    cudaGetSymbolAddress((void**)&S,    g_S);
    cudaGetSymbolAddress((void**)&Wfp,  g_Wf);
    cudaGetSymbolAddress((void**)&yvf,  g_yvf);
    cudaGetSymbolAddress((void**)&qfp,  g_qf);
    cudaGetSymbolAddress((void**)&kfp,  g_kf);
    cudaGetSymbolAddress((void**)&AsTg, g_AsT);
    cudaGetSymbolAddress((void**)&Ax,     g_Ax);
    cudaGetSymbolAddress((void**)&Bqkv,   g_Bqkv);
    cudaGetSymbolAddress((void**)&Bproj2, g_Bproj2);
    cudaGetSymbolAddress((void**)&AO2,    g_AO2);

    const int AV_SMEM = 8 * 8192 + 8 * 4096;  // 96 KB
    cudaFuncSetAttribute(av_mma_kernel,
                         cudaFuncAttributeMaxDynamicSharedMemorySize, AV_SMEM);
    const int QK_SMEM = 8 * 8192;             // 64 KB
    cudaFuncSetAttribute(qk_combo_kernel,
                         cudaFuncAttributeMaxDynamicSharedMemorySize, QK_SMEM);

    // 1. input splits + mask probe + A transpose
    convert_all_kernel<<<4225, 128>>>(x, q_w, kv_w, proj_w, assign, mask,
                                      Ax, Bqkv, Bproj2, AsTg);

    // 2. fused q/kv projection -> qf/kf/yvf compact fp32 (MTILE=256, 96 blocks)
    mma_gemm_t<3072, 48, 1, 256, false><<<dim3(12, 8), 256>>>(
        Ax, Bqkv, nullptr, yvf, nullptr, 0, 0, 0, qfp, kfp);

    // 3. S = 0.125 * q@k^T per (b,h), combo split-K
    qk_combo_kernel<<<128, 256, QK_SMEM>>>(qfp, kfp, S);

    // 4. logits + masked softmax + W (fp32)
    att_kernel<<<kB * kN, 256>>>(S, AsTg, mask, rel_bias, Wfp);

    // 5. O = W @ yv per (b,h), combo split-K (emits fp16 [Oh|Ol])
    av_mma_kernel<<<128, 256, AV_SMEM>>>(Wfp, yvf, AO2);

    // 6. out-proj fp16 2-term: [Oh|Ol] @ [Ph|Ph]^T + bias (K'=1024, 32 iters)
    mma_gemm_t<2048, 32, 0, 64, true><<<dim3(4, 32), 256>>>(
        (const __nv_bfloat16*)AO2, (const __nv_bfloat16*)Bproj2,
        (float*)d_out, (float*)d_out, proj_b, 1 << 30, kC, kC,
        nullptr, nullptr);
}

// round 17
// speedup vs baseline: 1.6251x; 1.1689x over previous
#include <cuda_runtime.h>
#include <cuda_bf16.h>
#include <cuda_fp16.h>
#include <cstdint>

// Problem dims
constexpr int kB  = 16;
constexpr int kN  = 128;
constexpr int kC  = 512;
constexpr int kH  = 8;
constexpr int kR  = 17;
constexpr int kHD = 64;
constexpr int kBN = kB * kN;    // 2048
constexpr int kKo = 2 * kC;     // 1024 split-K' (fp16 2-term)

// Scratch (device globals; no allocations allowed)
__device__ float g_S[kB * kH * kN * kN];
__device__ float g_Wf[kB * kH * kN * kN];
__device__ float g_yvf[kB * kH * kN * kHD];
__device__ float g_qf[kB * kH * kN * kHD];
__device__ float g_kf[kB * kH * kN * kHD];
__device__ float g_AsT[kN * kR * kN];
__device__ int   g_mask_mode;
__device__ __half g_Ax2[kBN * kKo];        // x  [Xh|Xl] fp16
__device__ __half g_Bqkv2[3 * kC * kKo];   // [q_w;kv_w] [Wh|Wh] fp16
__device__ __half g_Bproj2[kC * kKo];      // proj_w [Ph|Ph] fp16
__device__ __half g_AO2[kBN * kKo];        // O [Oh|Ol] fp16

__device__ __forceinline__ float neg_inf() { return __int_as_float(0xFF800000); }

// ===================== baseline-PTX helpers =====================
__device__ __forceinline__ uint32_t smem_u32(const void* p) {
    uint32_t a;
    asm("{ .reg .u64 t; cvta.to.shared.u64 t, %1; cvt.u32.u64 %0, t; }"
        : "=r"(a) : "l"(p));
    return a;
}
__device__ __forceinline__ void cp_async16(uint32_t saddr, const void* gaddr) {
    asm volatile("cp.async.cg.shared.global [%0], [%1], 16;"
                 :: "r"(saddr), "l"(gaddr) : "memory");
}
__device__ __forceinline__ void cp_commit() {
    asm volatile("cp.async.commit_group;" ::: "memory");
}
__device__ __forceinline__ void cp_wait0() {
    asm volatile("cp.async.wait_group 0;" ::: "memory");
}
__device__ __forceinline__ void ldsm_x4(uint32_t* r, uint32_t addr) {
    asm volatile("ldmatrix.sync.aligned.m8n8.x4.shared.b16 {%0,%1,%2,%3}, [%4];"
                 : "=r"(r[0]), "=r"(r[1]), "=r"(r[2]), "=r"(r[3]) : "r"(addr));
}
__device__ __forceinline__ void mma_bf16(float* d, const uint32_t* a, const uint32_t* b) {
    asm volatile("mma.sync.aligned.m16n8k16.row.col.f32.bf16.bf16.f32 "
                 "{%0,%1,%2,%3}, {%4,%5,%6,%7}, {%8,%9}, {%0,%1,%2,%3};"
                 : "+f"(d[0]), "+f"(d[1]), "+f"(d[2]), "+f"(d[3])
                 : "r"(a[0]), "r"(a[1]), "r"(a[2]), "r"(a[3]),
                   "r"(b[0]), "r"(b[1]));
}
__device__ __forceinline__ void mma_f16(float* d, const uint32_t* a, const uint32_t* b) {
    asm volatile("mma.sync.aligned.m16n8k16.row.col.f32.f16.f16.f32 "
                 "{%0,%1,%2,%3}, {%4,%5,%6,%7}, {%8,%9}, {%0,%1,%2,%3};"
                 : "+f"(d[0]), "+f"(d[1]), "+f"(d[2]), "+f"(d[3])
                 : "r"(a[0]), "r"(a[1]), "r"(a[2]), "r"(a[3]),
                   "r"(b[0]), "r"(b[1]));
}
__device__ __forceinline__ uint32_t pack_bf2(__nv_bfloat16 lo, __nv_bfloat16 hi) {
    return ((uint32_t)__bfloat16_as_ushort(hi) << 16) | __bfloat16_as_ushort(lo);
}
__device__ __forceinline__ uint32_t pack_h2(__half lo, __half hi) {
    return ((uint32_t)__half_as_ushort(hi) << 16) | __half_as_ushort(lo);
}
__device__ __forceinline__ void sts32(uint32_t addr, uint32_t v) {
    asm volatile("st.shared.b32 [%0], %1;" :: "r"(addr), "r"(v) : "memory");
}
__device__ __forceinline__ void sts64(uint32_t addr, uint32_t v0, uint32_t v1) {
    asm volatile("st.shared.v2.b32 [%0], {%1,%2};" :: "r"(addr), "r"(v0), "r"(v1) : "memory");
}
__device__ __forceinline__ float dot4(float4 a, float4 b) {
    return a.x * b.x + a.y * b.y + a.z * b.z + a.w * b.w;
}

// ===================== fused converts + mask probe + A-transpose ============
__global__ __launch_bounds__(128) void convert_all_kernel(
    const float* __restrict__ x, const float* __restrict__ q_w,
    const float* __restrict__ kv_w, const float* __restrict__ proj_w,
    const float* __restrict__ assign, const void* __restrict__ mask,
    __half* __restrict__ Ax2, __half* __restrict__ Bqkv2,
    __half* __restrict__ Bproj2, float* __restrict__ AsTg)
{
    const int rb = blockIdx.x;
    if (rb == 4096) {
        __shared__ int s_not_i32, s_not_f32;
        if (threadIdx.x == 0) { s_not_i32 = 0; s_not_f32 = 0; }
        __syncthreads();
        const unsigned int* w = (const unsigned int*)mask;
        int bad_i = 0, bad_f = 0;
        for (int i = threadIdx.x; i < 544; i += 128) {
            unsigned int v = w[i];
            if (v > 1u) bad_i = 1;
            if (v != 0u && v != 0x3F800000u) bad_f = 1;
        }
        if (bad_i) atomicOr(&s_not_i32, 1);
        if (bad_f) atomicOr(&s_not_f32, 1);
        __syncthreads();
        if (threadIdx.x == 0)
            g_mask_mode = (!s_not_i32) ? 0 : ((!s_not_f32) ? 1 : 2);
        return;
    }
    if (rb >= 4097) {
        const int n = rb - 4097;
        __shared__ __align__(16) float At[2176];
        const float* arow = assign + (size_t)n * 2176;
        for (int i = threadIdx.x; i < 544; i += 128)
            *(float4*)&At[i * 4] = *(const float4*)&arow[i * 4];
        __syncthreads();
        float* out = AsTg + (size_t)n * 2176;
        for (int j = threadIdx.x; j < 544; j += 128) {
            const int o = j * 4;
            const int r = o >> 7, m = o & 127;
            float4 v = make_float4(At[m * kR + r], At[(m + 1) * kR + r],
                                   At[(m + 2) * kR + r], At[(m + 3) * kR + r]);
            *(float4*)&out[o] = v;
        }
        return;
    }
    const int j0 = threadIdx.x * 4;
    if (rb < 2048) {
        // x -> fp16 [Xh|Xl] (A-side 2-term)
        const float* src = x + (size_t)rb * kC;
        __half* dst = Ax2 + (size_t)rb * kKo;
        float4 v = *(const float4*)&src[j0];
        float f[4] = {v.x, v.y, v.z, v.w};
        __half hi[4], lo[4];
#pragma unroll
        for (int t = 0; t < 4; t++) {
            hi[t] = __float2half(f[t]);
            lo[t] = __float2half(f[t] - __half2float(hi[t]));
        }
        uint32_t* d0 = (uint32_t*)(dst + j0);
        uint32_t* d1 = (uint32_t*)(dst + kC + j0);
        d0[0] = pack_h2(hi[0], hi[1]); d0[1] = pack_h2(hi[2], hi[3]);
        d1[0] = pack_h2(lo[0], lo[1]); d1[1] = pack_h2(lo[2], lo[3]);
        return;
    }
    // B-side fp16 [Wh|Wh]
    const float* src;
    __half* dst;
    if (rb < 2560)      { int r = rb - 2048; src = q_w + (size_t)r * kC;    dst = Bqkv2 + (size_t)r * kKo; }
    else if (rb < 3584) { int r = rb - 2560; src = kv_w + (size_t)r * kC;   dst = Bqkv2 + (size_t)(kC + r) * kKo; }
    else                { int r = rb - 3584; src = proj_w + (size_t)r * kC; dst = Bproj2 + (size_t)r * kKo; }
    float4 v = *(const float4*)&src[j0];
    uint32_t hp0 = pack_h2(__float2half(v.x), __float2half(v.y));
    uint32_t hp1 = pack_h2(__float2half(v.z), __float2half(v.w));
    uint32_t* d0 = (uint32_t*)(dst + j0);
    uint32_t* d1 = (uint32_t*)(dst + kC + j0);
    d0[0] = hp0; d0[1] = hp1;
    d1[0] = hp0; d1[1] = hp1;
}

// ===================== templated mma.sync GEMM ==============================
// MTILE = rows per block. N-tile fixed at 128. F16: use fp16 mma (else bf16).
// MODE 0: C0/C1 fp32 split-column output (+bias)
// MODE 1: qkv epilogue -> qf/kf/yvf compact fp32 [bh][row][64]
template<int KBYTES, int NITER, int MODE, int MTILE, bool F16>
__global__ __launch_bounds__(256) void mma_gemm_t(
    const __nv_bfloat16* __restrict__ A,
    const __nv_bfloat16* __restrict__ Bw,
    float* __restrict__ C0, float* __restrict__ C1,
    const float* __restrict__ bias, int split, int ld0, int ld1,
    float* __restrict__ qf, float* __restrict__ kf)
{
    constexpr int IR = MTILE / 64;
    constexpr int ASTG = MTILE * 64;
    constexpr int STAGE = ASTG + 8192;
    __shared__ __align__(16) char smem[2 * STAGE];
    const int tid = threadIdx.x;
    const int wid = tid >> 5, lane = tid & 31;
    const int warp_m = wid >> 1, warp_n = wid & 1;

    const int m0 = blockIdx.y * MTILE, n0 = blockIdx.x * 128;
    const char* Ag = (const char*)A  + (size_t)m0 * KBYTES;
    const char* Bg = (const char*)Bw + (size_t)n0 * KBYTES;

    const int lr = tid >> 2, lc = tid & 3;
    uint32_t sbase = smem_u32(&smem[0]);
    auto so = [&](int row) {
        return (uint32_t)(row * 64 + ((lc ^ (row & 3)) << 4));
    };

    auto stage_load = [&](int st, int k0b) {
        uint32_t sA = sbase + st * STAGE;
        uint32_t sB = sA + ASTG;
#pragma unroll
        for (int p = 0; p < IR; p++) {
            int row = lr + p * 64;
            cp_async16(sA + so(row), Ag + (size_t)row * KBYTES + k0b + lc * 16);
        }
        cp_async16(sB + so(lr), Bg + (size_t)lr * KBYTES + k0b + lc * 16);
        cp_async16(sB + so(lr + 64),
                   Bg + (size_t)(lr + 64) * KBYTES + k0b + lc * 16);
    };

    float acc[IR][8][4];
#pragma unroll
    for (int i = 0; i < IR; i++)
#pragma unroll
        for (int j = 0; j < 8; j++)
#pragma unroll
            for (int t = 0; t < 4; t++) acc[i][j][t] = 0.f;

    stage_load(0, 0);
    cp_commit();

    const int a_row = warp_m * (MTILE / 4) + (lane & 15);
    const int a_chsel = lane >> 4;
    const int b_mi = lane >> 3;
    const int b_row = warp_n * 64 + ((b_mi >> 1) << 3) + (lane & 7);
    const int b_chsel = b_mi & 1;

    for (int it = 0; it < NITER; it++) {
        cp_wait0();
        __syncthreads();
        if (it + 1 < NITER) { stage_load((it + 1) & 1, (it + 1) * 64); cp_commit(); }

        const uint32_t sA = sbase + (it & 1) * STAGE;
        const uint32_t sB = sA + ASTG;
#pragma unroll
        for (int kk = 0; kk < 2; kk++) {
            uint32_t a[IR][4];
#pragma unroll
            for (int i = 0; i < IR; i++) {
                int r = a_row + i * 16;
                int ch = 2 * kk + a_chsel;
                ldsm_x4(a[i], sA + r * 64 + ((ch ^ (r & 3)) << 4));
            }
            uint32_t b[8][2];
#pragma unroll
            for (int g = 0; g < 4; g++) {
                int r = b_row + g * 16;
                int ch = 2 * kk + b_chsel;
                uint32_t rr[4];
                ldsm_x4(rr, sB + r * 64 + ((ch ^ (r & 3)) << 4));
                b[2 * g][0] = rr[0]; b[2 * g][1] = rr[1];
                b[2 * g + 1][0] = rr[2]; b[2 * g + 1][1] = rr[3];
            }
#pragma unroll
            for (int i = 0; i < IR; i++)
#pragma unroll
                for (int j = 0; j < 8; j++) {
                    if (F16) mma_f16(acc[i][j], a[i], b[j]);
                    else     mma_bf16(acc[i][j], a[i], b[j]);
                }
        }
        __syncthreads();
    }

    const int gq = lane >> 2, t4 = lane & 3;

    if (MODE == 1) {
        auto emit = [&](int row, int colg, float f0, float f1) {
            float* dst; int c;
            if (colg < 512)       { dst = qf;  c = colg; }
            else if (colg < 1024) { dst = kf;  c = colg - 512; }
            else                  { dst = C1;  c = colg - 1024; }
            const int h = c >> 6, d = c & 63;
            const int bb = row >> 7, nn = row & 127;
            *(float2*)&dst[((size_t)((bb * kH + h) * kN + nn)) * kHD + d] =
                make_float2(f0, f1);
        };
#pragma unroll
        for (int i = 0; i < IR; i++) {
#pragma unroll
            for (int j = 0; j < 8; j++) {
                int colg = n0 + warp_n * 64 + j * 8 + t4 * 2;
                int row0 = m0 + warp_m * (MTILE / 4) + i * 16 + gq;
                emit(row0,     colg, acc[i][j][0], acc[i][j][1]);
                emit(row0 + 8, colg, acc[i][j][2], acc[i][j][3]);
            }
        }
        return;
    }

    // MODE 0
#pragma unroll
    for (int i = 0; i < IR; i++) {
#pragma unroll
        for (int j = 0; j < 8; j++) {
            int colg = n0 + warp_n * 64 + j * 8 + t4 * 2;
            float bz0 = bias ? bias[colg]     : 0.f;
            float bz1 = bias ? bias[colg + 1] : 0.f;
            float* Cc; int ldc, cc;
            if (colg < split) { Cc = C0; ldc = ld0; cc = colg; }
            else              { Cc = C1; ldc = ld1; cc = colg - split; }
            int row0 = m0 + warp_m * (MTILE / 4) + i * 16 + gq;
            *(float2*)&Cc[(size_t)row0 * ldc + cc] =
                make_float2(acc[i][j][0] + bz0, acc[i][j][1] + bz1);
            *(float2*)&Cc[(size_t)(row0 + 8) * ldc + cc] =
                make_float2(acc[i][j][2] + bz0, acc[i][j][3] + bz1);
        }
    }
}

// ===================== qk combo mma: S = 0.125 * q@k^T per (b,h) ============
__global__ __launch_bounds__(256) void qk_combo_kernel(
    const float* __restrict__ qf, const float* __restrict__ kf,
    float* __restrict__ S)
{
    extern __shared__ __align__(16) char dsm[];
    const int tid = threadIdx.x, wid = tid >> 5, lane = tid & 31;
    const int bh = blockIdx.x;
    const int warp_m = wid >> 1, warp_n = wid & 1;
    const uint32_t sbase = smem_u32(dsm);
    const uint32_t vbase = sbase + 32768u;

    auto load_side = [&](const float* src, uint32_t base) {
        const int dq = tid & 15, r0 = tid >> 4;
#pragma unroll
        for (int i = 0; i < 8; i++) {
            const int row = r0 + 16 * i;
            float4 v = *(const float4*)&src[(size_t)row * kHD + dq * 4];
            float f[4] = {v.x, v.y, v.z, v.w};
            __nv_bfloat16 hi[4], lo[4];
#pragma unroll
            for (int u = 0; u < 4; u++) {
                hi[u] = __float2bfloat16(f[u]);
                lo[u] = __float2bfloat16(f[u] - __bfloat162float(hi[u]));
            }
            const int d0 = dq * 4;
            const int stage = d0 >> 5;
            const int ch = (d0 & 31) >> 3;
            const int hb = (d0 & 7) >> 2;
            uint32_t addr = base + stage * 8192 + row * 64
                          + ((ch ^ (row & 3)) << 4) + hb * 8;
            sts64(addr, pack_bf2(hi[0], hi[1]), pack_bf2(hi[2], hi[3]));
            sts64(addr + 2 * 8192, pack_bf2(lo[0], lo[1]), pack_bf2(lo[2], lo[3]));
        }
    };
    load_side(qf + (size_t)bh * kN * kHD, sbase);
    load_side(kf + (size_t)bh * kN * kHD, vbase);
    __syncthreads();

    float acc[2][8][4];
#pragma unroll
    for (int i = 0; i < 2; i++)
#pragma unroll
        for (int j = 0; j < 8; j++)
#pragma unroll
            for (int t = 0; t < 4; t++) acc[i][j][t] = 0.f;

    const int a_row = warp_m * 32 + (lane & 15);
    const int a_chsel = lane >> 4;
    const int b_mi = lane >> 3;
    const int b_row = warp_n * 64 + ((b_mi >> 1) << 3) + (lane & 7);
    const int b_chsel = b_mi & 1;

    const int schedA[6] = {0,1, 2,3, 0,1};
    const int schedB[6] = {0,1, 0,1, 2,3};

#pragma unroll
    for (int it = 0; it < 6; it++) {
        const uint32_t sA = sbase + schedA[it] * 8192;
        const uint32_t sB = vbase + schedB[it] * 8192;
#pragma unroll
        for (int kk = 0; kk < 2; kk++) {
            uint32_t a[2][4];
#pragma unroll
            for (int i = 0; i < 2; i++) {
                int r = a_row + i * 16;
                int ch = 2 * kk + a_chsel;
                ldsm_x4(a[i], sA + r * 64 + ((ch ^ (r & 3)) << 4));
            }
            uint32_t b[8][2];
#pragma unroll
            for (int g = 0; g < 4; g++) {
                int r = b_row + g * 16;
                int ch = 2 * kk + b_chsel;
                uint32_t rr[4];
                ldsm_x4(rr, sB + r * 64 + ((ch ^ (r & 3)) << 4));
                b[2 * g][0] = rr[0]; b[2 * g][1] = rr[1];
                b[2 * g + 1][0] = rr[2]; b[2 * g + 1][1] = rr[3];
            }
#pragma unroll
            for (int i = 0; i < 2; i++)
#pragma unroll
                for (int j = 0; j < 8; j++)
                    mma_bf16(acc[i][j], a[i], b[j]);
        }
    }

    const int gq = lane >> 2, t4 = lane & 3;
    float* Sp = S + (size_t)bh * kN * kN;
#pragma unroll
    for (int i = 0; i < 2; i++) {
#pragma unroll
        for (int j = 0; j < 8; j++) {
            int col = warp_n * 64 + j * 8 + t4 * 2;
            int r0 = warp_m * 32 + i * 16 + gq;
            *(float2*)&Sp[(size_t)r0 * kN + col] =
                make_float2(acc[i][j][0] * 0.125f, acc[i][j][1] * 0.125f);
            *(float2*)&Sp[(size_t)(r0 + 8) * kN + col] =
                make_float2(acc[i][j][2] * 0.125f, acc[i][j][3] * 0.125f);
        }
    }
}

// ===================== att v7 (champion) =====================
__global__ __launch_bounds__(256) void att_kernel(
    const float* __restrict__ S, const float* __restrict__ AsTg,
    const void* __restrict__ mask, const float* __restrict__ rel_bias,
    float* __restrict__ Wf)
{
    __shared__ __align__(16) float As[kR * 132];
    __shared__ __align__(16) float Ss[kH * 132];
    __shared__ __align__(16) float Lp[kH * kR * 8];
    __shared__ __align__(16) float Ls[kH * 20];
    __shared__ __align__(16) float PsT[20 * kH];
    __shared__ __align__(16) float rb[136];
    __shared__ __align__(16) int   mk[kR];

    const int t = threadIdx.x, wid = t >> 5, lane = t & 31;
    const int b = blockIdx.x >> 7, n = blockIdx.x & 127;

    {
        const int h = t >> 5, m0 = (t & 31) * 4;
        *(float4*)&Ss[h * 132 + m0] =
            *(const float4*)&S[(((size_t)(b * kH + h)) * kN + n) * kN + m0];
    }
    const float* ag = AsTg + (size_t)n * (kR * kN);
    for (int i = t; i < 544; i += 256) {
        const int r = i >> 5, m0 = (i & 31) * 4;
        *(float4*)&As[r * 132 + m0] = *(const float4*)&ag[r * kN + m0];
    }
    if (t < 136) rb[t] = rel_bias[t];
    if (t < kR) {
        int mode = g_mask_mode;
        int idx = n * kR + t;
        bool m_;
        if (mode == 0)      m_ = ((const int*)mask)[idx] != 0;
        else if (mode == 1) m_ = ((const float*)mask)[idx] != 0.f;
        else                m_ = ((const unsigned char*)mask)[idx] != 0;
        mk[t] = m_ ? 1 : 0;
    }
    __syncthreads();

    {
        const int h = wid;
        float4 sv = *(const float4*)&Ss[h * 132 + lane * 4];
#pragma unroll
        for (int r = 0; r < kR; r++) {
            float4 av = *(const float4*)&As[r * 132 + lane * 4];
            float d = dot4(sv, av);
            d += __shfl_xor_sync(0xFFFFFFFFu, d, 1);
            d += __shfl_xor_sync(0xFFFFFFFFu, d, 2);
            if ((lane & 3) == 0)
                Lp[(h * kR + r) * 8 + (lane >> 2)] = d;
        }
    }
    __syncthreads();

    if (t < 136) {
        const int h = t / kR, r = t - h * kR;
        const float* p = &Lp[t * 8];
        float s = ((p[0] + p[1]) + (p[2] + p[3]))
                + ((p[4] + p[5]) + (p[6] + p[7]));
        Ls[h * 20 + r] = mk[r] ? neg_inf() : (s + rb[t]);
    }
    __syncthreads();

    {
        const int h = wid;
        float v = (lane < kR) ? Ls[h * 20 + lane] : neg_inf();
        float mx = v;
#pragma unroll
        for (int o = 16; o > 0; o >>= 1)
            mx = fmaxf(mx, __shfl_xor_sync(0xFFFFFFFFu, mx, o));
        float e = (lane < kR) ? __expf(v - mx) : 0.f;
        float s = e;
#pragma unroll
        for (int o = 16; o > 0; o >>= 1)
            s += __shfl_xor_sync(0xFFFFFFFFu, s, o);
        if (lane < kR) PsT[lane * kH + h] = e / s;
    }
    __syncthreads();

    {
        const int m = t & 127, hg = t >> 7;
        float acc[4] = {0.f, 0.f, 0.f, 0.f};
#pragma unroll
        for (int r = 0; r < kR; r++) {
            float a = As[r * 132 + m];
            float4 p = *(const float4*)&PsT[r * kH + hg * 4];
            acc[0] += p.x * a; acc[1] += p.y * a;
            acc[2] += p.z * a; acc[3] += p.w * a;
        }
#pragma unroll
        for (int u = 0; u < 4; u++)
            Wf[(((size_t)(b * kH + hg * 4 + u)) * kN + n) * kN + m] = acc[u];
    }
}

// ===================== av combo mma: O = W @ yv^T per (b,h) =================
// Emits fp16 [Oh|Ol] pairs into AO2 (row width 1024).
__global__ __launch_bounds__(256) void av_mma_kernel(
    const float* __restrict__ Wf, const float* __restrict__ yvf,
    __half* __restrict__ AO2)
{
    extern __shared__ __align__(16) char dsm[];
    const int tid = threadIdx.x, wid = tid >> 5, lane = tid & 31;
    const int bh = blockIdx.x;
    const int warp_m = wid >> 1, warp_n = wid & 1;
    const uint32_t sbase = smem_u32(dsm);
    const uint32_t vbase = sbase + 65536u;

    const float* Wb = Wf + (size_t)bh * kN * kN;
    {
        const int mq = tid & 31, r0 = tid >> 5;
#pragma unroll
        for (int i = 0; i < 16; i++) {
            const int row = r0 + 8 * i;
            float4 v = *(const float4*)&Wb[(size_t)row * kN + mq * 4];
            float f[4] = {v.x, v.y, v.z, v.w};
            __nv_bfloat16 hi[4], lo[4];
#pragma unroll
            for (int u = 0; u < 4; u++) {
                hi[u] = __float2bfloat16(f[u]);
                lo[u] = __float2bfloat16(f[u] - __bfloat162float(hi[u]));
            }
            const int m0 = mq * 4;
            const int stage = m0 >> 5;
            const int ch = (m0 & 31) >> 3;
            const int hb = (m0 & 7) >> 2;
            uint32_t addr = sbase + stage * 8192 + row * 64
                          + ((ch ^ (row & 3)) << 4) + hb * 8;
            sts64(addr, pack_bf2(hi[0], hi[1]), pack_bf2(hi[2], hi[3]));
            sts64(addr + 4 * 8192, pack_bf2(lo[0], lo[1]), pack_bf2(lo[2], lo[3]));
        }
    }
    const float* Vb = yvf + (size_t)bh * kN * kHD;
    {
        const int dq = tid & 15, mp0 = tid >> 4;
#pragma unroll
        for (int i = 0; i < 4; i++) {
            const int mp = mp0 + 16 * i;
            const int m0 = 2 * mp;
            float4 v0 = *(const float4*)&Vb[(size_t)m0 * kHD + dq * 4];
            float4 v1 = *(const float4*)&Vb[(size_t)(m0 + 1) * kHD + dq * 4];
            float f0[4] = {v0.x, v0.y, v0.z, v0.w};
            float f1[4] = {v1.x, v1.y, v1.z, v1.w};
            const int stage = m0 >> 5;
            const int ch = (m0 & 31) >> 3;
            const int ob = (m0 & 7) * 2;
#pragma unroll
            for (int u = 0; u < 4; u++) {
                const int row = dq * 4 + u;
                __nv_bfloat16 h0 = __float2bfloat16(f0[u]);
                __nv_bfloat16 h1 = __float2bfloat16(f1[u]);
                __nv_bfloat16 l0 = __float2bfloat16(f0[u] - __bfloat162float(h0));
                __nv_bfloat16 l1 = __float2bfloat16(f1[u] - __bfloat162float(h1));
                uint32_t addr = vbase + stage * 4096 + row * 64
                              + ((ch ^ (row & 3)) << 4) + ob;
                sts32(addr, pack_bf2(h0, h1));
                sts32(addr + 4 * 4096, pack_bf2(l0, l1));
            }
        }
    }
    __syncthreads();

    float acc[2][4][4];
#pragma unroll
    for (int i = 0; i < 2; i++)
#pragma unroll
        for (int j = 0; j < 4; j++)
#pragma unroll
            for (int t = 0; t < 4; t++) acc[i][j][t] = 0.f;

    const int a_row = warp_m * 32 + (lane & 15);
    const int a_chsel = lane >> 4;
    const int b_mi = lane >> 3;
    const int b_row = warp_n * 32 + ((b_mi >> 1) << 3) + (lane & 7);
    const int b_chsel = b_mi & 1;

    const int schedA[12] = {0,1,2,3, 4,5,6,7, 0,1,2,3};
    const int schedB[12] = {0,1,2,3, 0,1,2,3, 4,5,6,7};

#pragma unroll
    for (int it = 0; it < 12; it++) {
        const uint32_t sA = sbase + schedA[it] * 8192;
        const uint32_t sB = vbase + schedB[it] * 4096;
#pragma unroll
        for (int kk = 0; kk < 2; kk++) {
            uint32_t a[2][4];
#pragma unroll
            for (int i = 0; i < 2; i++) {
                int r = a_row + i * 16;
                int ch = 2 * kk + a_chsel;
                ldsm_x4(a[i], sA + r * 64 + ((ch ^ (r & 3)) << 4));
            }
            uint32_t b[4][2];
#pragma unroll
            for (int g = 0; g < 2; g++) {
                int r = b_row + g * 16;
                int ch = 2 * kk + b_chsel;
                uint32_t rr[4];
                ldsm_x4(rr, sB + r * 64 + ((ch ^ (r & 3)) << 4));
                b[2 * g][0] = rr[0]; b[2 * g][1] = rr[1];
                b[2 * g + 1][0] = rr[2]; b[2 * g + 1][1] = rr[3];
            }
#pragma unroll
            for (int i = 0; i < 2; i++)
#pragma unroll
                for (int j = 0; j < 4; j++)
                    mma_bf16(acc[i][j], a[i], b[j]);
        }
    }

    const int gq = lane >> 2, t4 = lane & 3;
    const int b_ = bh >> 3, h_ = bh & 7;
#pragma unroll
    for (int i = 0; i < 2; i++) {
#pragma unroll
        for (int j = 0; j < 4; j++) {
            const int d = warp_n * 32 + j * 8 + t4 * 2;
            const int c = h_ * kHD + d;
#pragma unroll
            for (int rr = 0; rr < 2; rr++) {
                const int nrow = warp_m * 32 + i * 16 + gq + rr * 8;
                const float f0 = acc[i][j][rr * 2], f1 = acc[i][j][rr * 2 + 1];
                __half h0 = __float2half(f0), h1 = __float2half(f1);
                __half l0 = __float2half(f0 - __half2float(h0));
                __half l1 = __float2half(f1 - __half2float(h1));
                __half* base = AO2 + (size_t)(b_ * kN + nrow) * kKo + c;
                *(uint32_t*)(base)       = pack_h2(h0, h1);
                *(uint32_t*)(base + 512) = pack_h2(l0, l1);
            }
        }
    }
}

// ===================== launch =====================
extern "C" void kernel_launch(void* const* d_in, const int* in_sizes, int n_in,
                              void* d_out, int out_size)
{
    const float* x        = (const float*)d_in[0];
    const float* assign   = (const float*)d_in[1];
    const void*  mask     = d_in[2];
    const float* q_w      = (const float*)d_in[3];
    const float* kv_w     = (const float*)d_in[4];
    const float* rel_bias = (const float*)d_in[5];
    const float* proj_w   = (const float*)d_in[6];
    const float* proj_b   = (const float*)d_in[7];

    float *S, *Wfp, *yvf, *qfp, *kfp, *AsTg;
    __half *Ax2, *Bqkv2, *Bproj2, *AO2;
    cudaGetSymbolAddress((void**)&S,    g_S);
    cudaGetSymbolAddress((void**)&Wfp,  g_Wf);
    cudaGetSymbolAddress((void**)&yvf,  g_yvf);
    cudaGetSymbolAddress((void**)&qfp,  g_qf);
    cudaGetSymbolAddress((void**)&kfp,  g_kf);
    cudaGetSymbolAddress((void**)&AsTg, g_AsT);
    cudaGetSymbolAddress((void**)&Ax2,    g_Ax2);
    cudaGetSymbolAddress((void**)&Bqkv2,  g_Bqkv2);
    cudaGetSymbolAddress((void**)&Bproj2, g_Bproj2);
    cudaGetSymbolAddress((void**)&AO2,    g_AO2);

    const int AV_SMEM = 8 * 8192 + 8 * 4096;  // 96 KB
    cudaFuncSetAttribute(av_mma_kernel,
                         cudaFuncAttributeMaxDynamicSharedMemorySize, AV_SMEM);
    const int QK_SMEM = 8 * 8192;             // 64 KB
    cudaFuncSetAttribute(qk_combo_kernel,
                         cudaFuncAttributeMaxDynamicSharedMemorySize, QK_SMEM);

    // 1. input splits + mask probe + A transpose
    convert_all_kernel<<<4225, 128>>>(x, q_w, kv_w, proj_w, assign, mask,
                                      Ax2, Bqkv2, Bproj2, AsTg);

    // 2. fused q/kv projection fp16 2-term (K'=1024, 32 iters, MTILE=256)
    mma_gemm_t<2048, 32, 1, 256, true><<<dim3(12, 8), 256>>>(
        (const __nv_bfloat16*)Ax2, (const __nv_bfloat16*)Bqkv2,
        nullptr, yvf, nullptr, 0, 0, 0, qfp, kfp);

    // 3. S = 0.125 * q@k^T per (b,h), combo split-K (bf16 3-term)
    qk_combo_kernel<<<128, 256, QK_SMEM>>>(qfp, kfp, S);

    // 4. logits + masked softmax + W (fp32)
    att_kernel<<<kB * kN, 256>>>(S, AsTg, mask, rel_bias, Wfp);

    // 5. O = W @ yv per (b,h), combo split-K (emits fp16 [Oh|Ol])
    av_mma_kernel<<<128, 256, AV_SMEM>>>(Wfp, yvf, AO2);

    // 6. out-proj fp16 2-term: [Oh|Ol] @ [Ph|Ph]^T + bias (K'=1024, 32 iters)
    mma_gemm_t<2048, 32, 0, 64, true><<<dim3(4, 32), 256>>>(
        (const __nv_bfloat16*)AO2, (const __nv_bfloat16*)Bproj2,
        (float*)d_out, (float*)d_out, proj_b, 1 << 30, kC, kC,
        nullptr, nullptr);
}